// round 1
// baseline (speedup 1.0000x reference)
#include <cuda_runtime.h>
#include <cstdint>

#define ASTRIDE 36
#define SMEM_FLOATS 48272
#define SMEM_BYTES (SMEM_FLOATS * 4)

__device__ __forceinline__ unsigned long long pack2(float lo, float hi) {
    unsigned long long r;
    asm("mov.b64 %0, {%1, %2};" : "=l"(r) : "f"(lo), "f"(hi));
    return r;
}
__device__ __forceinline__ void unpack2(unsigned long long v, float &lo, float &hi) {
    asm("mov.b64 {%0, %1}, %2;" : "=f"(lo), "=f"(hi) : "l"(v));
}
__device__ __forceinline__ unsigned long long ffma2(unsigned long long a, unsigned long long b,
                                                    unsigned long long c) {
    unsigned long long d;
    asm("fma.rn.f32x2 %0, %1, %2, %3;" : "=l"(d) : "l"(a), "l"(b), "l"(c));
    return d;
}
__device__ __forceinline__ void cp16(float* s, const float* g) {
    unsigned a = (unsigned)__cvta_generic_to_shared(s);
    asm volatile("cp.async.cg.shared.global [%0], [%1], 16;" :: "r"(a), "l"(g));
}

__global__ void __launch_bounds__(256, 1)
patchflow_kernel(const float* __restrict__ x, const float* __restrict__ pos,
                 const float* __restrict__ w1a, const float* __restrict__ b1a,
                 const float* __restrict__ w2a, const float* __restrict__ b2a,
                 const float* __restrict__ w3a, const float* __restrict__ b3a,
                 const float* __restrict__ gsa, const float* __restrict__ goa,
                 const int* __restrict__ pma,
                 const float* __restrict__ w1b, const float* __restrict__ b1b,
                 const float* __restrict__ w2b, const float* __restrict__ b2b,
                 const float* __restrict__ w3b, const float* __restrict__ b3b,
                 const float* __restrict__ gsb, const float* __restrict__ gob,
                 const int* __restrict__ pmb,
                 float* __restrict__ zout, float* __restrict__ ldjout)
{
    extern __shared__ float sm[];
    const int p = blockIdx.x;
    const int t = threadIdx.x;

    // ---- shared memory layout (all offsets multiples of 4 floats = 16B) ----
    float* W1s  = sm;                      // 2*2176
    float* B1s  = W1s + 2 * 2176;          // 2*128
    float* W2s  = B1s + 256;               // 2*16384
    float* B2s  = W2s + 32768;             // 2*128
    float* W3s  = B2s + 256;               // 2*512
    float* B3s  = W3s + 1024;              // 2*4
    float* POSs = B3s + 8;                 // 16
    float* A1s  = POSs + 16;               // 128*36
    float* A2s  = A1s + 128 * ASTRIDE;     // 128*36
    float* Hs   = A2s + 128 * ASTRIDE;     // 96  (b*3+c)
    float* OUTs = Hs + 96;                 // 96
    float* A3s  = OUTs + 96;               // 128 (b*4+j)
    float* LDJs = A3s + 128;               // 32
    float* SCs  = LDJs + 32;               // 8 (scale per blk,c)
    float* GOs  = SCs + 8;                 // 8
    int*   PMs  = (int*)(GOs + 8);         // 8 (perm per blk,c)

    // ---- prefetch group A (block-a weights + pos) ----
    {
        const float* s;
        s = w1a + (size_t)p * 2176;  for (int i = 4*t; i < 2176;  i += 1024) cp16(W1s + i, s + i);
        s = b1a + (size_t)p * 128;   for (int i = 4*t; i < 128;   i += 1024) cp16(B1s + i, s + i);
        s = w2a + (size_t)p * 16384; for (int i = 4*t; i < 16384; i += 1024) cp16(W2s + i, s + i);
        s = b2a + (size_t)p * 128;   for (int i = 4*t; i < 128;   i += 1024) cp16(B2s + i, s + i);
        s = w3a + (size_t)p * 512;   for (int i = 4*t; i < 512;   i += 1024) cp16(W3s + i, s + i);
        if (t == 0) cp16(B3s, b3a + (size_t)p * 4);
        s = pos + (size_t)p * 16;    for (int i = 4*t; i < 16;    i += 1024) cp16(POSs + i, s + i);
    }
    asm volatile("cp.async.commit_group;");
    // ---- prefetch group B (block-b weights) ----
    {
        const float* s;
        s = w1b + (size_t)p * 2176;  for (int i = 4*t; i < 2176;  i += 1024) cp16(W1s + 2176 + i, s + i);
        s = b1b + (size_t)p * 128;   for (int i = 4*t; i < 128;   i += 1024) cp16(B1s + 128 + i, s + i);
        s = w2b + (size_t)p * 16384; for (int i = 4*t; i < 16384; i += 1024) cp16(W2s + 16384 + i, s + i);
        s = b2b + (size_t)p * 128;   for (int i = 4*t; i < 128;   i += 1024) cp16(B2s + 128 + i, s + i);
        s = w3b + (size_t)p * 512;   for (int i = 4*t; i < 512;   i += 1024) cp16(W3s + 512 + i, s + i);
        if (t == 0) cp16(B3s + 4, b3b + (size_t)p * 4);
    }
    asm volatile("cp.async.commit_group;");

    // ---- tiny per-p params: precompute scale = 0.2*softplus(0.5*gs) ----
    if (t < 6) {
        int blk = t / 3, c = t % 3;
        float gsv = (blk ? gsb : gsa)[(size_t)p * 3 + c];
        float y = 0.5f * gsv;
        float sp = (y > 15.f) ? y : log1pf(expf(y));
        SCs[t] = 0.2f * sp;
    }
    if (t >= 32 && t < 38) {
        int u = t - 32;
        GOs[u] = ((u >= 3) ? gob : goa)[(size_t)p * 3 + (u % 3)];
    }
    if (t >= 64 && t < 70) {
        int u = t - 64;
        PMs[u] = ((u >= 3) ? pmb : pma)[(size_t)p * 3 + (u % 3)];
    }
    if (t < 32) LDJs[t] = 0.f;

    // ---- 3x3 stride-2 avg pool (sum/9, zero pad) for this p ----
    if (t < 96) {
        int b = t / 3, c = t % 3;
        int ph = p >> 6, pw = p & 63;
        const float* xp = x + (size_t)(b * 3 + c) * 16384;
        int y0 = 2 * ph - 1, x0 = 2 * pw - 1;
        float acc = 0.f;
        #pragma unroll
        for (int dy = 0; dy < 3; dy++) {
            int yy = y0 + dy;
            if (yy < 0) continue;
            #pragma unroll
            for (int dx = 0; dx < 3; dx++) {
                int xx = x0 + dx;
                if (xx < 0) continue;
                acc += __ldg(xp + yy * 128 + xx);
            }
        }
        Hs[t] = acc * (1.f / 9.f);
    }

    asm volatile("cp.async.wait_group 1;");   // block-a weights resident
    __syncthreads();

    for (int blk = 0; blk < 2; blk++) {
        if (blk == 1) {
            asm volatile("cp.async.wait_group 0;");
            __syncthreads();
        }
        const float* W1 = W1s + blk * 2176;
        const float* B1 = B1s + blk * 128;
        const float* W2 = W2s + blk * 16384;
        const float* B2 = B2s + blk * 128;
        const float* W3 = W3s + blk * 512;
        const float* B3 = B3s + blk * 4;

        // ---- layer 1: cond part is batch-invariant -> 1 FMA per element ----
        {
            int o = t & 127, bh = t >> 7;
            float cs = B1[o];
            #pragma unroll
            for (int k = 0; k < 16; k++) cs = fmaf(POSs[k], W1[(1 + k) * 128 + o], cs);
            float w0 = W1[o];
            #pragma unroll
            for (int bi = 0; bi < 16; bi++) {
                int b = bh * 16 + bi;
                float v = fmaf(Hs[b * 3], w0, cs);
                A1s[o * ASTRIDE + b] = v * normcdff(v);   // exact gelu
            }
        }
        __syncthreads();

        // ---- layer 2: 32x128 @ 128x128, f32x2 packed, 2b x 8o per thread ----
        {
            int bq = t & 15, oq = t >> 4;
            int b0 = 2 * bq, o0 = 8 * oq;
            const float* Ab = A1s + b0;
            const float* Wb = W2 + o0;
            unsigned long long a00 = 0, a01 = 0, a02 = 0, a03 = 0;
            unsigned long long a10 = 0, a11 = 0, a12 = 0, a13 = 0;
            #pragma unroll 4
            for (int i = 0; i < 128; i++) {
                float alo = Ab[i * ASTRIDE];
                float ahi = Ab[i * ASTRIDE + 1];
                unsigned long long d0 = pack2(alo, alo);
                unsigned long long d1 = pack2(ahi, ahi);
                ulonglong2 w01 = *(const ulonglong2*)(Wb + (size_t)i * 128);
                ulonglong2 w23 = *(const ulonglong2*)(Wb + (size_t)i * 128 + 4);
                a00 = ffma2(d0, w01.x, a00);
                a01 = ffma2(d0, w01.y, a01);
                a02 = ffma2(d0, w23.x, a02);
                a03 = ffma2(d0, w23.y, a03);
                a10 = ffma2(d1, w01.x, a10);
                a11 = ffma2(d1, w01.y, a11);
                a12 = ffma2(d1, w23.x, a12);
                a13 = ffma2(d1, w23.y, a13);
            }
            float lo, hi, v0, v1;
            #define EMIT(ACC, B_, O_) { unpack2(ACC, lo, hi);                                \
                v0 = lo + B2[(O_)]; v1 = hi + B2[(O_) + 1];                                  \
                A2s[(O_) * ASTRIDE + (B_)]       = v0 * normcdff(v0);                        \
                A2s[((O_) + 1) * ASTRIDE + (B_)] = v1 * normcdff(v1); }
            EMIT(a00, b0,     o0)     EMIT(a01, b0,     o0 + 2)
            EMIT(a02, b0,     o0 + 4) EMIT(a03, b0,     o0 + 6)
            EMIT(a10, b0 + 1, o0)     EMIT(a11, b0 + 1, o0 + 2)
            EMIT(a12, b0 + 1, o0 + 4) EMIT(a13, b0 + 1, o0 + 6)
            #undef EMIT
        }
        __syncthreads();

        // ---- layer 3: 128 -> 4, then *0.1 ----
        if (t < 128) {
            int j = t & 3, b = t >> 2;
            float acc = 0.f;
            #pragma unroll 8
            for (int i = 0; i < 128; i++)
                acc = fmaf(A2s[i * ASTRIDE + b], W3[i * 4 + j], acc);
            A3s[b * 4 + j] = (acc + B3[j]) * 0.1f;
        }
        __syncthreads();

        // ---- epilogue: affine coupling + scale/offset + ldj ----
        if (t < 96) {
            int b = t / 3, c = t % 3;
            float outv;
            if (c == 0) {
                outv = Hs[t];
            } else {
                float sc = 2.f * tanhf(A3s[b * 4 + (c - 1)]);
                outv = Hs[t] * expf(sc) + A3s[b * 4 + 2 + (c - 1)];
            }
            OUTs[t] = outv * SCs[blk * 3 + c] + GOs[blk * 3 + c];
        }
        if (t < 32) {
            float s0 = 2.f * tanhf(A3s[t * 4]);
            float s1 = 2.f * tanhf(A3s[t * 4 + 1]);
            float lss = logf(SCs[blk * 3]) + logf(SCs[blk * 3 + 1]) + logf(SCs[blk * 3 + 2]);
            LDJs[t] += s0 + s1 + lss;
        }
        __syncthreads();
        // ---- channel permutation into Hs (input of next block / final z) ----
        if (t < 96) {
            int b = t / 3, k = t % 3;
            Hs[t] = OUTs[b * 3 + PMs[blk * 3 + k]];
        }
        __syncthreads();
    }

    if (t < 96) zout[(size_t)p * 96 + t] = Hs[t];
    if (t < 32) ldjout[(size_t)p * 32 + t] = LDJs[t];
}

extern "C" void kernel_launch(void* const* d_in, const int* in_sizes, int n_in,
                              void* d_out, int out_size) {
    (void)n_in; (void)out_size;

    // Two plausible metadata orderings; disambiguate at runtime:
    //  dict order:       ..., gsa(8), goa(9), perma(10)=12288, w1b(11), ...
    //  signature order:  ..., gsa(8), goa(9), w1b(10)=8912896, ..., perma(18), permb(19)
    int ia[9], ib[9];
    if (in_sizes[10] == 12288) {
        const int A[9]  = {2, 3, 4, 5, 6, 7, 8, 9, 10};
        const int Bn[9] = {11, 12, 13, 14, 15, 16, 17, 18, 19};
        for (int i = 0; i < 9; i++) { ia[i] = A[i]; ib[i] = Bn[i]; }
    } else {
        const int A[9]  = {2, 3, 4, 5, 6, 7, 8, 9, 18};
        const int Bn[9] = {10, 11, 12, 13, 14, 15, 16, 17, 19};
        for (int i = 0; i < 9; i++) { ia[i] = A[i]; ib[i] = Bn[i]; }
    }

    cudaFuncSetAttribute(patchflow_kernel,
                         cudaFuncAttributeMaxDynamicSharedMemorySize, SMEM_BYTES);

    float* z = (float*)d_out;                 // [4096, 32, 3]
    float* ldj = z + (size_t)4096 * 32 * 3;   // [4096, 32]

    patchflow_kernel<<<4096, 256, SMEM_BYTES>>>(
        (const float*)d_in[0], (const float*)d_in[1],
        (const float*)d_in[ia[0]], (const float*)d_in[ia[1]],
        (const float*)d_in[ia[2]], (const float*)d_in[ia[3]],
        (const float*)d_in[ia[4]], (const float*)d_in[ia[5]],
        (const float*)d_in[ia[6]], (const float*)d_in[ia[7]],
        (const int*)d_in[ia[8]],
        (const float*)d_in[ib[0]], (const float*)d_in[ib[1]],
        (const float*)d_in[ib[2]], (const float*)d_in[ib[3]],
        (const float*)d_in[ib[4]], (const float*)d_in[ib[5]],
        (const float*)d_in[ib[6]], (const float*)d_in[ib[7]],
        (const int*)d_in[ib[8]],
        z, ldj);
}

// round 2
// speedup vs baseline: 1.3305x; 1.3305x over previous
#include <cuda_runtime.h>
#include <cstdint>

// ---- shared memory layout (floats) ----
#define OFF_W2   0        // 16384  (single-buffered, reloaded for block b)
#define OFF_W1   16384    // 2176
#define OFF_B1   18560    // 128
#define OFF_W3   18688    // 512
#define OFF_B3   19200    // 4
#define OFF_POS  19204    // 16
#define OFF_A1   19220    // 4096  (stride 32: [o][b])
#define OFF_A2   23316    // 4096  (stride 32: [o][b]; first 128 reused as CS scratch)
#define OFF_H    27412    // 96
#define OFF_OUT  27508    // 96
#define OFF_A3   27604    // 128
#define OFF_LDJ  27732    // 32
#define OFF_SC   27764    // 8
#define OFF_GO   27772    // 8
#define OFF_PM   27780    // 8 (ints)
#define SMEM_FLOATS 27792
#define SMEM_BYTES (SMEM_FLOATS * 4)

__device__ __forceinline__ unsigned long long pack2(float lo, float hi) {
    unsigned long long r;
    asm("mov.b64 %0, {%1, %2};" : "=l"(r) : "f"(lo), "f"(hi));
    return r;
}
__device__ __forceinline__ void unpack2(unsigned long long v, float &lo, float &hi) {
    asm("mov.b64 {%0, %1}, %2;" : "=f"(lo), "=f"(hi) : "l"(v));
}
__device__ __forceinline__ unsigned long long ffma2(unsigned long long a, unsigned long long b,
                                                    unsigned long long c) {
    unsigned long long d;
    asm("fma.rn.f32x2 %0, %1, %2, %3;" : "=l"(d) : "l"(a), "l"(b), "l"(c));
    return d;
}
__device__ __forceinline__ void cp16(float* s, const float* g) {
    unsigned a = (unsigned)__cvta_generic_to_shared(s);
    asm volatile("cp.async.cg.shared.global [%0], [%1], 16;" :: "r"(a), "l"(g));
}
#define COMMIT()  asm volatile("cp.async.commit_group;")
#define WAITG(N)  asm volatile("cp.async.wait_group %0;" :: "n"(N))

__global__ void __launch_bounds__(256, 2)
patchflow_kernel(const float* __restrict__ x, const float* __restrict__ pos,
                 const float* __restrict__ w1a, const float* __restrict__ b1a,
                 const float* __restrict__ w2a, const float* __restrict__ b2a,
                 const float* __restrict__ w3a, const float* __restrict__ b3a,
                 const float* __restrict__ gsa, const float* __restrict__ goa,
                 const int* __restrict__ pma,
                 const float* __restrict__ w1b, const float* __restrict__ b1b,
                 const float* __restrict__ w2b, const float* __restrict__ b2b,
                 const float* __restrict__ w3b, const float* __restrict__ b3b,
                 const float* __restrict__ gsb, const float* __restrict__ gob,
                 const int* __restrict__ pmb,
                 float* __restrict__ zout, float* __restrict__ ldjout)
{
    extern __shared__ float sm[];
    const int p = blockIdx.x;
    const int t = threadIdx.x;

    float* W2s  = sm + OFF_W2;
    float* W1s  = sm + OFF_W1;
    float* B1s  = sm + OFF_B1;
    float* W3s  = sm + OFF_W3;
    float* B3s  = sm + OFF_B3;
    float* POSs = sm + OFF_POS;
    float* A1s  = sm + OFF_A1;
    float* A2s  = sm + OFF_A2;
    float* CSs  = sm + OFF_A2;      // scratch aliasing A2 (safe: written before GEMM2 output)
    float* Hs   = sm + OFF_H;
    float* OUTs = sm + OFF_OUT;
    float* A3s  = sm + OFF_A3;
    float* LDJs = sm + OFF_LDJ;
    float* SCs  = sm + OFF_SC;
    float* GOs  = sm + OFF_GO;
    int*   PMs  = (int*)(sm + OFF_PM);

    const float* B2cur;   // b2 stays in gmem? no — b2 needed per-o broadcast; keep in regs via gmem LDG? cheap.

    // ---- group 0: small block-a weights + pos ----
    for (int i = 4*t; i < 2176; i += 1024) cp16(W1s + i, w1a + (size_t)p*2176 + i);
    for (int i = 4*t; i < 128;  i += 1024) cp16(B1s + i, b1a + (size_t)p*128 + i);
    for (int i = 4*t; i < 512;  i += 1024) cp16(W3s + i, w3a + (size_t)p*512 + i);
    if (t == 0) cp16(B3s, b3a + (size_t)p*4);
    for (int i = 4*t; i < 16;   i += 1024) cp16(POSs + i, pos + (size_t)p*16 + i);
    COMMIT();                                   // g0
    // ---- group 1: w2a (big) ----
    for (int i = 4*t; i < 16384; i += 1024) cp16(W2s + i, w2a + (size_t)p*16384 + i);
    COMMIT();                                   // g1

    // ---- per-p params (direct LDG, both blocks) ----
    if (t < 6) {
        int blk = t / 3, c = t % 3;
        float gsv = (blk ? gsb : gsa)[(size_t)p*3 + c];
        float y = 0.5f * gsv;
        float sp = (y > 15.f) ? y : log1pf(expf(y));
        SCs[t] = 0.2f * sp;
    }
    if (t >= 32 && t < 38) {
        int u = t - 32;
        GOs[u] = ((u >= 3) ? gob : goa)[(size_t)p*3 + (u % 3)];
    }
    if (t >= 64 && t < 70) {
        int u = t - 64;
        PMs[u] = ((u >= 3) ? pmb : pma)[(size_t)p*3 + (u % 3)];
    }
    if (t < 32) LDJs[t] = 0.f;

    // ---- 3x3 stride-2 avg pool for this p ----
    if (t < 96) {
        int b = t / 3, c = t % 3;
        int ph = p >> 6, pw = p & 63;
        const float* xp = x + (size_t)(b*3 + c) * 16384;
        int y0 = 2*ph - 1, x0 = 2*pw - 1;
        float acc = 0.f;
        #pragma unroll
        for (int dy = 0; dy < 3; dy++) {
            int yy = y0 + dy;
            if (yy < 0) continue;
            #pragma unroll
            for (int dx = 0; dx < 3; dx++) {
                int xx = x0 + dx;
                if (xx < 0) continue;
                acc += __ldg(xp + yy*128 + xx);
            }
        }
        Hs[t] = acc * (1.f / 9.f);
    }

    WAITG(1);           // g0 done (g1 may be in flight)
    __syncthreads();

    const float* b2ptrs[2] = { b2a + (size_t)p*128, b2b + (size_t)p*128 };

    for (int blk = 0; blk < 2; blk++) {
        // ---- cond-sum precompute: cs[o] = B1[o] + sum_k pos[k]*W1[1+k][o] ----
        if (t < 128) {
            int o = t;
            float cs = B1s[o];
            #pragma unroll
            for (int k = 0; k < 16; k++) cs = fmaf(POSs[k], W1s[(1 + k)*128 + o], cs);
            CSs[o] = cs;
        }
        __syncthreads();

        // ---- layer 1: lanes vary b -> conflict-free stride-32 stores ----
        {
            int b = t & 31, og = t >> 5;           // og in 0..7, 16 o's each
            float h = Hs[b * 3];
            #pragma unroll
            for (int r = 0; r < 16; r++) {
                int o = og * 16 + r;
                float v = fmaf(h, W1s[o], CSs[o]);
                A1s[o * 32 + b] = v * normcdff(v);
            }
        }
        __syncthreads();                            // A1 ready; W1/B1 fully read

        if (blk == 0) {
            // g2: w1b + b1b into the (now free) W1 buffer
            for (int i = 4*t; i < 2176; i += 1024) cp16(W1s + i, w1b + (size_t)p*2176 + i);
            for (int i = 4*t; i < 128;  i += 1024) cp16(B1s + i, b1b + (size_t)p*128 + i);
            COMMIT();                               // g2
            WAITG(1);                               // w2a resident (g2 may be in flight)
            __syncthreads();
        }

        // ---- layer 2: 32x128 @ 128x128, f32x2 packed, 2b x 8o per thread ----
        {
            int bq = t & 15, oq = t >> 4;
            int b0 = 2 * bq, o0 = 8 * oq;
            const float* Ab = A1s + b0;
            const float* Wb = W2s + o0;
            unsigned long long a00 = 0, a01 = 0, a02 = 0, a03 = 0;
            unsigned long long a10 = 0, a11 = 0, a12 = 0, a13 = 0;
            #pragma unroll 4
            for (int i = 0; i < 128; i++) {
                float2 av = *(const float2*)(Ab + i * 32);
                unsigned long long d0 = pack2(av.x, av.x);
                unsigned long long d1 = pack2(av.y, av.y);
                ulonglong2 w01 = *(const ulonglong2*)(Wb + (size_t)i * 128);
                ulonglong2 w23 = *(const ulonglong2*)(Wb + (size_t)i * 128 + 4);
                a00 = ffma2(d0, w01.x, a00);
                a01 = ffma2(d0, w01.y, a01);
                a02 = ffma2(d0, w23.x, a02);
                a03 = ffma2(d0, w23.y, a03);
                a10 = ffma2(d1, w01.x, a10);
                a11 = ffma2(d1, w01.y, a11);
                a12 = ffma2(d1, w23.x, a12);
                a13 = ffma2(d1, w23.y, a13);
            }
            const float* B2g = b2ptrs[blk];
            float lo, hi, v0, v1;
            #define EMIT(ACC, B_, O_) { unpack2(ACC, lo, hi);                             \
                v0 = lo + __ldg(B2g + (O_)); v1 = hi + __ldg(B2g + (O_) + 1);             \
                A2s[(O_) * 32 + (B_)]       = v0 * normcdff(v0);                          \
                A2s[((O_) + 1) * 32 + (B_)] = v1 * normcdff(v1); }
            EMIT(a00, b0,     o0)     EMIT(a01, b0,     o0 + 2)
            EMIT(a02, b0,     o0 + 4) EMIT(a03, b0,     o0 + 6)
            EMIT(a10, b0 + 1, o0)     EMIT(a11, b0 + 1, o0 + 2)
            EMIT(a12, b0 + 1, o0 + 4) EMIT(a13, b0 + 1, o0 + 6)
            #undef EMIT
        }
        __syncthreads();                            // A2 ready; W2 fully read

        // ---- layer 3 (threads <128) overlapped with w2b prefetch (threads >=128) ----
        if (blk == 0) {
            if (t >= 128) {
                int u = t - 128;
                for (int i = 4*u; i < 16384; i += 512) cp16(W2s + i, w2b + (size_t)p*16384 + i);
            }
            COMMIT();                               // g3 (empty for t<128)
        }
        if (t < 128) {
            int j = t & 3, b = t >> 2;
            float acc = 0.f;
            #pragma unroll 8
            for (int i = 0; i < 128; i++)
                acc = fmaf(A2s[i * 32 + b], W3s[i * 4 + j], acc);
            A3s[b * 4 + j] = (acc + B3s[j]) * 0.1f;
        }
        __syncthreads();                            // A3 ready; W3 fully read

        if (blk == 0) {
            if (t >= 128) {
                int u = t - 128;
                for (int i = 4*u; i < 512; i += 512) cp16(W3s + i, w3b + (size_t)p*512 + i);
                if (u == 0) cp16(B3s, b3b + (size_t)p*4);
            }
            COMMIT();                               // g4
        }

        // ---- epilogue: affine coupling + scale/offset + ldj ----
        if (t < 96) {
            int b = t / 3, c = t % 3;
            float outv;
            if (c == 0) {
                outv = Hs[t];
            } else {
                float sc = 2.f * tanhf(A3s[b * 4 + (c - 1)]);
                outv = Hs[t] * expf(sc) + A3s[b * 4 + 2 + (c - 1)];
            }
            OUTs[t] = outv * SCs[blk * 3 + c] + GOs[blk * 3 + c];
        }
        if (t < 32) {
            float s0 = 2.f * tanhf(A3s[t * 4]);
            float s1 = 2.f * tanhf(A3s[t * 4 + 1]);
            float lss = logf(SCs[blk*3]) + logf(SCs[blk*3 + 1]) + logf(SCs[blk*3 + 2]);
            LDJs[t] += s0 + s1 + lss;
        }
        __syncthreads();
        // ---- channel permutation into Hs ----
        if (t < 96) {
            int b = t / 3, k = t % 3;
            Hs[t] = OUTs[b * 3 + PMs[blk * 3 + k]];
        }

        if (blk == 0) {
            WAITG(0);                               // all block-b weights resident
        }
        __syncthreads();
    }

    if (t < 96) zout[(size_t)p * 96 + t] = Hs[t];
    if (t < 32) ldjout[(size_t)p * 32 + t] = LDJs[t];
}

extern "C" void kernel_launch(void* const* d_in, const int* in_sizes, int n_in,
                              void* d_out, int out_size) {
    (void)n_in; (void)out_size;

    int ia[9], ib[9];
    if (in_sizes[10] == 12288) {
        const int A[9]  = {2, 3, 4, 5, 6, 7, 8, 9, 10};
        const int Bn[9] = {11, 12, 13, 14, 15, 16, 17, 18, 19};
        for (int i = 0; i < 9; i++) { ia[i] = A[i]; ib[i] = Bn[i]; }
    } else {
        const int A[9]  = {2, 3, 4, 5, 6, 7, 8, 9, 18};
        const int Bn[9] = {10, 11, 12, 13, 14, 15, 16, 17, 19};
        for (int i = 0; i < 9; i++) { ia[i] = A[i]; ib[i] = Bn[i]; }
    }

    cudaFuncSetAttribute(patchflow_kernel,
                         cudaFuncAttributeMaxDynamicSharedMemorySize, SMEM_BYTES);

    float* z = (float*)d_out;                 // [4096, 32, 3]
    float* ldj = z + (size_t)4096 * 32 * 3;   // [4096, 32]

    patchflow_kernel<<<4096, 256, SMEM_BYTES>>>(
        (const float*)d_in[0], (const float*)d_in[1],
        (const float*)d_in[ia[0]], (const float*)d_in[ia[1]],
        (const float*)d_in[ia[2]], (const float*)d_in[ia[3]],
        (const float*)d_in[ia[4]], (const float*)d_in[ia[5]],
        (const float*)d_in[ia[6]], (const float*)d_in[ia[7]],
        (const int*)d_in[ia[8]],
        (const float*)d_in[ib[0]], (const float*)d_in[ib[1]],
        (const float*)d_in[ib[2]], (const float*)d_in[ib[3]],
        (const float*)d_in[ib[4]], (const float*)d_in[ib[5]],
        (const float*)d_in[ib[6]], (const float*)d_in[ib[7]],
        (const int*)d_in[ib[8]],
        z, ldj);
}

// round 3
// speedup vs baseline: 1.4428x; 1.0844x over previous
#include <cuda_runtime.h>
#include <cstdint>

// ---- shared memory layout (floats) ----
#define OFF_W2S0 0        // 4096 (K-chunk ping)
#define OFF_W2S1 4096     // 4096 (K-chunk pong)
#define OFF_W1   8192     // 2176
#define OFF_B1   10368    // 128
#define OFF_B2   10496    // 256  [0:128]=a [128:256]=b
#define OFF_W3   10752    // 1024 [0:512]=a [512:1024]=b
#define OFF_B3   11776    // 8
#define OFF_POS  11784    // 16
#define OFF_CS   11800    // 256  [0:128]=CS0 [128:256]=CS1
#define OFF_A    12056    // 4096 (single buffer, stride 32; A1 then A2 in place)
#define OFF_A3P  16152    // 256
#define OFF_A3   16408    // 128
#define OFF_H    16536    // 96
#define OFF_OUT  16632    // 96
#define OFF_LDJ  16728    // 32
#define OFF_SC   16760    // 8
#define OFF_GO   16768    // 8
#define OFF_PM   16776    // 8 (ints)
#define SMEM_FLOATS 16784
#define SMEM_BYTES (SMEM_FLOATS * 4)

__device__ __forceinline__ unsigned long long pack2(float lo, float hi) {
    unsigned long long r;
    asm("mov.b64 %0, {%1, %2};" : "=l"(r) : "f"(lo), "f"(hi));
    return r;
}
__device__ __forceinline__ void unpack2(unsigned long long v, float &lo, float &hi) {
    asm("mov.b64 {%0, %1}, %2;" : "=f"(lo), "=f"(hi) : "l"(v));
}
__device__ __forceinline__ unsigned long long ffma2(unsigned long long a, unsigned long long b,
                                                    unsigned long long c) {
    unsigned long long d;
    asm("fma.rn.f32x2 %0, %1, %2, %3;" : "=l"(d) : "l"(a), "l"(b), "l"(c));
    return d;
}
__device__ __forceinline__ void cp16(float* s, const float* g) {
    unsigned a = (unsigned)__cvta_generic_to_shared(s);
    asm volatile("cp.async.cg.shared.global [%0], [%1], 16;" :: "r"(a), "l"(g));
}
#define COMMIT()  asm volatile("cp.async.commit_group;")
#define WAITG(N)  asm volatile("cp.async.wait_group %0;" :: "n"(N))

// copy one 4096-float (16KB) W2 K-chunk
__device__ __forceinline__ void issue_w2(float* dst, const float* src, int t) {
    #pragma unroll
    for (int i = 4 * t; i < 4096; i += 1024) cp16(dst + i, src + i);
}

__global__ void __launch_bounds__(256, 3)
patchflow_kernel(const float* __restrict__ x, const float* __restrict__ pos,
                 const float* __restrict__ w1a, const float* __restrict__ b1a,
                 const float* __restrict__ w2a, const float* __restrict__ b2a,
                 const float* __restrict__ w3a, const float* __restrict__ b3a,
                 const float* __restrict__ gsa, const float* __restrict__ goa,
                 const int* __restrict__ pma,
                 const float* __restrict__ w1b, const float* __restrict__ b1b,
                 const float* __restrict__ w2b, const float* __restrict__ b2b,
                 const float* __restrict__ w3b, const float* __restrict__ b3b,
                 const float* __restrict__ gsb, const float* __restrict__ gob,
                 const int* __restrict__ pmb,
                 float* __restrict__ zout, float* __restrict__ ldjout)
{
    extern __shared__ float sm[];
    const int p = blockIdx.x;
    const int t = threadIdx.x;

    float* W2s0 = sm + OFF_W2S0;
    float* W2s1 = sm + OFF_W2S1;
    float* W1s  = sm + OFF_W1;
    float* B1s  = sm + OFF_B1;
    float* B2s  = sm + OFF_B2;
    float* W3s  = sm + OFF_W3;
    float* B3s  = sm + OFF_B3;
    float* POSs = sm + OFF_POS;
    float* CSs  = sm + OFF_CS;
    float* As   = sm + OFF_A;
    float* A3P  = sm + OFF_A3P;
    float* A3s  = sm + OFF_A3;
    float* Hs   = sm + OFF_H;
    float* OUTs = sm + OFF_OUT;
    float* LDJs = sm + OFF_LDJ;
    float* SCs  = sm + OFF_SC;
    float* GOs  = sm + OFF_GO;
    int*   PMs  = (int*)(sm + OFF_PM);

    const float* w2aP = w2a + (size_t)p * 16384;
    const float* w2bP = w2b + (size_t)p * 16384;

    // g0: small block-a weights + pos
    for (int i = 4*t; i < 2176; i += 1024) cp16(W1s + i, w1a + (size_t)p*2176 + i);
    for (int i = 4*t; i < 128;  i += 1024) cp16(B1s + i, b1a + (size_t)p*128 + i);
    for (int i = 4*t; i < 128;  i += 1024) cp16(B2s + i, b2a + (size_t)p*128 + i);
    for (int i = 4*t; i < 512;  i += 1024) cp16(W3s + i, w3a + (size_t)p*512 + i);
    if (t == 0) cp16(B3s, b3a + (size_t)p*4);
    for (int i = 4*t; i < 16;   i += 1024) cp16(POSs + i, pos + (size_t)p*16 + i);
    COMMIT();                                  // g0
    issue_w2(W2s0, w2aP,        t); COMMIT();  // g1: w2a chunk0
    issue_w2(W2s1, w2aP + 4096, t); COMMIT();  // g2: w2a chunk1

    // per-p params
    if (t < 6) {
        int blk = t / 3, c = t % 3;
        float gsv = (blk ? gsb : gsa)[(size_t)p*3 + c];
        float y = 0.5f * gsv;
        float sp = (y > 15.f) ? y : log1pf(expf(y));
        SCs[t] = 0.2f * sp;
    }
    if (t >= 32 && t < 38) {
        int u = t - 32;
        GOs[u] = ((u >= 3) ? gob : goa)[(size_t)p*3 + (u % 3)];
    }
    if (t >= 64 && t < 70) {
        int u = t - 64;
        PMs[u] = ((u >= 3) ? pmb : pma)[(size_t)p*3 + (u % 3)];
    }
    if (t < 32) LDJs[t] = 0.f;

    // 3x3 stride-2 avg pool
    if (t < 96) {
        int b = t / 3, c = t % 3;
        int ph = p >> 6, pw = p & 63;
        const float* xp = x + (size_t)(b*3 + c) * 16384;
        int y0 = 2*ph - 1, x0 = 2*pw - 1;
        float acc = 0.f;
        #pragma unroll
        for (int dy = 0; dy < 3; dy++) {
            int yy = y0 + dy;
            if (yy < 0) continue;
            #pragma unroll
            for (int dx = 0; dx < 3; dx++) {
                int xx = x0 + dx;
                if (xx < 0) continue;
                acc += __ldg(xp + yy*128 + xx);
            }
        }
        Hs[t] = acc * (1.f / 9.f);
    }

    WAITG(2);            // g0 done
    __syncthreads();

    // CS0: cond-sum for block a
    if (t < 128) {
        float cs = B1s[t];
        #pragma unroll
        for (int k = 0; k < 16; k++) cs = fmaf(POSs[k], W1s[(1 + k)*128 + t], cs);
        CSs[t] = cs;
    }
    __syncthreads();

    const int bq = t & 15, oq = t >> 4;
    const int b0 = 2 * bq, o0 = 8 * oq;

    for (int blk = 0; blk < 2; blk++) {
        // ---- layer 1: lanes vary b -> conflict-free stride-32 stores ----
        {
            int b = t & 31, og = t >> 5;
            float h = Hs[b * 3];
            const float* CS = CSs + blk * 128;
            #pragma unroll
            for (int r = 0; r < 16; r++) {
                int o = og * 16 + r;
                float v = fmaf(h, W1s[o], CS[o]);
                As[o * 32 + b] = v * normcdff(v);
            }
        }
        __syncthreads();   // A1 ready; (blk0) W1a fully read

        if (blk == 0) {
            // g3: w1b, b1b, b2b into the now-free small buffers
            for (int i = 4*t; i < 2176; i += 1024) cp16(W1s + i, w1b + (size_t)p*2176 + i);
            for (int i = 4*t; i < 128;  i += 1024) cp16(B1s + i, b1b + (size_t)p*128 + i);
            for (int i = 4*t; i < 128;  i += 1024) cp16(B2s + 128 + i, b2b + (size_t)p*128 + i);
            COMMIT();      // g3
        }

        // ---- layer 2: 32x128 @ 128x128, K streamed in 4 chunks ----
        unsigned long long a00 = 0, a01 = 0, a02 = 0, a03 = 0;
        unsigned long long a10 = 0, a11 = 0, a12 = 0, a13 = 0;
        #pragma unroll
        for (int c = 0; c < 4; c++) {
            if (blk == 0) { if (c < 2) { WAITG(2); } else { WAITG(1); } }
            else          { if (c < 3) { WAITG(1); } else { WAITG(0); } }
            __syncthreads();    // chunk c resident for everyone

            const float* Ab = As + c * 32 * 32 + b0;
            const float* Wb = ((c & 1) ? W2s1 : W2s0) + o0;
            #pragma unroll 4
            for (int i = 0; i < 32; i++) {
                float2 av = *(const float2*)(Ab + i * 32);
                unsigned long long d0 = pack2(av.x, av.x);
                unsigned long long d1 = pack2(av.y, av.y);
                ulonglong2 w01 = *(const ulonglong2*)(Wb + (size_t)i * 128);
                ulonglong2 w23 = *(const ulonglong2*)(Wb + (size_t)i * 128 + 4);
                a00 = ffma2(d0, w01.x, a00);
                a01 = ffma2(d0, w01.y, a01);
                a02 = ffma2(d0, w23.x, a02);
                a03 = ffma2(d0, w23.y, a03);
                a10 = ffma2(d1, w01.x, a10);
                a11 = ffma2(d1, w01.y, a11);
                a12 = ffma2(d1, w23.x, a12);
                a13 = ffma2(d1, w23.y, a13);
            }
            __syncthreads();    // everyone done reading this chunk's buffer

            if (blk == 0) {
                if      (c == 0) { issue_w2(W2s0, w2aP + 2*4096, t); COMMIT(); } // g4
                else if (c == 1) { issue_w2(W2s1, w2aP + 3*4096, t); COMMIT(); } // g5
                else if (c == 2) { issue_w2(W2s0, w2bP,          t); COMMIT(); } // g6
            } else {
                if      (c == 0) { issue_w2(W2s0, w2bP + 2*4096, t); COMMIT(); } // g8
                else if (c == 1) { issue_w2(W2s1, w2bP + 3*4096, t); COMMIT(); } // g9
            }
        }
        // last chunk's trailing sync doubles as the A1-read barrier:
        // safe to overwrite As with A2 now.
        {
            const float* B2 = B2s + blk * 128;
            float lo, hi, v0, v1;
            #define EMIT(ACC, B_, O_) { unpack2(ACC, lo, hi);                  \
                v0 = lo + B2[(O_)]; v1 = hi + B2[(O_) + 1];                    \
                As[(O_) * 32 + (B_)]       = v0 * normcdff(v0);                \
                As[((O_) + 1) * 32 + (B_)] = v1 * normcdff(v1); }
            EMIT(a00, b0,     o0)     EMIT(a01, b0,     o0 + 2)
            EMIT(a02, b0,     o0 + 4) EMIT(a03, b0,     o0 + 6)
            EMIT(a10, b0 + 1, o0)     EMIT(a11, b0 + 1, o0 + 2)
            EMIT(a12, b0 + 1, o0 + 4) EMIT(a13, b0 + 1, o0 + 6)
            #undef EMIT
        }
        if (blk == 0) {
            // g7: w2b chunk1 (buf1 free after c3), w3b, b3b
            issue_w2(W2s1, w2bP + 4096, t);
            for (int i = 4*t; i < 512; i += 1024) cp16(W3s + 512 + i, w3b + (size_t)p*512 + i);
            if (t == 0) cp16(B3s + 4, b3b + (size_t)p*4);
            COMMIT();  // g7
        }
        __syncthreads();   // A2 ready

        // ---- layer 3: split-K over all 256 threads ----
        {
            int idx = t & 127, half = t >> 7;
            int j = idx & 3, b = idx >> 2;
            const float* W3c = W3s + blk * 512 + half * 64 * 4;
            const float* Ac  = As + half * 64 * 32 + b;
            float acc = 0.f;
            #pragma unroll 8
            for (int i = 0; i < 64; i++)
                acc = fmaf(Ac[i * 32], W3c[i * 4 + j], acc);
            A3P[t] = acc;
        }
        // block-b cond-sum, computed by upper half during blk0's layer3
        if (blk == 0 && t >= 128) {
            int o = t - 128;
            float cs = B1s[o];   // b1b (g3 complete: enforced by chunk-loop waits)
            #pragma unroll
            for (int k = 0; k < 16; k++) cs = fmaf(POSs[k], W1s[(1 + k)*128 + o], cs);
            CSs[128 + o] = cs;
        }
        __syncthreads();
        if (t < 128) {
            int j = t & 3;
            A3s[t] = (A3P[t] + A3P[t + 128] + B3s[blk * 4 + j]) * 0.1f;
        }
        __syncthreads();

        // ---- epilogue ----
        if (t < 96) {
            int b = t / 3, c = t % 3;
            float outv;
            if (c == 0) {
                outv = Hs[t];
            } else {
                float sc = 2.f * tanhf(A3s[b * 4 + (c - 1)]);
                outv = Hs[t] * expf(sc) + A3s[b * 4 + 2 + (c - 1)];
            }
            OUTs[t] = outv * SCs[blk * 3 + c] + GOs[blk * 3 + c];
        }
        if (t < 32) {
            float s0 = 2.f * tanhf(A3s[t * 4]);
            float s1 = 2.f * tanhf(A3s[t * 4 + 1]);
            float lss = logf(SCs[blk*3]) + logf(SCs[blk*3 + 1]) + logf(SCs[blk*3 + 2]);
            LDJs[t] += s0 + s1 + lss;
        }
        __syncthreads();
        if (t < 96) {
            int b = t / 3, k = t % 3;
            Hs[t] = OUTs[b * 3 + PMs[blk * 3 + k]];
        }
        __syncthreads();
    }

    if (t < 96) zout[(size_t)p * 96 + t] = Hs[t];
    if (t < 32) ldjout[(size_t)p * 32 + t] = LDJs[t];
}

extern "C" void kernel_launch(void* const* d_in, const int* in_sizes, int n_in,
                              void* d_out, int out_size) {
    (void)n_in; (void)out_size;

    int ia[9], ib[9];
    if (in_sizes[10] == 12288) {
        const int A[9]  = {2, 3, 4, 5, 6, 7, 8, 9, 10};
        const int Bn[9] = {11, 12, 13, 14, 15, 16, 17, 18, 19};
        for (int i = 0; i < 9; i++) { ia[i] = A[i]; ib[i] = Bn[i]; }
    } else {
        const int A[9]  = {2, 3, 4, 5, 6, 7, 8, 9, 18};
        const int Bn[9] = {10, 11, 12, 13, 14, 15, 16, 17, 19};
        for (int i = 0; i < 9; i++) { ia[i] = A[i]; ib[i] = Bn[i]; }
    }

    cudaFuncSetAttribute(patchflow_kernel,
                         cudaFuncAttributeMaxDynamicSharedMemorySize, SMEM_BYTES);

    float* z = (float*)d_out;                 // [4096, 32, 3]
    float* ldj = z + (size_t)4096 * 32 * 3;   // [4096, 32]

    patchflow_kernel<<<4096, 256, SMEM_BYTES>>>(
        (const float*)d_in[0], (const float*)d_in[1],
        (const float*)d_in[ia[0]], (const float*)d_in[ia[1]],
        (const float*)d_in[ia[2]], (const float*)d_in[ia[3]],
        (const float*)d_in[ia[4]], (const float*)d_in[ia[5]],
        (const float*)d_in[ia[6]], (const float*)d_in[ia[7]],
        (const int*)d_in[ia[8]],
        (const float*)d_in[ib[0]], (const float*)d_in[ib[1]],
        (const float*)d_in[ib[2]], (const float*)d_in[ib[3]],
        (const float*)d_in[ib[4]], (const float*)d_in[ib[5]],
        (const float*)d_in[ib[6]], (const float*)d_in[ib[7]],
        (const int*)d_in[ib[8]],
        z, ldj);
}

// round 4
// speedup vs baseline: 1.8225x; 1.2632x over previous
#include <cuda_runtime.h>
#include <cstdint>

// ---- shared memory layout (floats) ----
#define OFF_W2S0 0        // 4096 (W2 K-chunk ping)
#define OFF_W2S1 4096     // 4096 (W2 K-chunk pong)
#define OFF_A    8192     // 4096 (A1 then A2 in place, [i][b] stride 32)
#define OFF_B2   12288    // 256  [0:128]=a [128:256]=b
#define OFF_W3   12544    // 1024 [0:512]=a [512:1024]=b
#define OFF_B3   13568    // 8
#define OFF_CS   13576    // 256  [0:128]=CS_a [128:256]=CS_b
#define OFF_A3   13832    // 128
#define OFF_H    13960    // 96
#define SMEM_FLOATS 14056
#define SMEM_BYTES (SMEM_FLOATS * 4)

__device__ __forceinline__ unsigned long long pack2(float lo, float hi) {
    unsigned long long r;
    asm("mov.b64 %0, {%1, %2};" : "=l"(r) : "f"(lo), "f"(hi));
    return r;
}
__device__ __forceinline__ void unpack2(unsigned long long v, float &lo, float &hi) {
    asm("mov.b64 {%0, %1}, %2;" : "=f"(lo), "=f"(hi) : "l"(v));
}
__device__ __forceinline__ unsigned long long ffma2(unsigned long long a, unsigned long long b,
                                                    unsigned long long c) {
    unsigned long long d;
    asm("fma.rn.f32x2 %0, %1, %2, %3;" : "=l"(d) : "l"(a), "l"(b), "l"(c));
    return d;
}
__device__ __forceinline__ void cp16(float* s, const float* g) {
    unsigned a = (unsigned)__cvta_generic_to_shared(s);
    asm volatile("cp.async.cg.shared.global [%0], [%1], 16;" :: "r"(a), "l"(g));
}
#define COMMIT()  asm volatile("cp.async.commit_group;")
#define WAITG(N)  asm volatile("cp.async.wait_group %0;" :: "n"(N))

__device__ __forceinline__ void issue_w2(float* dst, const float* src, int t) {
    #pragma unroll
    for (int i = 4 * t; i < 4096; i += 1024) cp16(dst + i, src + i);
}

// exact GELU via A&S 7.1.26 erfc (|abs err| <= ~1.5e-7)
__device__ __forceinline__ float gelu_fast(float v) {
    float z = fabsf(v) * 0.7071067811865475f;
    float t;
    asm("rcp.approx.f32 %0, %1;" : "=f"(t) : "f"(fmaf(0.3275911f, z, 1.0f)));
    float e;
    asm("ex2.approx.f32 %0, %1;" : "=f"(e) : "f"(z * z * -1.4426950408889634f));
    float poly = fmaf(t, 1.061405429f, -1.453152027f);
    poly = fmaf(t, poly, 1.421413741f);
    poly = fmaf(t, poly, -0.284496736f);
    poly = fmaf(t, poly, 0.254829592f);
    float erfc_half = 0.5f * (poly * t) * e;            // 0.5*erfc(z), z>=0
    float phi = 0.5f + copysignf(0.5f - erfc_half, v);  // Phi(v)
    return v * phi;
}

__global__ void __launch_bounds__(256, 4)
patchflow_kernel(const float* __restrict__ x, const float* __restrict__ pos,
                 const float* __restrict__ w1a, const float* __restrict__ b1a,
                 const float* __restrict__ w2a, const float* __restrict__ b2a,
                 const float* __restrict__ w3a, const float* __restrict__ b3a,
                 const float* __restrict__ gsa, const float* __restrict__ goa,
                 const int* __restrict__ pma,
                 const float* __restrict__ w1b, const float* __restrict__ b1b,
                 const float* __restrict__ w2b, const float* __restrict__ b2b,
                 const float* __restrict__ w3b, const float* __restrict__ b3b,
                 const float* __restrict__ gsb, const float* __restrict__ gob,
                 const int* __restrict__ pmb,
                 float* __restrict__ zout, float* __restrict__ ldjout)
{
    extern __shared__ float sm[];
    const int p = blockIdx.x;
    const int t = threadIdx.x;

    float* W2s0 = sm + OFF_W2S0;
    float* W2s1 = sm + OFF_W2S1;
    float* As   = sm + OFF_A;
    float* B2s  = sm + OFF_B2;
    float* W3s  = sm + OFF_W3;
    float* B3s  = sm + OFF_B3;
    float* CSs  = sm + OFF_CS;
    float* A3s  = sm + OFF_A3;
    float* Hs   = sm + OFF_H;

    const float* w2aP = w2a + (size_t)p * 16384;
    const float* w2bP = w2b + (size_t)p * 16384;

    // ---- g0: W2a chunk0 + all small weights (both blocks) ----
    issue_w2(W2s0, w2aP, t);
    {
        int i = 4 * t;
        if (i < 128) { cp16(B2s + i, b2a + (size_t)p*128 + i);
                       cp16(B2s + 128 + i, b2b + (size_t)p*128 + i); }
        if (i < 512) { cp16(W3s + i, w3a + (size_t)p*512 + i);
                       cp16(W3s + 512 + i, w3b + (size_t)p*512 + i); }
        if (t == 0) { cp16(B3s, b3a + (size_t)p*4); cp16(B3s + 4, b3b + (size_t)p*4); }
    }
    COMMIT();                                   // g0
    issue_w2(W2s1, w2aP + 4096, t); COMMIT();   // g1

    // ---- 3x3 stride-2 avg pool ----
    if (t < 96) {
        int b = t / 3, c = t % 3;
        int ph = p >> 6, pw = p & 63;
        const float* xp = x + (size_t)(b*3 + c) * 16384;
        int y0 = 2*ph - 1, x0 = 2*pw - 1;
        float acc = 0.f;
        #pragma unroll
        for (int dy = 0; dy < 3; dy++) {
            int yy = y0 + dy;
            if (yy < 0) continue;
            #pragma unroll
            for (int dx = 0; dx < 3; dx++) {
                int xx = x0 + dx;
                if (xx < 0) continue;
                acc += __ldg(xp + yy*128 + xx);
            }
        }
        Hs[t] = acc * (1.f / 9.f);
    }

    // ---- cond-sums for BOTH blocks, straight from gmem (coalesced in o) ----
    {
        int o = t & 127;
        const float* w1P = ((t < 128) ? w1a : w1b) + (size_t)p * 2176;
        const float* b1P = ((t < 128) ? b1a : b1b) + (size_t)p * 128;
        const float* posP = pos + (size_t)p * 16;
        float cs = __ldg(b1P + o);
        #pragma unroll
        for (int k = 0; k < 16; k++)
            cs = fmaf(__ldg(posP + k), __ldg(w1P + (1 + k)*128 + o), cs);
        CSs[t] = cs;   // t<128 -> CS_a[o]; t>=128 -> CS_b[o]
    }
    __syncthreads();

    const int bq = t & 15, oq = t >> 4;
    const int b0 = 2 * bq, o0 = 8 * oq;
    float ldj = 0.f;   // valid for t<32

    for (int blk = 0; blk < 2; blk++) {
        // ---- layer 1 (no trailing sync: first chunk-wait's sync covers it) ----
        {
            int b = t & 31, og = t >> 5;
            float h = Hs[b * 3];
            const float* w1r0 = (blk ? w1b : w1a) + (size_t)p * 2176;  // row 0
            const float* CS = CSs + blk * 128;
            #pragma unroll
            for (int r = 0; r < 16; r++) {
                int o = og * 16 + r;
                float v = fmaf(h, __ldg(w1r0 + o), CS[o]);
                As[o * 32 + b] = gelu_fast(v);
            }
        }

        // ---- layer 2: K streamed in 4 chunks (16KB each), double-buffered ----
        unsigned long long a00 = 0, a01 = 0, a02 = 0, a03 = 0;
        unsigned long long a10 = 0, a11 = 0, a12 = 0, a13 = 0;
        #pragma unroll
        for (int c = 0; c < 4; c++) {
            int j = blk * 4 + c;                // global chunk 0..7
            if (j == 7) { WAITG(0); } else { WAITG(1); }
            __syncthreads();                    // chunk j resident (+ As visible on c==0)

            const float* Ab = As + c * 1024 + b0;
            const float* Wb = ((c & 1) ? W2s1 : W2s0) + o0;
            #pragma unroll 4
            for (int i = 0; i < 32; i++) {
                float2 av = *(const float2*)(Ab + i * 32);
                unsigned long long d0 = pack2(av.x, av.x);
                unsigned long long d1 = pack2(av.y, av.y);
                ulonglong2 w01 = *(const ulonglong2*)(Wb + (size_t)i * 128);
                ulonglong2 w23 = *(const ulonglong2*)(Wb + (size_t)i * 128 + 4);
                a00 = ffma2(d0, w01.x, a00);
                a01 = ffma2(d0, w01.y, a01);
                a02 = ffma2(d0, w23.x, a02);
                a03 = ffma2(d0, w23.y, a03);
                a10 = ffma2(d1, w01.x, a10);
                a11 = ffma2(d1, w01.y, a11);
                a12 = ffma2(d1, w23.x, a12);
                a13 = ffma2(d1, w23.y, a13);
            }
            __syncthreads();                    // buffer free for refill

            if (j <= 5) {                       // prefetch chunk j+2 into same buffer
                const float* src = (j < 2) ? (w2aP + (j + 2) * 4096)
                                           : (w2bP + (j - 2) * 4096);
                issue_w2((j & 1) ? W2s1 : W2s0, src, t);
                COMMIT();
            }
        }

        // ---- A2 = gelu(acc + b2), overwrites As in place ----
        {
            const float* B2 = B2s + blk * 128;
            float lo, hi, v0, v1;
            #define EMIT(ACC, B_, O_) { unpack2(ACC, lo, hi);              \
                v0 = lo + B2[(O_)]; v1 = hi + B2[(O_) + 1];                \
                As[(O_) * 32 + (B_)]       = gelu_fast(v0);                \
                As[((O_) + 1) * 32 + (B_)] = gelu_fast(v1); }
            EMIT(a00, b0,     o0)     EMIT(a01, b0,     o0 + 2)
            EMIT(a02, b0,     o0 + 4) EMIT(a03, b0,     o0 + 6)
            EMIT(a10, b0 + 1, o0)     EMIT(a11, b0 + 1, o0 + 2)
            EMIT(a12, b0 + 1, o0 + 4) EMIT(a13, b0 + 1, o0 + 6)
            #undef EMIT
        }
        __syncthreads();                        // A2 ready

        // ---- layer 3: 128 threads, full K ----
        if (t < 128) {
            int jj = t & 3, b = t >> 2;
            const float* W3c = W3s + blk * 512;
            float acc = 0.f;
            #pragma unroll 8
            for (int i = 0; i < 128; i++)
                acc = fmaf(As[i * 32 + b], W3c[i * 4 + jj], acc);
            A3s[t] = (acc + B3s[blk * 4 + jj]) * 0.1f;
        }
        __syncthreads();                        // A3 ready

        // ---- fused epilogue + permutation: one thread per batch row ----
        if (t < 32) {
            int b = t;
            const float* gsP = (blk ? gsb : gsa) + (size_t)p * 3;
            const float* goP = (blk ? gob : goa) + (size_t)p * 3;
            const int*   pmP = (blk ? pmb : pma) + (size_t)p * 3;
            float sc0, sc1, sc2, lg;
            {
                float y0 = 0.5f * __ldg(gsP);
                float y1 = 0.5f * __ldg(gsP + 1);
                float y2 = 0.5f * __ldg(gsP + 2);
                sc0 = 0.2f * ((y0 > 15.f) ? y0 : log1pf(expf(y0)));
                sc1 = 0.2f * ((y1 > 15.f) ? y1 : log1pf(expf(y1)));
                sc2 = 0.2f * ((y2 > 15.f) ? y2 : log1pf(expf(y2)));
                lg = logf(sc0) + logf(sc1) + logf(sc2);
            }
            float s0 = 2.f * tanhf(A3s[b * 4]);
            float s1 = 2.f * tanhf(A3s[b * 4 + 1]);
            float ov0 = Hs[b * 3];
            float ov1 = Hs[b * 3 + 1] * expf(s0) + A3s[b * 4 + 2];
            float ov2 = Hs[b * 3 + 2] * expf(s1) + A3s[b * 4 + 3];
            ov0 = ov0 * sc0 + __ldg(goP);
            ov1 = ov1 * sc1 + __ldg(goP + 1);
            ov2 = ov2 * sc2 + __ldg(goP + 2);
            ldj += s0 + s1 + lg;
            int k0 = __ldg(pmP), k1 = __ldg(pmP + 1), k2 = __ldg(pmP + 2);
            Hs[b * 3 + 0] = (k0 == 0) ? ov0 : ((k0 == 1) ? ov1 : ov2);
            Hs[b * 3 + 1] = (k1 == 0) ? ov0 : ((k1 == 1) ? ov1 : ov2);
            Hs[b * 3 + 2] = (k2 == 0) ? ov0 : ((k2 == 1) ? ov1 : ov2);
        }
        __syncthreads();                        // Hs visible for next block / store
    }

    if (t < 96) zout[(size_t)p * 96 + t] = Hs[t];
    if (t < 32) ldjout[(size_t)p * 32 + t] = ldj;
}

extern "C" void kernel_launch(void* const* d_in, const int* in_sizes, int n_in,
                              void* d_out, int out_size) {
    (void)n_in; (void)out_size;

    int ia[9], ib[9];
    if (in_sizes[10] == 12288) {
        const int A[9]  = {2, 3, 4, 5, 6, 7, 8, 9, 10};
        const int Bn[9] = {11, 12, 13, 14, 15, 16, 17, 18, 19};
        for (int i = 0; i < 9; i++) { ia[i] = A[i]; ib[i] = Bn[i]; }
    } else {
        const int A[9]  = {2, 3, 4, 5, 6, 7, 8, 9, 18};
        const int Bn[9] = {10, 11, 12, 13, 14, 15, 16, 17, 19};
        for (int i = 0; i < 9; i++) { ia[i] = A[i]; ib[i] = Bn[i]; }
    }

    cudaFuncSetAttribute(patchflow_kernel,
                         cudaFuncAttributeMaxDynamicSharedMemorySize, SMEM_BYTES);

    float* z = (float*)d_out;                 // [4096, 32, 3]
    float* ldj = z + (size_t)4096 * 32 * 3;   // [4096, 32]

    patchflow_kernel<<<4096, 256, SMEM_BYTES>>>(
        (const float*)d_in[0], (const float*)d_in[1],
        (const float*)d_in[ia[0]], (const float*)d_in[ia[1]],
        (const float*)d_in[ia[2]], (const float*)d_in[ia[3]],
        (const float*)d_in[ia[4]], (const float*)d_in[ia[5]],
        (const float*)d_in[ia[6]], (const float*)d_in[ia[7]],
        (const int*)d_in[ia[8]],
        (const float*)d_in[ib[0]], (const float*)d_in[ib[1]],
        (const float*)d_in[ib[2]], (const float*)d_in[ib[3]],
        (const float*)d_in[ib[4]], (const float*)d_in[ib[5]],
        (const float*)d_in[ib[6]], (const float*)d_in[ib[7]],
        (const int*)d_in[ib[8]],
        z, ldj);
}

// round 5
// speedup vs baseline: 1.8376x; 1.0083x over previous
#include <cuda_runtime.h>
#include <cstdint>

// ---- shared memory layout (floats) ----
#define OFF_W2S0 0        // 4096 (W2 K-chunk ping)
#define OFF_W2S1 4096     // 4096 (W2 K-chunk pong)
#define OFF_A    8192     // 4096 (A1, then K-half partials, then A2 in place)
#define OFF_B2   12288    // 256  [0:128]=a [128:256]=b
#define OFF_W3   12544    // 1024 [0:512]=a [512:1024]=b
#define OFF_B3   13568    // 8
#define OFF_CS   13576    // 256  [0:128]=CS_a [128:256]=CS_b
#define OFF_A3   13832    // 128
#define OFF_H    13960    // 96
#define SMEM_FLOATS 14056
#define SMEM_BYTES (SMEM_FLOATS * 4)

__device__ __forceinline__ unsigned long long pack2(float lo, float hi) {
    unsigned long long r;
    asm("mov.b64 %0, {%1, %2};" : "=l"(r) : "f"(lo), "f"(hi));
    return r;
}
__device__ __forceinline__ void unpack2(unsigned long long v, float &lo, float &hi) {
    asm("mov.b64 {%0, %1}, %2;" : "=f"(lo), "=f"(hi) : "l"(v));
}
__device__ __forceinline__ unsigned long long ffma2(unsigned long long a, unsigned long long b,
                                                    unsigned long long c) {
    unsigned long long d;
    asm("fma.rn.f32x2 %0, %1, %2, %3;" : "=l"(d) : "l"(a), "l"(b), "l"(c));
    return d;
}
__device__ __forceinline__ void cp16(float* s, const float* g) {
    unsigned a = (unsigned)__cvta_generic_to_shared(s);
    asm volatile("cp.async.cg.shared.global [%0], [%1], 16;" :: "r"(a), "l"(g));
}
#define COMMIT()  asm volatile("cp.async.commit_group;")
#define WAITG(N)  asm volatile("cp.async.wait_group %0;" :: "n"(N))

__device__ __forceinline__ void issue_w2(float* dst, const float* src, int t) {
    #pragma unroll
    for (int i = 4 * t; i < 4096; i += 1024) cp16(dst + i, src + i);
}

// exact GELU via A&S 7.1.26 erfc (|abs err| <= ~1.5e-7)
__device__ __forceinline__ float gelu_fast(float v) {
    float z = fabsf(v) * 0.7071067811865475f;
    float t;
    asm("rcp.approx.f32 %0, %1;" : "=f"(t) : "f"(fmaf(0.3275911f, z, 1.0f)));
    float e;
    asm("ex2.approx.f32 %0, %1;" : "=f"(e) : "f"(z * z * -1.4426950408889634f));
    float poly = fmaf(t, 1.061405429f, -1.453152027f);
    poly = fmaf(t, poly, 1.421413741f);
    poly = fmaf(t, poly, -0.284496736f);
    poly = fmaf(t, poly, 0.254829592f);
    float erfc_half = 0.5f * (poly * t) * e;            // 0.5*erfc(z), z>=0
    float phi = 0.5f + copysignf(0.5f - erfc_half, v);  // Phi(v)
    return v * phi;
}

__global__ void __launch_bounds__(256, 4)
patchflow_kernel(const float* __restrict__ x, const float* __restrict__ pos,
                 const float* __restrict__ w1a, const float* __restrict__ b1a,
                 const float* __restrict__ w2a, const float* __restrict__ b2a,
                 const float* __restrict__ w3a, const float* __restrict__ b3a,
                 const float* __restrict__ gsa, const float* __restrict__ goa,
                 const int* __restrict__ pma,
                 const float* __restrict__ w1b, const float* __restrict__ b1b,
                 const float* __restrict__ w2b, const float* __restrict__ b2b,
                 const float* __restrict__ w3b, const float* __restrict__ b3b,
                 const float* __restrict__ gsb, const float* __restrict__ gob,
                 const int* __restrict__ pmb,
                 float* __restrict__ zout, float* __restrict__ ldjout)
{
    extern __shared__ float sm[];
    const int p = blockIdx.x;
    const int t = threadIdx.x;

    float* W2s0 = sm + OFF_W2S0;
    float* W2s1 = sm + OFF_W2S1;
    float* As   = sm + OFF_A;
    float* B2s  = sm + OFF_B2;
    float* W3s  = sm + OFF_W3;
    float* B3s  = sm + OFF_B3;
    float* CSs  = sm + OFF_CS;
    float* A3s  = sm + OFF_A3;
    float* Hs   = sm + OFF_H;

    const float* w2aP = w2a + (size_t)p * 16384;
    const float* w2bP = w2b + (size_t)p * 16384;

    // ---- g0: W2a chunk0 + all small weights (both blocks) ----
    issue_w2(W2s0, w2aP, t);
    {
        int i = 4 * t;
        if (i < 128) { cp16(B2s + i, b2a + (size_t)p*128 + i);
                       cp16(B2s + 128 + i, b2b + (size_t)p*128 + i); }
        if (i < 512) { cp16(W3s + i, w3a + (size_t)p*512 + i);
                       cp16(W3s + 512 + i, w3b + (size_t)p*512 + i); }
        if (t == 0) { cp16(B3s, b3a + (size_t)p*4); cp16(B3s + 4, b3b + (size_t)p*4); }
    }
    COMMIT();                                   // g0
    issue_w2(W2s1, w2aP + 4096, t); COMMIT();   // g1

    // ---- 3x3 stride-2 avg pool ----
    if (t < 96) {
        int b = t / 3, c = t % 3;
        int ph = p >> 6, pw = p & 63;
        const float* xp = x + (size_t)(b*3 + c) * 16384;
        int y0 = 2*ph - 1, x0 = 2*pw - 1;
        float acc = 0.f;
        #pragma unroll
        for (int dy = 0; dy < 3; dy++) {
            int yy = y0 + dy;
            if (yy < 0) continue;
            #pragma unroll
            for (int dx = 0; dx < 3; dx++) {
                int xx = x0 + dx;
                if (xx < 0) continue;
                acc += __ldg(xp + yy*128 + xx);
            }
        }
        Hs[t] = acc * (1.f / 9.f);
    }

    // ---- cond-sums for BOTH blocks, straight from gmem (coalesced in o) ----
    {
        int o = t & 127;
        const float* w1P = ((t < 128) ? w1a : w1b) + (size_t)p * 2176;
        const float* b1P = ((t < 128) ? b1a : b1b) + (size_t)p * 128;
        const float* posP = pos + (size_t)p * 16;
        float cs = __ldg(b1P + o);
        #pragma unroll
        for (int k = 0; k < 16; k++)
            cs = fmaf(__ldg(posP + k), __ldg(w1P + (1 + k)*128 + o), cs);
        CSs[t] = cs;   // t<128 -> CS_a[o]; t>=128 -> CS_b[o]
    }
    __syncthreads();

    // GEMM2 mapping: K-split halves, 4b x 8o register tile
    const int kh = t >> 7;                 // K-half: rows [16kh,16kh+16) of each chunk
    const int tt = t & 127;
    const int b0 = 4 * (tt & 7);           // 4 consecutive batches
    const int o0 = 8 * (tt >> 3);          // 8 consecutive outputs
    float ldj = 0.f;                       // valid for t<32

    for (int blk = 0; blk < 2; blk++) {
        // ---- layer 1 ----
        {
            int b = t & 31, og = t >> 5;
            float h = Hs[b * 3];
            const float* w1r0 = (blk ? w1b : w1a) + (size_t)p * 2176;  // row 0
            const float* CS = CSs + blk * 128;
            #pragma unroll
            for (int r = 0; r < 16; r++) {
                int o = og * 16 + r;
                float v = fmaf(h, __ldg(w1r0 + o), CS[o]);
                As[o * 32 + b] = gelu_fast(v);
            }
        }

        // ---- layer 2: K streamed in 4 chunks; each half does 16 rows/chunk ----
        unsigned long long acc0[4], acc1[4], acc2[4], acc3[4];  // [b][opair]
        #pragma unroll
        for (int o = 0; o < 4; o++) { acc0[o] = 0; acc1[o] = 0; acc2[o] = 0; acc3[o] = 0; }

        #pragma unroll
        for (int c = 0; c < 4; c++) {
            int j = blk * 4 + c;                // global chunk 0..7
            if (j == 7) { WAITG(0); } else { WAITG(1); }
            __syncthreads();                    // chunk j resident (+ As visible on c==0)

            const float* Ab = As + (c * 32 + kh * 16) * 32 + b0;
            const float* Wb = ((c & 1) ? W2s1 : W2s0) + kh * 16 * 128 + o0;
            #pragma unroll 4
            for (int i = 0; i < 16; i++) {
                float4 av = *(const float4*)(Ab);
                ulonglong2 w01 = *(const ulonglong2*)(Wb);
                ulonglong2 w23 = *(const ulonglong2*)(Wb + 4);
                unsigned long long d;
                d = pack2(av.x, av.x);
                acc0[0] = ffma2(d, w01.x, acc0[0]);
                acc0[1] = ffma2(d, w01.y, acc0[1]);
                acc0[2] = ffma2(d, w23.x, acc0[2]);
                acc0[3] = ffma2(d, w23.y, acc0[3]);
                d = pack2(av.y, av.y);
                acc1[0] = ffma2(d, w01.x, acc1[0]);
                acc1[1] = ffma2(d, w01.y, acc1[1]);
                acc1[2] = ffma2(d, w23.x, acc1[2]);
                acc1[3] = ffma2(d, w23.y, acc1[3]);
                d = pack2(av.z, av.z);
                acc2[0] = ffma2(d, w01.x, acc2[0]);
                acc2[1] = ffma2(d, w01.y, acc2[1]);
                acc2[2] = ffma2(d, w23.x, acc2[2]);
                acc2[3] = ffma2(d, w23.y, acc2[3]);
                d = pack2(av.w, av.w);
                acc3[0] = ffma2(d, w01.x, acc3[0]);
                acc3[1] = ffma2(d, w01.y, acc3[1]);
                acc3[2] = ffma2(d, w23.x, acc3[2]);
                acc3[3] = ffma2(d, w23.y, acc3[3]);
                Ab += 32; Wb += 128;
            }
            __syncthreads();                    // buffer free for refill

            if (j <= 5) {                       // prefetch chunk j+2 into same buffer
                const float* src = (j < 2) ? (w2aP + (j + 2) * 4096)
                                           : (w2bP + (j - 2) * 4096);
                issue_w2((j & 1) ? W2s1 : W2s0, src, t);
                COMMIT();
            }
        }

        // unpack accumulators -> f[b][o_local]
        float f0[8], f1[8], f2[8], f3[8];
        #pragma unroll
        for (int o = 0; o < 4; o++) {
            unpack2(acc0[o], f0[2*o], f0[2*o + 1]);
            unpack2(acc1[o], f1[2*o], f1[2*o + 1]);
            unpack2(acc2[o], f2[2*o], f2[2*o + 1]);
            unpack2(acc3[o], f3[2*o], f3[2*o + 1]);
        }

        // ---- K-half reduction through the dead A1 region ----
        if (kh == 1) {
            #pragma unroll
            for (int k = 0; k < 8; k++) {
                float4 v = make_float4(f0[k], f1[k], f2[k], f3[k]);
                *(float4*)(As + (o0 + k) * 32 + b0) = v;
            }
        }
        __syncthreads();
        if (kh == 0) {
            const float* B2 = B2s + blk * 128;
            #pragma unroll
            for (int k = 0; k < 8; k++) {
                float4 pp = *(const float4*)(As + (o0 + k) * 32 + b0);
                float bias = B2[o0 + k];
                float4 v;
                v.x = gelu_fast(f0[k] + pp.x + bias);
                v.y = gelu_fast(f1[k] + pp.y + bias);
                v.z = gelu_fast(f2[k] + pp.z + bias);
                v.w = gelu_fast(f3[k] + pp.w + bias);
                *(float4*)(As + (o0 + k) * 32 + b0) = v;
            }
        }
        __syncthreads();                        // A2 ready

        // ---- layer 3: 128 threads, full K ----
        if (t < 128) {
            int jj = t & 3, b = t >> 2;
            const float* W3c = W3s + blk * 512;
            float acc = 0.f;
            #pragma unroll 8
            for (int i = 0; i < 128; i++)
                acc = fmaf(As[i * 32 + b], W3c[i * 4 + jj], acc);
            A3s[t] = (acc + B3s[blk * 4 + jj]) * 0.1f;
        }
        __syncthreads();                        // A3 ready

        // ---- fused epilogue + permutation: one thread per batch row ----
        if (t < 32) {
            int b = t;
            const float* gsP = (blk ? gsb : gsa) + (size_t)p * 3;
            const float* goP = (blk ? gob : goa) + (size_t)p * 3;
            const int*   pmP = (blk ? pmb : pma) + (size_t)p * 3;
            float sc0, sc1, sc2, lg;
            {
                float y0 = 0.5f * __ldg(gsP);
                float y1 = 0.5f * __ldg(gsP + 1);
                float y2 = 0.5f * __ldg(gsP + 2);
                sc0 = 0.2f * ((y0 > 15.f) ? y0 : log1pf(expf(y0)));
                sc1 = 0.2f * ((y1 > 15.f) ? y1 : log1pf(expf(y1)));
                sc2 = 0.2f * ((y2 > 15.f) ? y2 : log1pf(expf(y2)));
                lg = logf(sc0) + logf(sc1) + logf(sc2);
            }
            float s0 = 2.f * tanhf(A3s[b * 4]);
            float s1 = 2.f * tanhf(A3s[b * 4 + 1]);
            float ov0 = Hs[b * 3];
            float ov1 = Hs[b * 3 + 1] * expf(s0) + A3s[b * 4 + 2];
            float ov2 = Hs[b * 3 + 2] * expf(s1) + A3s[b * 4 + 3];
            ov0 = ov0 * sc0 + __ldg(goP);
            ov1 = ov1 * sc1 + __ldg(goP + 1);
            ov2 = ov2 * sc2 + __ldg(goP + 2);
            ldj += s0 + s1 + lg;
            int k0 = __ldg(pmP), k1 = __ldg(pmP + 1), k2 = __ldg(pmP + 2);
            Hs[b * 3 + 0] = (k0 == 0) ? ov0 : ((k0 == 1) ? ov1 : ov2);
            Hs[b * 3 + 1] = (k1 == 0) ? ov0 : ((k1 == 1) ? ov1 : ov2);
            Hs[b * 3 + 2] = (k2 == 0) ? ov0 : ((k2 == 1) ? ov1 : ov2);
        }
        __syncthreads();                        // Hs visible for next block / store
    }

    if (t < 96) zout[(size_t)p * 96 + t] = Hs[t];
    if (t < 32) ldjout[(size_t)p * 32 + t] = ldj;
}

extern "C" void kernel_launch(void* const* d_in, const int* in_sizes, int n_in,
                              void* d_out, int out_size) {
    (void)n_in; (void)out_size;

    int ia[9], ib[9];
    if (in_sizes[10] == 12288) {
        const int A[9]  = {2, 3, 4, 5, 6, 7, 8, 9, 10};
        const int Bn[9] = {11, 12, 13, 14, 15, 16, 17, 18, 19};
        for (int i = 0; i < 9; i++) { ia[i] = A[i]; ib[i] = Bn[i]; }
    } else {
        const int A[9]  = {2, 3, 4, 5, 6, 7, 8, 9, 18};
        const int Bn[9] = {10, 11, 12, 13, 14, 15, 16, 17, 19};
        for (int i = 0; i < 9; i++) { ia[i] = A[i]; ib[i] = Bn[i]; }
    }

    cudaFuncSetAttribute(patchflow_kernel,
                         cudaFuncAttributeMaxDynamicSharedMemorySize, SMEM_BYTES);

    float* z = (float*)d_out;                 // [4096, 32, 3]
    float* ldj = z + (size_t)4096 * 32 * 3;   // [4096, 32]

    patchflow_kernel<<<4096, 256, SMEM_BYTES>>>(
        (const float*)d_in[0], (const float*)d_in[1],
        (const float*)d_in[ia[0]], (const float*)d_in[ia[1]],
        (const float*)d_in[ia[2]], (const float*)d_in[ia[3]],
        (const float*)d_in[ia[4]], (const float*)d_in[ia[5]],
        (const float*)d_in[ia[6]], (const float*)d_in[ia[7]],
        (const int*)d_in[ia[8]],
        (const float*)d_in[ib[0]], (const float*)d_in[ib[1]],
        (const float*)d_in[ib[2]], (const float*)d_in[ib[3]],
        (const float*)d_in[ib[4]], (const float*)d_in[ib[5]],
        (const float*)d_in[ib[6]], (const float*)d_in[ib[7]],
        (const int*)d_in[ib[8]],
        z, ldj);
}

// round 6
// speedup vs baseline: 1.9369x; 1.0540x over previous
#include <cuda_runtime.h>
#include <cstdint>

// ---- shared memory layout (floats) ----
#define OFF_W2S0 0        // 4096 (W2 K-chunk ping)
#define OFF_W2S1 4096     // 4096 (W2 K-chunk pong)
#define OFF_A    8192     // 4096 (A1, then K-half partials, then A2 in place)
#define OFF_B2   12288    // 256  [0:128]=a [128:256]=b
#define OFF_W3   12544    // 1024 [0:512]=a [512:1024]=b
#define OFF_B3   13568    // 8
#define OFF_CS   13576    // 256  [0:128]=CS_a [128:256]=CS_b
#define OFF_A3   13832    // 128
#define OFF_H    13960    // 96
#define SMEM_FLOATS 14056
#define SMEM_BYTES (SMEM_FLOATS * 4)

__device__ __forceinline__ unsigned long long pack2(float lo, float hi) {
    unsigned long long r;
    asm("mov.b64 %0, {%1, %2};" : "=l"(r) : "f"(lo), "f"(hi));
    return r;
}
__device__ __forceinline__ void unpack2(unsigned long long v, float &lo, float &hi) {
    asm("mov.b64 {%0, %1}, %2;" : "=f"(lo), "=f"(hi) : "l"(v));
}
__device__ __forceinline__ unsigned long long ffma2(unsigned long long a, unsigned long long b,
                                                    unsigned long long c) {
    unsigned long long d;
    asm("fma.rn.f32x2 %0, %1, %2, %3;" : "=l"(d) : "l"(a), "l"(b), "l"(c));
    return d;
}
__device__ __forceinline__ void cp16(float* s, const float* g) {
    unsigned a = (unsigned)__cvta_generic_to_shared(s);
    asm volatile("cp.async.cg.shared.global [%0], [%1], 16;" :: "r"(a), "l"(g));
}
#define COMMIT()  asm volatile("cp.async.commit_group;")
#define WAITG(N)  asm volatile("cp.async.wait_group %0;" :: "n"(N))

__device__ __forceinline__ void issue_w2(float* dst, const float* src, int t) {
    #pragma unroll
    for (int i = 4 * t; i < 4096; i += 1024) cp16(dst + i, src + i);
}

// exact GELU via A&S 7.1.26 erfc (|abs err| <= ~1.5e-7)
__device__ __forceinline__ float gelu_fast(float v) {
    float z = fabsf(v) * 0.7071067811865475f;
    float t;
    asm("rcp.approx.f32 %0, %1;" : "=f"(t) : "f"(fmaf(0.3275911f, z, 1.0f)));
    float e;
    asm("ex2.approx.f32 %0, %1;" : "=f"(e) : "f"(z * z * -1.4426950408889634f));
    float poly = fmaf(t, 1.061405429f, -1.453152027f);
    poly = fmaf(t, poly, 1.421413741f);
    poly = fmaf(t, poly, -0.284496736f);
    poly = fmaf(t, poly, 0.254829592f);
    float erfc_half = 0.5f * (poly * t) * e;            // 0.5*erfc(z), z>=0
    float phi = 0.5f + copysignf(0.5f - erfc_half, v);  // Phi(v)
    return v * phi;
}

__global__ void __launch_bounds__(256, 4)
patchflow_kernel(const float* __restrict__ x, const float* __restrict__ pos,
                 const float* __restrict__ w1a, const float* __restrict__ b1a,
                 const float* __restrict__ w2a, const float* __restrict__ b2a,
                 const float* __restrict__ w3a, const float* __restrict__ b3a,
                 const float* __restrict__ gsa, const float* __restrict__ goa,
                 const int* __restrict__ pma,
                 const float* __restrict__ w1b, const float* __restrict__ b1b,
                 const float* __restrict__ w2b, const float* __restrict__ b2b,
                 const float* __restrict__ w3b, const float* __restrict__ b3b,
                 const float* __restrict__ gsb, const float* __restrict__ gob,
                 const int* __restrict__ pmb,
                 float* __restrict__ zout, float* __restrict__ ldjout)
{
    extern __shared__ float sm[];
    const int p = blockIdx.x;
    const int t = threadIdx.x;

    float* W2s0 = sm + OFF_W2S0;
    float* W2s1 = sm + OFF_W2S1;
    float* As   = sm + OFF_A;
    float* B2s  = sm + OFF_B2;
    float* W3s  = sm + OFF_W3;
    float* B3s  = sm + OFF_B3;
    float* CSs  = sm + OFF_CS;
    float* A3s  = sm + OFF_A3;
    float* Hs   = sm + OFF_H;

    const float* w2aP = w2a + (size_t)p * 16384;
    const float* w2bP = w2b + (size_t)p * 16384;

    // ---- g0: W2a chunk0 + all small weights (both blocks) ----
    issue_w2(W2s0, w2aP, t);
    {
        int i = 4 * t;
        if (i < 128) { cp16(B2s + i, b2a + (size_t)p*128 + i);
                       cp16(B2s + 128 + i, b2b + (size_t)p*128 + i); }
        if (i < 512) { cp16(W3s + i, w3a + (size_t)p*512 + i);
                       cp16(W3s + 512 + i, w3b + (size_t)p*512 + i); }
        if (t == 0) { cp16(B3s, b3a + (size_t)p*4); cp16(B3s + 4, b3b + (size_t)p*4); }
    }
    COMMIT();                                   // g0
    issue_w2(W2s1, w2aP + 4096, t); COMMIT();   // g1

    // ---- 3x3 stride-2 avg pool ----
    if (t < 96) {
        int b = t / 3, c = t % 3;
        int ph = p >> 6, pw = p & 63;
        const float* xp = x + (size_t)(b*3 + c) * 16384;
        int y0 = 2*ph - 1, x0 = 2*pw - 1;
        float acc = 0.f;
        #pragma unroll
        for (int dy = 0; dy < 3; dy++) {
            int yy = y0 + dy;
            if (yy < 0) continue;
            #pragma unroll
            for (int dx = 0; dx < 3; dx++) {
                int xx = x0 + dx;
                if (xx < 0) continue;
                acc += __ldg(xp + yy*128 + xx);
            }
        }
        Hs[t] = acc * (1.f / 9.f);
    }

    // ---- cond-sums for BOTH blocks, straight from gmem (coalesced in o) ----
    {
        int o = t & 127;
        const float* w1P = ((t < 128) ? w1a : w1b) + (size_t)p * 2176;
        const float* b1P = ((t < 128) ? b1a : b1b) + (size_t)p * 128;
        const float* posP = pos + (size_t)p * 16;
        float cs = __ldg(b1P + o);
        #pragma unroll
        for (int k = 0; k < 16; k++)
            cs = fmaf(__ldg(posP + k), __ldg(w1P + (1 + k)*128 + o), cs);
        CSs[t] = cs;   // t<128 -> CS_a[o]; t>=128 -> CS_b[o]
    }
    __syncthreads();

    // GEMM2 mapping: K-split halves, 4b x 8o register tile
    const int kh = t >> 7;                 // K-half: rows [16kh,16kh+16) of each chunk
    const int tt = t & 127;
    const int b0 = 4 * (tt & 7);           // 4 consecutive batches
    const int o0 = 8 * (tt >> 3);          // 8 consecutive outputs
    float ldj = 0.f;                       // valid for t<32

    for (int blk = 0; blk < 2; blk++) {
        // ---- layer 1 ----
        {
            int b = t & 31, og = t >> 5;
            float h = Hs[b * 3];
            const float* w1r0 = (blk ? w1b : w1a) + (size_t)p * 2176;  // row 0
            const float* CS = CSs + blk * 128;
            #pragma unroll
            for (int r = 0; r < 16; r++) {
                int o = og * 16 + r;
                float v = fmaf(h, __ldg(w1r0 + o), CS[o]);
                As[o * 32 + b] = gelu_fast(v);
            }
        }

        // ---- layer 2: K streamed in 4 chunks; each half does 16 rows/chunk ----
        unsigned long long acc0[4], acc1[4], acc2[4], acc3[4];  // [b][opair]
        #pragma unroll
        for (int o = 0; o < 4; o++) { acc0[o] = 0; acc1[o] = 0; acc2[o] = 0; acc3[o] = 0; }

        #pragma unroll
        for (int c = 0; c < 4; c++) {
            int j = blk * 4 + c;                // global chunk 0..7
            if (j == 7) { WAITG(0); } else { WAITG(1); }
            __syncthreads();                    // chunk j resident (+ As visible on c==0)

            const float* Ab = As + (c * 32 + kh * 16) * 32 + b0;
            const float* Wb = ((c & 1) ? W2s1 : W2s0) + kh * 16 * 128 + o0;
            #pragma unroll 4
            for (int i = 0; i < 16; i++) {
                float4 av = *(const float4*)(Ab);
                ulonglong2 w01 = *(const ulonglong2*)(Wb);
                ulonglong2 w23 = *(const ulonglong2*)(Wb + 4);
                unsigned long long d;
                d = pack2(av.x, av.x);
                acc0[0] = ffma2(d, w01.x, acc0[0]);
                acc0[1] = ffma2(d, w01.y, acc0[1]);
                acc0[2] = ffma2(d, w23.x, acc0[2]);
                acc0[3] = ffma2(d, w23.y, acc0[3]);
                d = pack2(av.y, av.y);
                acc1[0] = ffma2(d, w01.x, acc1[0]);
                acc1[1] = ffma2(d, w01.y, acc1[1]);
                acc1[2] = ffma2(d, w23.x, acc1[2]);
                acc1[3] = ffma2(d, w23.y, acc1[3]);
                d = pack2(av.z, av.z);
                acc2[0] = ffma2(d, w01.x, acc2[0]);
                acc2[1] = ffma2(d, w01.y, acc2[1]);
                acc2[2] = ffma2(d, w23.x, acc2[2]);
                acc2[3] = ffma2(d, w23.y, acc2[3]);
                d = pack2(av.w, av.w);
                acc3[0] = ffma2(d, w01.x, acc3[0]);
                acc3[1] = ffma2(d, w01.y, acc3[1]);
                acc3[2] = ffma2(d, w23.x, acc3[2]);
                acc3[3] = ffma2(d, w23.y, acc3[3]);
                Ab += 32; Wb += 128;
            }
            __syncthreads();                    // buffer free for refill

            if (j <= 5) {                       // prefetch chunk j+2 into same buffer
                const float* src = (j < 2) ? (w2aP + (j + 2) * 4096)
                                           : (w2bP + (j - 2) * 4096);
                issue_w2((j & 1) ? W2s1 : W2s0, src, t);
                COMMIT();
            }
        }

        // unpack accumulators -> f[b][o_local]
        float f0[8], f1[8], f2[8], f3[8];
        #pragma unroll
        for (int o = 0; o < 4; o++) {
            unpack2(acc0[o], f0[2*o], f0[2*o + 1]);
            unpack2(acc1[o], f1[2*o], f1[2*o + 1]);
            unpack2(acc2[o], f2[2*o], f2[2*o + 1]);
            unpack2(acc3[o], f3[2*o], f3[2*o + 1]);
        }

        // ---- K-half reduction through the dead A1 region ----
        if (kh == 1) {
            #pragma unroll
            for (int k = 0; k < 8; k++) {
                float4 v = make_float4(f0[k], f1[k], f2[k], f3[k]);
                *(float4*)(As + (o0 + k) * 32 + b0) = v;
            }
        }
        __syncthreads();
        if (kh == 0) {
            const float* B2 = B2s + blk * 128;
            #pragma unroll
            for (int k = 0; k < 8; k++) {
                float4 pp = *(const float4*)(As + (o0 + k) * 32 + b0);
                float bias = B2[o0 + k];
                float4 v;
                v.x = gelu_fast(f0[k] + pp.x + bias);
                v.y = gelu_fast(f1[k] + pp.y + bias);
                v.z = gelu_fast(f2[k] + pp.z + bias);
                v.w = gelu_fast(f3[k] + pp.w + bias);
                *(float4*)(As + (o0 + k) * 32 + b0) = v;
            }
        }
        __syncthreads();                        // A2 ready

        // ---- layer 3: 128 threads, full K ----
        if (t < 128) {
            int jj = t & 3, b = t >> 2;
            const float* W3c = W3s + blk * 512;
            float acc = 0.f;
            #pragma unroll 8
            for (int i = 0; i < 128; i++)
                acc = fmaf(As[i * 32 + b], W3c[i * 4 + jj], acc);
            A3s[t] = (acc + B3s[blk * 4 + jj]) * 0.1f;
        }
        __syncthreads();                        // A3 ready

        // ---- fused epilogue + permutation: one thread per batch row ----
        if (t < 32) {
            int b = t;
            const float* gsP = (blk ? gsb : gsa) + (size_t)p * 3;
            const float* goP = (blk ? gob : goa) + (size_t)p * 3;
            const int*   pmP = (blk ? pmb : pma) + (size_t)p * 3;
            float sc0, sc1, sc2, lg;
            {
                float y0 = 0.5f * __ldg(gsP);
                float y1 = 0.5f * __ldg(gsP + 1);
                float y2 = 0.5f * __ldg(gsP + 2);
                sc0 = 0.2f * ((y0 > 15.f) ? y0 : log1pf(expf(y0)));
                sc1 = 0.2f * ((y1 > 15.f) ? y1 : log1pf(expf(y1)));
                sc2 = 0.2f * ((y2 > 15.f) ? y2 : log1pf(expf(y2)));
                lg = logf(sc0) + logf(sc1) + logf(sc2);
            }
            float s0 = 2.f * tanhf(A3s[b * 4]);
            float s1 = 2.f * tanhf(A3s[b * 4 + 1]);
            float ov0 = Hs[b * 3];
            float ov1 = Hs[b * 3 + 1] * expf(s0) + A3s[b * 4 + 2];
            float ov2 = Hs[b * 3 + 2] * expf(s1) + A3s[b * 4 + 3];
            ov0 = ov0 * sc0 + __ldg(goP);
            ov1 = ov1 * sc1 + __ldg(goP + 1);
            ov2 = ov2 * sc2 + __ldg(goP + 2);
            ldj += s0 + s1 + lg;
            int k0 = __ldg(pmP), k1 = __ldg(pmP + 1), k2 = __ldg(pmP + 2);
            Hs[b * 3 + 0] = (k0 == 0) ? ov0 : ((k0 == 1) ? ov1 : ov2);
            Hs[b * 3 + 1] = (k1 == 0) ? ov0 : ((k1 == 1) ? ov1 : ov2);
            Hs[b * 3 + 2] = (k2 == 0) ? ov0 : ((k2 == 1) ? ov1 : ov2);
        }
        __syncthreads();                        // Hs visible for next block / store
    }

    if (t < 96) zout[(size_t)p * 96 + t] = Hs[t];
    if (t < 32) ldjout[(size_t)p * 32 + t] = ldj;
}

extern "C" void kernel_launch(void* const* d_in, const int* in_sizes, int n_in,
                              void* d_out, int out_size) {
    (void)n_in; (void)out_size;

    int ia[9], ib[9];
    if (in_sizes[10] == 12288) {
        const int A[9]  = {2, 3, 4, 5, 6, 7, 8, 9, 10};
        const int Bn[9] = {11, 12, 13, 14, 15, 16, 17, 18, 19};
        for (int i = 0; i < 9; i++) { ia[i] = A[i]; ib[i] = Bn[i]; }
    } else {
        const int A[9]  = {2, 3, 4, 5, 6, 7, 8, 9, 18};
        const int Bn[9] = {10, 11, 12, 13, 14, 15, 16, 17, 19};
        for (int i = 0; i < 9; i++) { ia[i] = A[i]; ib[i] = Bn[i]; }
    }

    cudaFuncSetAttribute(patchflow_kernel,
                         cudaFuncAttributeMaxDynamicSharedMemorySize, SMEM_BYTES);

    float* z = (float*)d_out;                 // [4096, 32, 3]
    float* ldj = z + (size_t)4096 * 32 * 3;   // [4096, 32]

    patchflow_kernel<<<4096, 256, SMEM_BYTES>>>(
        (const float*)d_in[0], (const float*)d_in[1],
        (const float*)d_in[ia[0]], (const float*)d_in[ia[1]],
        (const float*)d_in[ia[2]], (const float*)d_in[ia[3]],
        (const float*)d_in[ia[4]], (const float*)d_in[ia[5]],
        (const float*)d_in[ia[6]], (const float*)d_in[ia[7]],
        (const int*)d_in[ia[8]],
        (const float*)d_in[ib[0]], (const float*)d_in[ib[1]],
        (const float*)d_in[ib[2]], (const float*)d_in[ib[3]],
        (const float*)d_in[ib[4]], (const float*)d_in[ib[5]],
        (const float*)d_in[ib[6]], (const float*)d_in[ib[7]],
        (const int*)d_in[ib[8]],
        z, ldj);
}

// round 8
// speedup vs baseline: 2.2918x; 1.1832x over previous
#include <cuda_runtime.h>
#include <cstdint>

// ---- shared memory layout (floats) ----
#define OFF_P0   0        // 4096: W2^T panel ping  [o=128][i=32], XOR-swizzled
#define OFF_P1   4096     // 4096: W2^T panel pong
#define OFF_A    8192     // 4096: A1 then A2 in place [b=32][col=128], XOR-swizzled
#define OFF_B2   12288    // 256  [0:128]=a [128:256]=b
#define OFF_W3   12544    // 1024 [0:512]=a [512:1024]=b
#define OFF_B3   13568    // 8
#define OFF_CS   13576    // 256
#define OFF_A3   13832    // 128
#define OFF_H    13960    // 96
#define SMEM_FLOATS 14056
#define SMEM_BYTES (SMEM_FLOATS * 4)

#define SWZ(r) (((r) & 7) << 2)

// exact GELU via A&S 7.1.26 erfc (|abs err| <= ~1.5e-7)
__device__ __forceinline__ float gelu_fast(float v) {
    float z = fabsf(v) * 0.7071067811865475f;
    float t;
    asm("rcp.approx.f32 %0, %1;" : "=f"(t) : "f"(fmaf(0.3275911f, z, 1.0f)));
    float e;
    asm("ex2.approx.f32 %0, %1;" : "=f"(e) : "f"(z * z * -1.4426950408889634f));
    float poly = fmaf(t, 1.061405429f, -1.453152027f);
    poly = fmaf(t, poly, 1.421413741f);
    poly = fmaf(t, poly, -0.284496736f);
    poly = fmaf(t, poly, 0.254829592f);
    float erfc_half = 0.5f * (poly * t) * e;
    float phi = 0.5f + copysignf(0.5f - erfc_half, v);
    return v * phi;
}

__device__ __forceinline__ float to_tf32(float x) {
    float r;
    asm("cvt.rna.tf32.f32 %0, %1;" : "=f"(r) : "f"(x));
    return r;
}

__device__ __forceinline__ void mma_tf32(float* c,
                                         uint32_t a0, uint32_t a1, uint32_t a2, uint32_t a3,
                                         uint32_t b0, uint32_t b1) {
    asm volatile(
        "mma.sync.aligned.m16n8k8.row.col.f32.tf32.tf32.f32 "
        "{%0,%1,%2,%3}, {%4,%5,%6,%7}, {%8,%9}, {%0,%1,%2,%3};"
        : "+f"(c[0]), "+f"(c[1]), "+f"(c[2]), "+f"(c[3])
        : "r"(a0), "r"(a1), "r"(a2), "r"(a3), "r"(b0), "r"(b1));
}

// stage one W2^T panel (i-chunk c): gmem [i][o] -> regs (coalesced over o)
__device__ __forceinline__ void ldg_panel(const float* w2P, int c, int w, int l, float4* q) {
    int o = ((w & 3) << 5) + l;
    int ib = (w >> 2) << 4;                 // 0 or 16
    #pragma unroll
    for (int qq = 0; qq < 4; qq++) {
        const float* src = w2P + (size_t)(c * 32 + ib + 4 * qq) * 128 + o;
        q[qq].x = __ldg(src);
        q[qq].y = __ldg(src + 128);
        q[qq].z = __ldg(src + 256);
        q[qq].w = __ldg(src + 384);
    }
}
// regs -> swizzled smem panel [o][i], tf32-rounded
__device__ __forceinline__ void sts_panel(float* buf, int w, int l, const float4* q) {
    int o = ((w & 3) << 5) + l;
    int ib = (w >> 2) << 4;
    #pragma unroll
    for (int qq = 0; qq < 4; qq++) {
        float4 v;
        v.x = to_tf32(q[qq].x); v.y = to_tf32(q[qq].y);
        v.z = to_tf32(q[qq].z); v.w = to_tf32(q[qq].w);
        *(float4*)(buf + o * 32 + ((ib + 4 * qq) ^ SWZ(o))) = v;
    }
}

__global__ void __launch_bounds__(256, 4)
patchflow_kernel(const float* __restrict__ x, const float* __restrict__ pos,
                 const float* __restrict__ w1a, const float* __restrict__ b1a,
                 const float* __restrict__ w2a, const float* __restrict__ b2a,
                 const float* __restrict__ w3a, const float* __restrict__ b3a,
                 const float* __restrict__ gsa, const float* __restrict__ goa,
                 const int* __restrict__ pma,
                 const float* __restrict__ w1b, const float* __restrict__ b1b,
                 const float* __restrict__ w2b, const float* __restrict__ b2b,
                 const float* __restrict__ w3b, const float* __restrict__ b3b,
                 const float* __restrict__ gsb, const float* __restrict__ gob,
                 const int* __restrict__ pmb,
                 float* __restrict__ zout, float* __restrict__ ldjout)
{
    extern __shared__ float sm[];
    const int p = blockIdx.x;
    const int t = threadIdx.x;
    const int w = t >> 5, l = t & 31;

    float* P0  = sm + OFF_P0;
    float* P1  = sm + OFF_P1;
    float* As  = sm + OFF_A;
    float* B2s = sm + OFF_B2;
    float* W3s = sm + OFF_W3;
    float* B3s = sm + OFF_B3;
    float* CSs = sm + OFF_CS;
    float* A3s = sm + OFF_A3;
    float* Hs  = sm + OFF_H;

    // ---- small weights into smem (plain LDG) ----
    if (t < 128) {
        B2s[t]       = __ldg(b2a + (size_t)p * 128 + t);
        B2s[128 + t] = __ldg(b2b + (size_t)p * 128 + t);
        *(float4*)(W3s + 4 * t) = __ldg((const float4*)(w3a + (size_t)p * 512) + t);
    } else {
        *(float4*)(W3s + 512 + 4 * (t - 128)) =
            __ldg((const float4*)(w3b + (size_t)p * 512) + (t - 128));
    }
    if (t == 32) {
        *(float4*)(B3s)     = __ldg((const float4*)(b3a + (size_t)p * 4));
        *(float4*)(B3s + 4) = __ldg((const float4*)(b3b + (size_t)p * 4));
    }

    // ---- 3x3 stride-2 avg pool ----
    if (t < 96) {
        int b = t / 3, c = t % 3;
        int ph = p >> 6, pw = p & 63;
        const float* xp = x + (size_t)(b * 3 + c) * 16384;
        int y0 = 2 * ph - 1, x0 = 2 * pw - 1;
        float acc = 0.f;
        #pragma unroll
        for (int dy = 0; dy < 3; dy++) {
            int yy = y0 + dy;
            if (yy < 0) continue;
            #pragma unroll
            for (int dx = 0; dx < 3; dx++) {
                int xx = x0 + dx;
                if (xx < 0) continue;
                acc += __ldg(xp + yy * 128 + xx);
            }
        }
        Hs[t] = acc * (1.f / 9.f);
    }

    // ---- cond-sums for BOTH blocks (coalesced in o) ----
    {
        int o = t & 127;
        const float* w1P = ((t < 128) ? w1a : w1b) + (size_t)p * 2176;
        const float* b1P = ((t < 128) ? b1a : b1b) + (size_t)p * 128;
        const float* posP = pos + (size_t)p * 16;
        float cs = __ldg(b1P + o);
        #pragma unroll
        for (int k = 0; k < 16; k++)
            cs = fmaf(__ldg(posP + k), __ldg(w1P + (1 + k) * 128 + o), cs);
        CSs[t] = cs;
    }

    // prologue staging of block-a panel 0 (LDG before the sync for overlap)
    float4 st[4];
    const float* w2aP = w2a + (size_t)p * 16384;
    const float* w2bP = w2b + (size_t)p * 16384;
    ldg_panel(w2aP, 0, w, l, st);

    __syncthreads();    // Hs, CSs, small weights visible

    // ---- layer 1 (block a) -> A1 [b][i] swizzled, tf32-rounded ----
    {
        const float* w1r0 = w1a + (size_t)p * 2176;
        float4 w1v = __ldg((const float4*)(w1r0) + l);
        float4 csv = *(const float4*)(CSs + 4 * l);
        #pragma unroll
        for (int r = 0; r < 4; r++) {
            int b = w + 8 * r;
            float h = Hs[b * 3];
            float4 v;
            v.x = to_tf32(gelu_fast(fmaf(h, w1v.x, csv.x)));
            v.y = to_tf32(gelu_fast(fmaf(h, w1v.y, csv.y)));
            v.z = to_tf32(gelu_fast(fmaf(h, w1v.z, csv.z)));
            v.w = to_tf32(gelu_fast(fmaf(h, w1v.w, csv.w)));
            *(float4*)(As + b * 128 + ((4 * l) ^ SWZ(b))) = v;
        }
    }
    sts_panel(P0, w, l, st);

    // mma thread geometry
    const int gid = l >> 2, tig = l & 3;
    const int bh = w & 1;                  // m-half
    const int obase = (w >> 1) << 5;       // n-base (32 outputs per warp)
    const int r0 = bh * 16 + gid, r1 = r0 + 8;
    const int swz0 = SWZ(r0), swz1 = SWZ(r1);

    float ldj = 0.f;   // valid for t<32

    for (int blk = 0; blk < 2; blk++) {
        const float* w2P = blk ? w2bP : w2aP;

        float acc[4][4];
        #pragma unroll
        for (int nt = 0; nt < 4; nt++)
            #pragma unroll
            for (int k = 0; k < 4; k++) acc[nt][k] = 0.f;

        // ---- GEMM2: 4 panels, ping-pong, 1 sync per panel ----
        #pragma unroll
        for (int c = 0; c < 4; c++) {
            __syncthreads();               // panel c (+ A1 on c==0) visible
            if (c < 3) ldg_panel(w2P, c + 1, w, l, st);

            const float* Pc = (c & 1) ? P1 : P0;
            #pragma unroll
            for (int ks = 0; ks < 4; ks++) {
                int col = c * 32 + ks * 8 + tig;
                uint32_t a0 = __float_as_uint(As[r0 * 128 + (col ^ swz0)]);
                uint32_t a1 = __float_as_uint(As[r1 * 128 + (col ^ swz1)]);
                uint32_t a2 = __float_as_uint(As[r0 * 128 + ((col + 4) ^ swz0)]);
                uint32_t a3 = __float_as_uint(As[r1 * 128 + ((col + 4) ^ swz1)]);
                int kl = ks * 8 + tig;
                #pragma unroll
                for (int nt = 0; nt < 4; nt++) {
                    int oo = obase + nt * 8 + gid;
                    uint32_t b0 = __float_as_uint(Pc[oo * 32 + (kl ^ SWZ(oo))]);
                    uint32_t b1 = __float_as_uint(Pc[oo * 32 + ((kl + 4) ^ SWZ(oo))]);
                    mma_tf32(acc[nt], a0, a1, a2, a3, b0, b1);
                }
            }
            if (c < 3) sts_panel((c & 1) ? P0 : P1, w, l, st);  // buf (c+1)&1
        }
        __syncthreads();                   // all warps done reading A1/panels

        if (blk == 0) ldg_panel(w2bP, 0, w, l, st);   // next block panel 0

        // ---- epilogue: bias + gelu -> A2 in place of A1 ----
        {
            const float* B2 = B2s + blk * 128;
            #pragma unroll
            for (int nt = 0; nt < 4; nt++) {
                int col = obase + nt * 8 + 2 * tig;
                float b2l = B2[col], b2h = B2[col + 1];
                float2 v0, v1;
                v0.x = gelu_fast(acc[nt][0] + b2l);
                v0.y = gelu_fast(acc[nt][1] + b2h);
                v1.x = gelu_fast(acc[nt][2] + b2l);
                v1.y = gelu_fast(acc[nt][3] + b2h);
                *(float2*)(As + r0 * 128 + (col ^ swz0)) = v0;
                *(float2*)(As + r1 * 128 + (col ^ swz1)) = v1;
            }
        }
        __syncthreads();                   // A2 visible

        if (blk == 0) sts_panel(P0, w, l, st);        // P0 free (last read at c==2)

        // ---- layer 3: 128 threads, full K, swizzled float4 reads ----
        if (t < 128) {
            int jj = t & 3, b = t >> 2;
            int sw = SWZ(b);
            const float* W3c = W3s + blk * 512;
            const float* Ar = As + b * 128;
            float a4 = 0.f;
            #pragma unroll 8
            for (int m = 0; m < 32; m++) {
                float4 av = *(const float4*)(Ar + ((4 * m) ^ sw));
                int i = 4 * m;
                a4 = fmaf(av.x, W3c[i * 4 + jj], a4);
                a4 = fmaf(av.y, W3c[(i + 1) * 4 + jj], a4);
                a4 = fmaf(av.z, W3c[(i + 2) * 4 + jj], a4);
                a4 = fmaf(av.w, W3c[(i + 3) * 4 + jj], a4);
            }
            A3s[t] = (a4 + B3s[blk * 4 + jj]) * 0.1f;
        }
        __syncthreads();                   // A3 ready

        // ---- fused epilogue + permutation: one thread per batch row ----
        if (t < 32) {
            int b = t;
            const float* gsP = (blk ? gsb : gsa) + (size_t)p * 3;
            const float* goP = (blk ? gob : goa) + (size_t)p * 3;
            const int*   pmP = (blk ? pmb : pma) + (size_t)p * 3;
            float sc0, sc1, sc2, lg;
            {
                float y0 = 0.5f * __ldg(gsP);
                float y1 = 0.5f * __ldg(gsP + 1);
                float y2 = 0.5f * __ldg(gsP + 2);
                sc0 = 0.2f * ((y0 > 15.f) ? y0 : log1pf(expf(y0)));
                sc1 = 0.2f * ((y1 > 15.f) ? y1 : log1pf(expf(y1)));
                sc2 = 0.2f * ((y2 > 15.f) ? y2 : log1pf(expf(y2)));
                lg = logf(sc0) + logf(sc1) + logf(sc2);
            }
            float s0 = 2.f * tanhf(A3s[b * 4]);
            float s1 = 2.f * tanhf(A3s[b * 4 + 1]);
            float ov0 = Hs[b * 3];
            float ov1 = Hs[b * 3 + 1] * expf(s0) + A3s[b * 4 + 2];
            float ov2 = Hs[b * 3 + 2] * expf(s1) + A3s[b * 4 + 3];
            ov0 = ov0 * sc0 + __ldg(goP);
            ov1 = ov1 * sc1 + __ldg(goP + 1);
            ov2 = ov2 * sc2 + __ldg(goP + 2);
            ldj += s0 + s1 + lg;
            int k0 = __ldg(pmP), k1 = __ldg(pmP + 1), k2 = __ldg(pmP + 2);
            Hs[b * 3 + 0] = (k0 == 0) ? ov0 : ((k0 == 1) ? ov1 : ov2);
            Hs[b * 3 + 1] = (k1 == 0) ? ov0 : ((k1 == 1) ? ov1 : ov2);
            Hs[b * 3 + 2] = (k2 == 0) ? ov0 : ((k2 == 1) ? ov1 : ov2);
        }
        __syncthreads();                   // Hs visible; A2 reads (layer3) done

        // ---- layer 1 for block b (A1 overwrites A2) ----
        if (blk == 0) {
            const float* w1r0 = w1b + (size_t)p * 2176;
            float4 w1v = __ldg((const float4*)(w1r0) + l);
            float4 csv = *(const float4*)(CSs + 128 + 4 * l);
            #pragma unroll
            for (int r = 0; r < 4; r++) {
                int b = w + 8 * r;
                float h = Hs[b * 3];
                float4 v;
                v.x = to_tf32(gelu_fast(fmaf(h, w1v.x, csv.x)));
                v.y = to_tf32(gelu_fast(fmaf(h, w1v.y, csv.y)));
                v.z = to_tf32(gelu_fast(fmaf(h, w1v.z, csv.z)));
                v.w = to_tf32(gelu_fast(fmaf(h, w1v.w, csv.w)));
                *(float4*)(As + b * 128 + ((4 * l) ^ SWZ(b))) = v;
            }
            // next loop iteration's first __syncthreads publishes A1 + P0
        }
    }

    if (t < 96) zout[(size_t)p * 96 + t] = Hs[t];
    if (t < 32) ldjout[(size_t)p * 32 + t] = ldj;
}

extern "C" void kernel_launch(void* const* d_in, const int* in_sizes, int n_in,
                              void* d_out, int out_size) {
    (void)n_in; (void)out_size;

    int ia[9], ib[9];
    if (in_sizes[10] == 12288) {
        const int A[9]  = {2, 3, 4, 5, 6, 7, 8, 9, 10};
        const int Bn[9] = {11, 12, 13, 14, 15, 16, 17, 18, 19};
        for (int i = 0; i < 9; i++) { ia[i] = A[i]; ib[i] = Bn[i]; }
    } else {
        const int A[9]  = {2, 3, 4, 5, 6, 7, 8, 9, 18};
        const int Bn[9] = {10, 11, 12, 13, 14, 15, 16, 17, 19};
        for (int i = 0; i < 9; i++) { ia[i] = A[i]; ib[i] = Bn[i]; }
    }

    cudaFuncSetAttribute(patchflow_kernel,
                         cudaFuncAttributeMaxDynamicSharedMemorySize, SMEM_BYTES);

    float* z = (float*)d_out;                 // [4096, 32, 3]
    float* ldj = z + (size_t)4096 * 32 * 3;   // [4096, 32]

    patchflow_kernel<<<4096, 256, SMEM_BYTES>>>(
        (const float*)d_in[0], (const float*)d_in[1],
        (const float*)d_in[ia[0]], (const float*)d_in[ia[1]],
        (const float*)d_in[ia[2]], (const float*)d_in[ia[3]],
        (const float*)d_in[ia[4]], (const float*)d_in[ia[5]],
        (const float*)d_in[ia[6]], (const float*)d_in[ia[7]],
        (const int*)d_in[ia[8]],
        (const float*)d_in[ib[0]], (const float*)d_in[ib[1]],
        (const float*)d_in[ib[2]], (const float*)d_in[ib[3]],
        (const float*)d_in[ib[4]], (const float*)d_in[ib[5]],
        (const float*)d_in[ib[6]], (const float*)d_in[ib[7]],
        (const int*)d_in[ib[8]],
        z, ldj);
}

// round 9
// speedup vs baseline: 2.4072x; 1.0503x over previous
#include <cuda_runtime.h>
#include <cstdint>

// ---- shared memory layout (floats) ----
#define OFF_P0   0        // 4096: W2^T panel ping  [o=128][i=32], XOR-swizzled
#define OFF_P1   4096     // 4096: W2^T panel pong
#define OFF_A    8192     // 4096: A1 then A2 in place [b=32][col=128], XOR-swizzled
#define OFF_B2   12288    // 256  [0:128]=a [128:256]=b
#define OFF_W3   12544    // 1024 [0:512]=a [512:1024]=b
#define OFF_B3   13568    // 8
#define OFF_CS   13576    // 256
#define OFF_A3   13832    // 128
#define OFF_H    13960    // 96
#define OFF_MB   14056    // 6 mbarriers x 8B (8B-aligned: 14056*4 % 8 == 0)
#define SMEM_FLOATS 14068
#define SMEM_BYTES (SMEM_FLOATS * 4)

#define SWZ(r) (((r) & 7) << 2)

// mbarrier ids (byte offsets from mb base): 0=FULL0 1=FULL1 2=FREE0 3=FREE1 4=H1RDY 5=A1RDY
#define MB(i) (mb + 8u * (i))

// exact GELU via A&S 7.1.26 erfc (|abs err| <= ~1.5e-7)
__device__ __forceinline__ float gelu_fast(float v) {
    float z = fabsf(v) * 0.7071067811865475f;
    float t;
    asm("rcp.approx.f32 %0, %1;" : "=f"(t) : "f"(fmaf(0.3275911f, z, 1.0f)));
    float e;
    asm("ex2.approx.f32 %0, %1;" : "=f"(e) : "f"(z * z * -1.4426950408889634f));
    float poly = fmaf(t, 1.061405429f, -1.453152027f);
    poly = fmaf(t, poly, 1.421413741f);
    poly = fmaf(t, poly, -0.284496736f);
    poly = fmaf(t, poly, 0.254829592f);
    float erfc_half = 0.5f * (poly * t) * e;
    float phi = 0.5f + copysignf(0.5f - erfc_half, v);
    return v * phi;
}

__device__ __forceinline__ float to_tf32(float x) {
    float r;
    asm("cvt.rna.tf32.f32 %0, %1;" : "=f"(r) : "f"(x));
    return r;
}

__device__ __forceinline__ void mma_tf32(float* c,
                                         uint32_t a0, uint32_t a1, uint32_t a2, uint32_t a3,
                                         uint32_t b0, uint32_t b1) {
    asm volatile(
        "mma.sync.aligned.m16n8k8.row.col.f32.tf32.tf32.f32 "
        "{%0,%1,%2,%3}, {%4,%5,%6,%7}, {%8,%9}, {%0,%1,%2,%3};"
        : "+f"(c[0]), "+f"(c[1]), "+f"(c[2]), "+f"(c[3])
        : "r"(a0), "r"(a1), "r"(a2), "r"(a3), "r"(b0), "r"(b1));
}

__device__ __forceinline__ void mbar_init(uint32_t a, uint32_t cnt) {
    asm volatile("mbarrier.init.shared.b64 [%0], %1;" :: "r"(a), "r"(cnt) : "memory");
}
__device__ __forceinline__ void mbar_arrive(uint32_t a) {
    asm volatile("mbarrier.arrive.shared.b64 _, [%0];" :: "r"(a) : "memory");
}
__device__ __forceinline__ void mbar_wait(uint32_t a, uint32_t par) {
    asm volatile(
        "{\n\t"
        ".reg .pred P1;\n"
        "WL%=:\n\t"
        "mbarrier.try_wait.parity.acquire.cta.shared::cta.b64 P1, [%0], %1, 0x989680;\n\t"
        "@P1 bra WD%=;\n\t"
        "bra.uni WL%=;\n"
        "WD%=:\n\t"
        "}"
        :: "r"(a), "r"(par) : "memory");
}
#define CBAR() asm volatile("bar.sync 5, 128;" ::: "memory")

__global__ void __launch_bounds__(256, 4)
patchflow_kernel(const float* __restrict__ x, const float* __restrict__ pos,
                 const float* __restrict__ w1a, const float* __restrict__ b1a,
                 const float* __restrict__ w2a, const float* __restrict__ b2a,
                 const float* __restrict__ w3a, const float* __restrict__ b3a,
                 const float* __restrict__ gsa, const float* __restrict__ goa,
                 const int* __restrict__ pma,
                 const float* __restrict__ w1b, const float* __restrict__ b1b,
                 const float* __restrict__ w2b, const float* __restrict__ b2b,
                 const float* __restrict__ w3b, const float* __restrict__ b3b,
                 const float* __restrict__ gsb, const float* __restrict__ gob,
                 const int* __restrict__ pmb,
                 float* __restrict__ zout, float* __restrict__ ldjout)
{
    extern __shared__ float sm[];
    const int p = blockIdx.x;
    const int t = threadIdx.x;
    const int w = t >> 5, l = t & 31;

    float* As  = sm + OFF_A;
    float* B2s = sm + OFF_B2;
    float* W3s = sm + OFF_W3;
    float* B3s = sm + OFF_B3;
    float* CSs = sm + OFF_CS;
    float* A3s = sm + OFF_A3;
    float* Hs  = sm + OFF_H;
    const uint32_t mb = (uint32_t)__cvta_generic_to_shared(sm + OFF_MB);

    const float* w2aP = w2a + (size_t)p * 16384;
    const float* w2bP = w2b + (size_t)p * 16384;

    if (t == 0) {
        #pragma unroll
        for (int i = 0; i < 6; i++) mbar_init(MB(i), 128);
    }

    // ---- small weights into smem ----
    if (t < 128) {
        B2s[t]       = __ldg(b2a + (size_t)p * 128 + t);
        B2s[128 + t] = __ldg(b2b + (size_t)p * 128 + t);
        *(float4*)(W3s + 4 * t) = __ldg((const float4*)(w3a + (size_t)p * 512) + t);
    } else {
        *(float4*)(W3s + 512 + 4 * (t - 128)) =
            __ldg((const float4*)(w3b + (size_t)p * 512) + (t - 128));
    }
    if (t == 32) {
        *(float4*)(B3s)     = __ldg((const float4*)(b3a + (size_t)p * 4));
        *(float4*)(B3s + 4) = __ldg((const float4*)(b3b + (size_t)p * 4));
    }

    // ---- 3x3 stride-2 avg pool ----
    if (t < 96) {
        int b = t / 3, c = t % 3;
        int ph = p >> 6, pw = p & 63;
        const float* xp = x + (size_t)(b * 3 + c) * 16384;
        int y0 = 2 * ph - 1, x0 = 2 * pw - 1;
        float acc = 0.f;
        #pragma unroll
        for (int dy = 0; dy < 3; dy++) {
            int yy = y0 + dy;
            if (yy < 0) continue;
            #pragma unroll
            for (int dx = 0; dx < 3; dx++) {
                int xx = x0 + dx;
                if (xx < 0) continue;
                acc += __ldg(xp + yy * 128 + xx);
            }
        }
        Hs[t] = acc * (1.f / 9.f);
    }

    // ---- cond-sums for BOTH blocks (coalesced in o) ----
    {
        int o = t & 127;
        const float* w1P = ((t < 128) ? w1a : w1b) + (size_t)p * 2176;
        const float* b1P = ((t < 128) ? b1a : b1b) + (size_t)p * 128;
        const float* posP = pos + (size_t)p * 16;
        float cs = __ldg(b1P + o);
        #pragma unroll
        for (int k = 0; k < 16; k++)
            cs = fmaf(__ldg(posP + k), __ldg(w1P + (1 + k) * 128 + o), cs);
        CSs[t] = cs;
    }
    __syncthreads();   // Hs, CSs, small weights, mbarriers visible

    // ---- layer 1 (block a), all 256 threads ----
    {
        const float* w1r0 = w1a + (size_t)p * 2176;
        float4 w1v = __ldg((const float4*)(w1r0) + l);
        float4 csv = *(const float4*)(CSs + 4 * l);
        #pragma unroll
        for (int r = 0; r < 4; r++) {
            int b = w + 8 * r;
            float h = Hs[b * 3];
            float4 v;
            v.x = to_tf32(gelu_fast(fmaf(h, w1v.x, csv.x)));
            v.y = to_tf32(gelu_fast(fmaf(h, w1v.y, csv.y)));
            v.z = to_tf32(gelu_fast(fmaf(h, w1v.z, csv.z)));
            v.w = to_tf32(gelu_fast(fmaf(h, w1v.w, csv.w)));
            *(float4*)(As + b * 128 + ((4 * l) ^ SWZ(b))) = v;
        }
    }
    __syncthreads();   // A1(blk a) visible; ROLES DIVERGE BELOW (no __syncthreads after!)

    if (t >= 128) {
        // ================= PRODUCER (warps 4-7) =================
        const int u = t - 128;
        const int o = u;                     // 0..127, warp-coalesced in lanes

        #define FILL(G) {                                                              \
            const int bb = (G) & 1;                                                    \
            if ((G) >= 2) mbar_wait(MB(2 + bb), (uint32_t)((((G) - 2) >> 1) & 1));     \
            const float* w2P = ((G) < 4) ? w2aP : w2bP;                                \
            const float* src = w2P + (size_t)(((G) & 3) * 32) * 128 + o;               \
            float4 q[8];                                                               \
            _Pragma("unroll")                                                          \
            for (int k = 0; k < 8; k++) {                                              \
                q[k].x = __ldg(src + (4 * k + 0) * 128);                               \
                q[k].y = __ldg(src + (4 * k + 1) * 128);                               \
                q[k].z = __ldg(src + (4 * k + 2) * 128);                               \
                q[k].w = __ldg(src + (4 * k + 3) * 128);                               \
            }                                                                          \
            float* buf = sm + (bb ? OFF_P1 : OFF_P0) + o * 32;                         \
            _Pragma("unroll")                                                          \
            for (int k = 0; k < 8; k++) {                                              \
                float4 v;                                                              \
                v.x = to_tf32(q[k].x); v.y = to_tf32(q[k].y);                          \
                v.z = to_tf32(q[k].z); v.w = to_tf32(q[k].w);                          \
                *(float4*)(buf + ((4 * k) ^ SWZ(o))) = v;                              \
            }                                                                          \
            mbar_arrive(MB(bb));                                                       \
        }

        FILL(0) FILL(1) FILL(2) FILL(3) FILL(4) FILL(5)

        // layer 1 for block b (As is free: consumers signaled H1RDY after layer3)
        mbar_wait(MB(4), 0u);
        {
            const float* w1r0 = w1b + (size_t)p * 2176;
            int li = u & 31, bw = u >> 5;
            float4 w1v = __ldg((const float4*)(w1r0) + li);
            float4 csv = *(const float4*)(CSs + 128 + 4 * li);
            #pragma unroll
            for (int r = 0; r < 8; r++) {
                int b = bw + 4 * r;
                float h = Hs[b * 3];
                float4 v;
                v.x = to_tf32(gelu_fast(fmaf(h, w1v.x, csv.x)));
                v.y = to_tf32(gelu_fast(fmaf(h, w1v.y, csv.y)));
                v.z = to_tf32(gelu_fast(fmaf(h, w1v.z, csv.z)));
                v.w = to_tf32(gelu_fast(fmaf(h, w1v.w, csv.w)));
                *(float4*)(As + b * 128 + ((4 * li) ^ SWZ(b))) = v;
            }
        }
        mbar_arrive(MB(5));                  // A1(blk b) ready

        FILL(6) FILL(7)
        #undef FILL
        // producers done; fall through to kernel exit
    } else {
        // ================= CONSUMER (warps 0-3) =================
        const int gid = l >> 2, tig = l & 3;
        const int obase = w << 5;            // 32 outputs per warp
        float ldj = 0.f;                     // valid for t<32

        for (int blk = 0; blk < 2; blk++) {
            if (blk == 1) mbar_wait(MB(5), 0u);     // A1(blk b) ready

            float acc[2][4][4];
            #pragma unroll
            for (int mh = 0; mh < 2; mh++)
                #pragma unroll
                for (int nt = 0; nt < 4; nt++)
                    #pragma unroll
                    for (int k = 0; k < 4; k++) acc[mh][nt][k] = 0.f;

            #pragma unroll
            for (int c = 0; c < 4; c++) {
                int g = blk * 4 + c, bb = g & 1;
                mbar_wait(MB(bb), (uint32_t)((g >> 1) & 1));   // panel full
                const float* Pc = sm + (bb ? OFF_P1 : OFF_P0);
                #pragma unroll
                for (int ks = 0; ks < 4; ks++) {
                    int col = c * 32 + ks * 8 + tig;
                    int kl = ks * 8 + tig;
                    uint32_t a[2][4];
                    #pragma unroll
                    for (int mh = 0; mh < 2; mh++) {
                        int r0 = mh * 16 + gid, r1 = r0 + 8;
                        a[mh][0] = __float_as_uint(As[r0 * 128 + (col ^ SWZ(r0))]);
                        a[mh][1] = __float_as_uint(As[r1 * 128 + (col ^ SWZ(r1))]);
                        a[mh][2] = __float_as_uint(As[r0 * 128 + ((col + 4) ^ SWZ(r0))]);
                        a[mh][3] = __float_as_uint(As[r1 * 128 + ((col + 4) ^ SWZ(r1))]);
                    }
                    #pragma unroll
                    for (int nt = 0; nt < 4; nt++) {
                        int oo = obase + nt * 8 + gid;
                        uint32_t b0 = __float_as_uint(Pc[oo * 32 + (kl ^ SWZ(oo))]);
                        uint32_t b1 = __float_as_uint(Pc[oo * 32 + ((kl + 4) ^ SWZ(oo))]);
                        mma_tf32(acc[0][nt], a[0][0], a[0][1], a[0][2], a[0][3], b0, b1);
                        mma_tf32(acc[1][nt], a[1][0], a[1][1], a[1][2], a[1][3], b0, b1);
                    }
                }
                mbar_arrive(MB(2 + bb));     // panel free
            }
            CBAR();                          // all consumers done reading A1

            // ---- A2 = gelu(acc + b2), in place of A1 ----
            {
                const float* B2 = B2s + blk * 128;
                #pragma unroll
                for (int mh = 0; mh < 2; mh++) {
                    int r0 = mh * 16 + gid, r1 = r0 + 8;
                    #pragma unroll
                    for (int nt = 0; nt < 4; nt++) {
                        int colo = obase + nt * 8 + 2 * tig;
                        float b2l = B2[colo], b2h = B2[colo + 1];
                        float2 v0, v1;
                        v0.x = gelu_fast(acc[mh][nt][0] + b2l);
                        v0.y = gelu_fast(acc[mh][nt][1] + b2h);
                        v1.x = gelu_fast(acc[mh][nt][2] + b2l);
                        v1.y = gelu_fast(acc[mh][nt][3] + b2h);
                        *(float2*)(As + r0 * 128 + (colo ^ SWZ(r0))) = v0;
                        *(float2*)(As + r1 * 128 + (colo ^ SWZ(r1))) = v1;
                    }
                }
            }
            CBAR();                          // A2 visible

            // ---- layer 3: all 128 consumers, full K ----
            {
                int jj = t & 3, b = t >> 2;
                int sw = SWZ(b);
                const float* W3c = W3s + blk * 512;
                const float* Ar = As + b * 128;
                float a4 = 0.f;
                #pragma unroll 8
                for (int m = 0; m < 32; m++) {
                    float4 av = *(const float4*)(Ar + ((4 * m) ^ sw));
                    int i = 4 * m;
                    a4 = fmaf(av.x, W3c[i * 4 + jj], a4);
                    a4 = fmaf(av.y, W3c[(i + 1) * 4 + jj], a4);
                    a4 = fmaf(av.z, W3c[(i + 2) * 4 + jj], a4);
                    a4 = fmaf(av.w, W3c[(i + 3) * 4 + jj], a4);
                }
                A3s[t] = (a4 + B3s[blk * 4 + jj]) * 0.1f;
            }
            CBAR();                          // A3 ready; As reads done

            // ---- coupling epilogue + permutation: one thread per batch row ----
            if (t < 32) {
                int b = t;
                const float* gsP = (blk ? gsb : gsa) + (size_t)p * 3;
                const float* goP = (blk ? gob : goa) + (size_t)p * 3;
                const int*   pmP = (blk ? pmb : pma) + (size_t)p * 3;
                float sc0, sc1, sc2, lg;
                {
                    float y0 = 0.5f * __ldg(gsP);
                    float y1 = 0.5f * __ldg(gsP + 1);
                    float y2 = 0.5f * __ldg(gsP + 2);
                    sc0 = 0.2f * ((y0 > 15.f) ? y0 : log1pf(expf(y0)));
                    sc1 = 0.2f * ((y1 > 15.f) ? y1 : log1pf(expf(y1)));
                    sc2 = 0.2f * ((y2 > 15.f) ? y2 : log1pf(expf(y2)));
                    lg = logf(sc0) + logf(sc1) + logf(sc2);
                }
                float s0 = 2.f * tanhf(A3s[b * 4]);
                float s1 = 2.f * tanhf(A3s[b * 4 + 1]);
                float ov0 = Hs[b * 3];
                float ov1 = Hs[b * 3 + 1] * expf(s0) + A3s[b * 4 + 2];
                float ov2 = Hs[b * 3 + 2] * expf(s1) + A3s[b * 4 + 3];
                ov0 = ov0 * sc0 + __ldg(goP);
                ov1 = ov1 * sc1 + __ldg(goP + 1);
                ov2 = ov2 * sc2 + __ldg(goP + 2);
                ldj += s0 + s1 + lg;
                int k0 = __ldg(pmP), k1 = __ldg(pmP + 1), k2 = __ldg(pmP + 2);
                Hs[b * 3 + 0] = (k0 == 0) ? ov0 : ((k0 == 1) ? ov1 : ov2);
                Hs[b * 3 + 1] = (k1 == 0) ? ov0 : ((k1 == 1) ? ov1 : ov2);
                Hs[b * 3 + 2] = (k2 == 0) ? ov0 : ((k2 == 1) ? ov1 : ov2);
            }
            CBAR();                          // Hs visible among consumers
            if (blk == 0) mbar_arrive(MB(4));   // H ready -> producers do layer1(blk b)
        }

        if (t < 96) zout[(size_t)p * 96 + t] = Hs[t];
        if (t < 32) ldjout[(size_t)p * 32 + t] = ldj;
    }
}

extern "C" void kernel_launch(void* const* d_in, const int* in_sizes, int n_in,
                              void* d_out, int out_size) {
    (void)n_in; (void)out_size;

    int ia[9], ib[9];
    if (in_sizes[10] == 12288) {
        const int A[9]  = {2, 3, 4, 5, 6, 7, 8, 9, 10};
        const int Bn[9] = {11, 12, 13, 14, 15, 16, 17, 18, 19};
        for (int i = 0; i < 9; i++) { ia[i] = A[i]; ib[i] = Bn[i]; }
    } else {
        const int A[9]  = {2, 3, 4, 5, 6, 7, 8, 9, 18};
        const int Bn[9] = {10, 11, 12, 13, 14, 15, 16, 17, 19};
        for (int i = 0; i < 9; i++) { ia[i] = A[i]; ib[i] = Bn[i]; }
    }

    cudaFuncSetAttribute(patchflow_kernel,
                         cudaFuncAttributeMaxDynamicSharedMemorySize, SMEM_BYTES);

    float* z = (float*)d_out;                 // [4096, 32, 3]
    float* ldj = z + (size_t)4096 * 32 * 3;   // [4096, 32]

    patchflow_kernel<<<4096, 256, SMEM_BYTES>>>(
        (const float*)d_in[0], (const float*)d_in[1],
        (const float*)d_in[ia[0]], (const float*)d_in[ia[1]],
        (const float*)d_in[ia[2]], (const float*)d_in[ia[3]],
        (const float*)d_in[ia[4]], (const float*)d_in[ia[5]],
        (const float*)d_in[ia[6]], (const float*)d_in[ia[7]],
        (const int*)d_in[ia[8]],
        (const float*)d_in[ib[0]], (const float*)d_in[ib[1]],
        (const float*)d_in[ib[2]], (const float*)d_in[ib[3]],
        (const float*)d_in[ib[4]], (const float*)d_in[ib[5]],
        (const float*)d_in[ib[6]], (const float*)d_in[ib[7]],
        (const int*)d_in[ib[8]],
        z, ldj);
}

// round 10
// speedup vs baseline: 2.5117x; 1.0434x over previous
#include <cuda_runtime.h>
#include <cstdint>

// ---- shared memory layout (floats) ----
#define OFF_P0   0        // 4096: W2 panel ping  [i=32][o=128] k-major, XOR-swizzled
#define OFF_P1   4096     // 4096: W2 panel pong
#define OFF_A    8192     // 4096: A1 then A2 in place [b=32][col=128], XOR-swizzled
#define OFF_B2   12288    // 256  [0:128]=a [128:256]=b
#define OFF_W3   12544    // 1024 [0:512]=a [512:1024]=b
#define OFF_B3   13568    // 8
#define OFF_CS   13576    // 256
#define OFF_A3   13832    // 128
#define OFF_H    13960    // 96
#define OFF_MB   14056    // 6 mbarriers x 8B
#define SMEM_FLOATS 14068
#define SMEM_BYTES (SMEM_FLOATS * 4)

#define SWZ(r) (((r) & 7) << 2)
#define MB(i) (mb + 8u * (i))

// exact GELU via A&S 7.1.26 erfc (|abs err| <= ~1.5e-7)
__device__ __forceinline__ float gelu_fast(float v) {
    float z = fabsf(v) * 0.7071067811865475f;
    float t;
    asm("rcp.approx.f32 %0, %1;" : "=f"(t) : "f"(fmaf(0.3275911f, z, 1.0f)));
    float e;
    asm("ex2.approx.f32 %0, %1;" : "=f"(e) : "f"(z * z * -1.4426950408889634f));
    float poly = fmaf(t, 1.061405429f, -1.453152027f);
    poly = fmaf(t, poly, 1.421413741f);
    poly = fmaf(t, poly, -0.284496736f);
    poly = fmaf(t, poly, 0.254829592f);
    float erfc_half = 0.5f * (poly * t) * e;
    float phi = 0.5f + copysignf(0.5f - erfc_half, v);
    return v * phi;
}

__device__ __forceinline__ float to_tf32(float x) {
    float r;
    asm("cvt.rna.tf32.f32 %0, %1;" : "=f"(r) : "f"(x));
    return r;
}

__device__ __forceinline__ void mma_tf32(float* c,
                                         uint32_t a0, uint32_t a1, uint32_t a2, uint32_t a3,
                                         uint32_t b0, uint32_t b1) {
    asm volatile(
        "mma.sync.aligned.m16n8k8.row.col.f32.tf32.tf32.f32 "
        "{%0,%1,%2,%3}, {%4,%5,%6,%7}, {%8,%9}, {%0,%1,%2,%3};"
        : "+f"(c[0]), "+f"(c[1]), "+f"(c[2]), "+f"(c[3])
        : "r"(a0), "r"(a1), "r"(a2), "r"(a3), "r"(b0), "r"(b1));
}

__device__ __forceinline__ void mbar_init(uint32_t a, uint32_t cnt) {
    asm volatile("mbarrier.init.shared.b64 [%0], %1;" :: "r"(a), "r"(cnt) : "memory");
}
__device__ __forceinline__ void mbar_arrive(uint32_t a) {
    asm volatile("mbarrier.arrive.shared.b64 _, [%0];" :: "r"(a) : "memory");
}
__device__ __forceinline__ void mbar_wait(uint32_t a, uint32_t par) {
    asm volatile(
        "{\n\t"
        ".reg .pred P1;\n"
        "WL%=:\n\t"
        "mbarrier.try_wait.parity.acquire.cta.shared::cta.b64 P1, [%0], %1, 0x989680;\n\t"
        "@P1 bra WD%=;\n\t"
        "bra.uni WL%=;\n"
        "WD%=:\n\t"
        "}"
        :: "r"(a), "r"(par) : "memory");
}
#define CBAR() asm volatile("bar.sync 5, 128;" ::: "memory")

__global__ void __launch_bounds__(256, 4)
patchflow_kernel(const float* __restrict__ x, const float* __restrict__ pos,
                 const float* __restrict__ w1a, const float* __restrict__ b1a,
                 const float* __restrict__ w2a, const float* __restrict__ b2a,
                 const float* __restrict__ w3a, const float* __restrict__ b3a,
                 const float* __restrict__ gsa, const float* __restrict__ goa,
                 const int* __restrict__ pma,
                 const float* __restrict__ w1b, const float* __restrict__ b1b,
                 const float* __restrict__ w2b, const float* __restrict__ b2b,
                 const float* __restrict__ w3b, const float* __restrict__ b3b,
                 const float* __restrict__ gsb, const float* __restrict__ gob,
                 const int* __restrict__ pmb,
                 float* __restrict__ zout, float* __restrict__ ldjout)
{
    extern __shared__ float sm[];
    const int p = blockIdx.x;
    const int t = threadIdx.x;
    const int w = t >> 5, l = t & 31;

    float* As  = sm + OFF_A;
    float* B2s = sm + OFF_B2;
    float* W3s = sm + OFF_W3;
    float* B3s = sm + OFF_B3;
    float* CSs = sm + OFF_CS;
    float* A3s = sm + OFF_A3;
    float* Hs  = sm + OFF_H;
    const uint32_t mb = (uint32_t)__cvta_generic_to_shared(sm + OFF_MB);

    const float* w2aP = w2a + (size_t)p * 16384;
    const float* w2bP = w2b + (size_t)p * 16384;

    if (t == 0) {
        #pragma unroll
        for (int i = 0; i < 6; i++) mbar_init(MB(i), 128);
    }

    // ---- small weights into smem ----
    if (t < 128) {
        B2s[t]       = __ldg(b2a + (size_t)p * 128 + t);
        B2s[128 + t] = __ldg(b2b + (size_t)p * 128 + t);
        *(float4*)(W3s + 4 * t) = __ldg((const float4*)(w3a + (size_t)p * 512) + t);
    } else {
        *(float4*)(W3s + 512 + 4 * (t - 128)) =
            __ldg((const float4*)(w3b + (size_t)p * 512) + (t - 128));
    }
    if (t == 32) {
        *(float4*)(B3s)     = __ldg((const float4*)(b3a + (size_t)p * 4));
        *(float4*)(B3s + 4) = __ldg((const float4*)(b3b + (size_t)p * 4));
    }

    // ---- 3x3 stride-2 avg pool ----
    if (t < 96) {
        int b = t / 3, c = t % 3;
        int ph = p >> 6, pw = p & 63;
        const float* xp = x + (size_t)(b * 3 + c) * 16384;
        int y0 = 2 * ph - 1, x0 = 2 * pw - 1;
        float acc = 0.f;
        #pragma unroll
        for (int dy = 0; dy < 3; dy++) {
            int yy = y0 + dy;
            if (yy < 0) continue;
            #pragma unroll
            for (int dx = 0; dx < 3; dx++) {
                int xx = x0 + dx;
                if (xx < 0) continue;
                acc += __ldg(xp + yy * 128 + xx);
            }
        }
        Hs[t] = acc * (1.f / 9.f);
    }

    // ---- cond-sums for BOTH blocks (coalesced in o) ----
    {
        int o = t & 127;
        const float* w1P = ((t < 128) ? w1a : w1b) + (size_t)p * 2176;
        const float* b1P = ((t < 128) ? b1a : b1b) + (size_t)p * 128;
        const float* posP = pos + (size_t)p * 16;
        float cs = __ldg(b1P + o);
        #pragma unroll
        for (int k = 0; k < 16; k++)
            cs = fmaf(__ldg(posP + k), __ldg(w1P + (1 + k) * 128 + o), cs);
        CSs[t] = cs;
    }
    __syncthreads();   // Hs, CSs, small weights, mbarriers visible

    // ---- layer 1 (block a), all 256 threads ----
    {
        const float* w1r0 = w1a + (size_t)p * 2176;
        float4 w1v = __ldg((const float4*)(w1r0) + l);
        float4 csv = *(const float4*)(CSs + 4 * l);
        #pragma unroll
        for (int r = 0; r < 4; r++) {
            int b = w + 8 * r;
            float h = Hs[b * 3];
            float4 v;
            v.x = to_tf32(gelu_fast(fmaf(h, w1v.x, csv.x)));
            v.y = to_tf32(gelu_fast(fmaf(h, w1v.y, csv.y)));
            v.z = to_tf32(gelu_fast(fmaf(h, w1v.z, csv.z)));
            v.w = to_tf32(gelu_fast(fmaf(h, w1v.w, csv.w)));
            *(float4*)(As + b * 128 + ((4 * l) ^ SWZ(b))) = v;
        }
    }
    __syncthreads();   // A1(blk a) visible; ROLES DIVERGE BELOW

    if (t >= 128) {
        // ================= PRODUCER (warps 4-7): straight tiled copy =================
        const int u = t - 128;
        const int wrow = u >> 5;              // 0..3 (warp within producer group)
        const int co = 4 * (u & 31);          // float4 chunk offset in a 128-float row

        // k-major panel copy: row i, coalesced LDG.128 over o, swizzled STS.128
        #define FILL(G) {                                                              \
            const int bb = (G) & 1;                                                    \
            if ((G) >= 2) mbar_wait(MB(2 + bb), (uint32_t)((((G) - 2) >> 1) & 1));     \
            const float* w2P = ((G) < 4) ? w2aP : w2bP;                                \
            float* buf = sm + (bb ? OFF_P1 : OFF_P0);                                  \
            _Pragma("unroll")                                                          \
            for (int k = 0; k < 8; k++) {                                              \
                int i = wrow + 4 * k;                                                  \
                float4 q = *(const float4*)(w2P + (size_t)(((G) & 3) * 32 + i) * 128 + co); \
                float4 v;                                                              \
                v.x = to_tf32(q.x); v.y = to_tf32(q.y);                                \
                v.z = to_tf32(q.z); v.w = to_tf32(q.w);                                \
                *(float4*)(buf + i * 128 + (co ^ SWZ(i))) = v;                         \
            }                                                                          \
            mbar_arrive(MB(bb));                                                       \
        }

        FILL(0) FILL(1) FILL(2) FILL(3) FILL(4) FILL(5)

        // layer 1 for block b (As free after consumers' H1RDY)
        mbar_wait(MB(4), 0u);
        {
            const float* w1r0 = w1b + (size_t)p * 2176;
            int li = u & 31, bw = u >> 5;
            float4 w1v = __ldg((const float4*)(w1r0) + li);
            float4 csv = *(const float4*)(CSs + 128 + 4 * li);
            #pragma unroll
            for (int r = 0; r < 8; r++) {
                int b = bw + 4 * r;
                float h = Hs[b * 3];
                float4 v;
                v.x = to_tf32(gelu_fast(fmaf(h, w1v.x, csv.x)));
                v.y = to_tf32(gelu_fast(fmaf(h, w1v.y, csv.y)));
                v.z = to_tf32(gelu_fast(fmaf(h, w1v.z, csv.z)));
                v.w = to_tf32(gelu_fast(fmaf(h, w1v.w, csv.w)));
                *(float4*)(As + b * 128 + ((4 * li) ^ SWZ(b))) = v;
            }
        }
        mbar_arrive(MB(5));                  // A1(blk b) ready

        FILL(6) FILL(7)
        #undef FILL
    } else {
        // ================= CONSUMER (warps 0-3) =================
        const int gid = l >> 2, tig = l & 3;
        const int obase = w << 5;            // 32 outputs per warp
        const int bsw0 = SWZ(tig);           // B swizzle consts (kl&7 = tig / tig+4)
        const int bsw1 = SWZ(tig + 4);
        float ldj = 0.f;                     // valid for t<32

        for (int blk = 0; blk < 2; blk++) {
            if (blk == 1) mbar_wait(MB(5), 0u);     // A1(blk b) ready

            float acc[2][4][4];
            #pragma unroll
            for (int mh = 0; mh < 2; mh++)
                #pragma unroll
                for (int nt = 0; nt < 4; nt++)
                    #pragma unroll
                    for (int k = 0; k < 4; k++) acc[mh][nt][k] = 0.f;

            #pragma unroll
            for (int c = 0; c < 4; c++) {
                int g = blk * 4 + c, bb = g & 1;
                mbar_wait(MB(bb), (uint32_t)((g >> 1) & 1));   // panel full
                const float* Pc = sm + (bb ? OFF_P1 : OFF_P0);
                #pragma unroll
                for (int ks = 0; ks < 4; ks++) {
                    int col = c * 32 + ks * 8 + tig;
                    uint32_t a[2][4];
                    #pragma unroll
                    for (int mh = 0; mh < 2; mh++) {
                        int r0 = mh * 16 + gid, r1 = r0 + 8;
                        a[mh][0] = __float_as_uint(As[r0 * 128 + (col ^ SWZ(r0))]);
                        a[mh][1] = __float_as_uint(As[r1 * 128 + (col ^ SWZ(r1))]);
                        a[mh][2] = __float_as_uint(As[r0 * 128 + ((col + 4) ^ SWZ(r0))]);
                        a[mh][3] = __float_as_uint(As[r1 * 128 + ((col + 4) ^ SWZ(r1))]);
                    }
                    // B rows (k-major panel): kl = ks*8+tig and kl+4
                    const float* Brow0 = Pc + (ks * 8 + tig) * 128;
                    const float* Brow1 = Brow0 + 4 * 128;
                    #pragma unroll
                    for (int nt = 0; nt < 4; nt++) {
                        int oo = obase + nt * 8 + gid;
                        uint32_t b0 = __float_as_uint(Brow0[oo ^ bsw0]);
                        uint32_t b1 = __float_as_uint(Brow1[oo ^ bsw1]);
                        mma_tf32(acc[0][nt], a[0][0], a[0][1], a[0][2], a[0][3], b0, b1);
                        mma_tf32(acc[1][nt], a[1][0], a[1][1], a[1][2], a[1][3], b0, b1);
                    }
                }
                mbar_arrive(MB(2 + bb));     // panel free
            }
            CBAR();                          // consumers done reading A1

            // ---- A2 = gelu(acc + b2), in place of A1 ----
            {
                const float* B2 = B2s + blk * 128;
                #pragma unroll
                for (int mh = 0; mh < 2; mh++) {
                    int r0 = mh * 16 + gid, r1 = r0 + 8;
                    #pragma unroll
                    for (int nt = 0; nt < 4; nt++) {
                        int colo = obase + nt * 8 + 2 * tig;
                        float b2l = B2[colo], b2h = B2[colo + 1];
                        float2 v0, v1;
                        v0.x = gelu_fast(acc[mh][nt][0] + b2l);
                        v0.y = gelu_fast(acc[mh][nt][1] + b2h);
                        v1.x = gelu_fast(acc[mh][nt][2] + b2l);
                        v1.y = gelu_fast(acc[mh][nt][3] + b2h);
                        *(float2*)(As + r0 * 128 + (colo ^ SWZ(r0))) = v0;
                        *(float2*)(As + r1 * 128 + (colo ^ SWZ(r1))) = v1;
                    }
                }
            }
            CBAR();                          // A2 visible

            // ---- layer 3: all 128 consumers, full K ----
            {
                int jj = t & 3, b = t >> 2;
                int sw = SWZ(b);
                const float* W3c = W3s + blk * 512;
                const float* Ar = As + b * 128;
                float a4 = 0.f;
                #pragma unroll 8
                for (int m = 0; m < 32; m++) {
                    float4 av = *(const float4*)(Ar + ((4 * m) ^ sw));
                    int i = 4 * m;
                    a4 = fmaf(av.x, W3c[i * 4 + jj], a4);
                    a4 = fmaf(av.y, W3c[(i + 1) * 4 + jj], a4);
                    a4 = fmaf(av.z, W3c[(i + 2) * 4 + jj], a4);
                    a4 = fmaf(av.w, W3c[(i + 3) * 4 + jj], a4);
                }
                A3s[t] = (a4 + B3s[blk * 4 + jj]) * 0.1f;
            }
            CBAR();                          // A3 ready; As reads done

            // ---- coupling epilogue + permutation ----
            if (t < 32) {
                int b = t;
                const float* gsP = (blk ? gsb : gsa) + (size_t)p * 3;
                const float* goP = (blk ? gob : goa) + (size_t)p * 3;
                const int*   pmP = (blk ? pmb : pma) + (size_t)p * 3;
                float sc0, sc1, sc2, lg;
                {
                    float y0 = 0.5f * __ldg(gsP);
                    float y1 = 0.5f * __ldg(gsP + 1);
                    float y2 = 0.5f * __ldg(gsP + 2);
                    sc0 = 0.2f * ((y0 > 15.f) ? y0 : log1pf(expf(y0)));
                    sc1 = 0.2f * ((y1 > 15.f) ? y1 : log1pf(expf(y1)));
                    sc2 = 0.2f * ((y2 > 15.f) ? y2 : log1pf(expf(y2)));
                    lg = logf(sc0) + logf(sc1) + logf(sc2);
                }
                float s0 = 2.f * tanhf(A3s[b * 4]);
                float s1 = 2.f * tanhf(A3s[b * 4 + 1]);
                float ov0 = Hs[b * 3];
                float ov1 = Hs[b * 3 + 1] * expf(s0) + A3s[b * 4 + 2];
                float ov2 = Hs[b * 3 + 2] * expf(s1) + A3s[b * 4 + 3];
                ov0 = ov0 * sc0 + __ldg(goP);
                ov1 = ov1 * sc1 + __ldg(goP + 1);
                ov2 = ov2 * sc2 + __ldg(goP + 2);
                ldj += s0 + s1 + lg;
                int k0 = __ldg(pmP), k1 = __ldg(pmP + 1), k2 = __ldg(pmP + 2);
                Hs[b * 3 + 0] = (k0 == 0) ? ov0 : ((k0 == 1) ? ov1 : ov2);
                Hs[b * 3 + 1] = (k1 == 0) ? ov0 : ((k1 == 1) ? ov1 : ov2);
                Hs[b * 3 + 2] = (k2 == 0) ? ov0 : ((k2 == 1) ? ov1 : ov2);
            }
            CBAR();                          // Hs visible among consumers
            if (blk == 0) mbar_arrive(MB(4));   // H ready -> producers layer1(blk b)
        }

        if (t < 96) zout[(size_t)p * 96 + t] = Hs[t];
        if (t < 32) ldjout[(size_t)p * 32 + t] = ldj;
    }
}

extern "C" void kernel_launch(void* const* d_in, const int* in_sizes, int n_in,
                              void* d_out, int out_size) {
    (void)n_in; (void)out_size;

    int ia[9], ib[9];
    if (in_sizes[10] == 12288) {
        const int A[9]  = {2, 3, 4, 5, 6, 7, 8, 9, 10};
        const int Bn[9] = {11, 12, 13, 14, 15, 16, 17, 18, 19};
        for (int i = 0; i < 9; i++) { ia[i] = A[i]; ib[i] = Bn[i]; }
    } else {
        const int A[9]  = {2, 3, 4, 5, 6, 7, 8, 9, 18};
        const int Bn[9] = {10, 11, 12, 13, 14, 15, 16, 17, 19};
        for (int i = 0; i < 9; i++) { ia[i] = A[i]; ib[i] = Bn[i]; }
    }

    cudaFuncSetAttribute(patchflow_kernel,
                         cudaFuncAttributeMaxDynamicSharedMemorySize, SMEM_BYTES);

    float* z = (float*)d_out;                 // [4096, 32, 3]
    float* ldj = z + (size_t)4096 * 32 * 3;   // [4096, 32]

    patchflow_kernel<<<4096, 256, SMEM_BYTES>>>(
        (const float*)d_in[0], (const float*)d_in[1],
        (const float*)d_in[ia[0]], (const float*)d_in[ia[1]],
        (const float*)d_in[ia[2]], (const float*)d_in[ia[3]],
        (const float*)d_in[ia[4]], (const float*)d_in[ia[5]],
        (const float*)d_in[ia[6]], (const float*)d_in[ia[7]],
        (const int*)d_in[ia[8]],
        (const float*)d_in[ib[0]], (const float*)d_in[ib[1]],
        (const float*)d_in[ib[2]], (const float*)d_in[ib[3]],
        (const float*)d_in[ib[4]], (const float*)d_in[ib[5]],
        (const float*)d_in[ib[6]], (const float*)d_in[ib[7]],
        (const int*)d_in[ib[8]],
        z, ldj);
}

// round 11
// speedup vs baseline: 2.5972x; 1.0340x over previous
#include <cuda_runtime.h>
#include <cstdint>

// ---- shared memory layout (floats) ----
#define OFF_P0   0        // 4096: W2 panel ping  [i=32][o=128] k-major, XOR-swizzled
#define OFF_P1   4096     // 4096: W2 panel pong
#define OFF_A    8192     // 4096: A1 then A2 in place [b=32][col=128], XOR-swizzled
#define OFF_B2   12288    // 256  [0:128]=a [128:256]=b
#define OFF_W3   12544    // 1024 [0:512]=a [512:1024]=b
#define OFF_B3   13568    // 8
#define OFF_CS   13576    // 256
#define OFF_A3   13832    // 128
#define OFF_H    13960    // 96
#define OFF_SC2  14056    // 8: scale per (blk,c)
#define OFF_LG   14064    // 2: sum log scale per blk
#define OFF_MB   14068    // 6 mbarriers x 8B (14068*4 % 8 == 0)
#define SMEM_FLOATS 14080
#define SMEM_BYTES (SMEM_FLOATS * 4)

#define SWZ(r) (((r) & 7) << 2)
#define MB(i) (mb + 8u * (i))

// exact GELU via A&S 7.1.26 erfc (|abs err| <= ~1.5e-7)
__device__ __forceinline__ float gelu_fast(float v) {
    float z = fabsf(v) * 0.7071067811865475f;
    float t;
    asm("rcp.approx.f32 %0, %1;" : "=f"(t) : "f"(fmaf(0.3275911f, z, 1.0f)));
    float e;
    asm("ex2.approx.f32 %0, %1;" : "=f"(e) : "f"(z * z * -1.4426950408889634f));
    float poly = fmaf(t, 1.061405429f, -1.453152027f);
    poly = fmaf(t, poly, 1.421413741f);
    poly = fmaf(t, poly, -0.284496736f);
    poly = fmaf(t, poly, 0.254829592f);
    float erfc_half = 0.5f * (poly * t) * e;
    float phi = 0.5f + copysignf(0.5f - erfc_half, v);
    return v * phi;
}

__device__ __forceinline__ float to_tf32(float x) {
    float r;
    asm("cvt.rna.tf32.f32 %0, %1;" : "=f"(r) : "f"(x));
    return r;
}
// fast tanh: 1 - 2/(e^{2x}+1), ex2+rcp approx (~1e-6 err)
__device__ __forceinline__ float fast_tanh(float x) {
    float e;
    asm("ex2.approx.f32 %0, %1;" : "=f"(e) : "f"(x * 2.8853900817779268f));
    float r;
    asm("rcp.approx.f32 %0, %1;" : "=f"(r) : "f"(e + 1.0f));
    return fmaf(-2.0f, r, 1.0f);
}
__device__ __forceinline__ float fast_exp(float x) {
    float e;
    asm("ex2.approx.f32 %0, %1;" : "=f"(e) : "f"(x * 1.4426950408889634f));
    return e;
}

__device__ __forceinline__ void mma_tf32(float* c,
                                         uint32_t a0, uint32_t a1, uint32_t a2, uint32_t a3,
                                         uint32_t b0, uint32_t b1) {
    asm volatile(
        "mma.sync.aligned.m16n8k8.row.col.f32.tf32.tf32.f32 "
        "{%0,%1,%2,%3}, {%4,%5,%6,%7}, {%8,%9}, {%0,%1,%2,%3};"
        : "+f"(c[0]), "+f"(c[1]), "+f"(c[2]), "+f"(c[3])
        : "r"(a0), "r"(a1), "r"(a2), "r"(a3), "r"(b0), "r"(b1));
}

__device__ __forceinline__ void mbar_init(uint32_t a, uint32_t cnt) {
    asm volatile("mbarrier.init.shared.b64 [%0], %1;" :: "r"(a), "r"(cnt) : "memory");
}
__device__ __forceinline__ void mbar_arrive(uint32_t a) {
    asm volatile("mbarrier.arrive.shared.b64 _, [%0];" :: "r"(a) : "memory");
}
__device__ __forceinline__ void mbar_wait(uint32_t a, uint32_t par) {
    asm volatile(
        "{\n\t"
        ".reg .pred P1;\n"
        "WL%=:\n\t"
        "mbarrier.try_wait.parity.acquire.cta.shared::cta.b64 P1, [%0], %1, 0x989680;\n\t"
        "@P1 bra WD%=;\n\t"
        "bra.uni WL%=;\n"
        "WD%=:\n\t"
        "}"
        :: "r"(a), "r"(par) : "memory");
}
#define CBAR() asm volatile("bar.sync 5, 128;" ::: "memory")

__global__ void __launch_bounds__(256, 4)
patchflow_kernel(const float* __restrict__ x, const float* __restrict__ pos,
                 const float* __restrict__ w1a, const float* __restrict__ b1a,
                 const float* __restrict__ w2a, const float* __restrict__ b2a,
                 const float* __restrict__ w3a, const float* __restrict__ b3a,
                 const float* __restrict__ gsa, const float* __restrict__ goa,
                 const int* __restrict__ pma,
                 const float* __restrict__ w1b, const float* __restrict__ b1b,
                 const float* __restrict__ w2b, const float* __restrict__ b2b,
                 const float* __restrict__ w3b, const float* __restrict__ b3b,
                 const float* __restrict__ gsb, const float* __restrict__ gob,
                 const int* __restrict__ pmb,
                 float* __restrict__ zout, float* __restrict__ ldjout)
{
    extern __shared__ float sm[];
    const int p = blockIdx.x;
    const int t = threadIdx.x;
    const int w = t >> 5, l = t & 31;

    float* As  = sm + OFF_A;
    float* B2s = sm + OFF_B2;
    float* W3s = sm + OFF_W3;
    float* B3s = sm + OFF_B3;
    float* CSs = sm + OFF_CS;
    float* A3s = sm + OFF_A3;
    float* Hs  = sm + OFF_H;
    float* SC2 = sm + OFF_SC2;
    float* LGs = sm + OFF_LG;
    const uint32_t mb = (uint32_t)__cvta_generic_to_shared(sm + OFF_MB);

    const float* w2aP = w2a + (size_t)p * 16384;
    const float* w2bP = w2b + (size_t)p * 16384;

    if (t == 0) {
        #pragma unroll
        for (int i = 0; i < 6; i++) mbar_init(MB(i), 128);
    }

    // ---- small weights into smem ----
    if (t < 128) {
        B2s[t]       = __ldg(b2a + (size_t)p * 128 + t);
        B2s[128 + t] = __ldg(b2b + (size_t)p * 128 + t);
        *(float4*)(W3s + 4 * t) = __ldg((const float4*)(w3a + (size_t)p * 512) + t);
    } else {
        *(float4*)(W3s + 512 + 4 * (t - 128)) =
            __ldg((const float4*)(w3b + (size_t)p * 512) + (t - 128));
    }
    if (t == 32) {
        *(float4*)(B3s)     = __ldg((const float4*)(b3a + (size_t)p * 4));
        *(float4*)(B3s + 4) = __ldg((const float4*)(b3b + (size_t)p * 4));
    }

    // ---- per-block coupling scales (independent of A3 -> prologue) ----
    if (t == 96 || t == 97) {
        int blk = t - 96;
        const float* gsP = (blk ? gsb : gsa) + (size_t)p * 3;
        float lg = 0.f;
        #pragma unroll
        for (int c = 0; c < 3; c++) {
            float y = 0.5f * __ldg(gsP + c);
            float sc = 0.2f * ((y > 15.f) ? y : log1pf(expf(y)));
            SC2[blk * 3 + c] = sc;
            lg += logf(sc);
        }
        LGs[blk] = lg;
    }

    // ---- 3x3 stride-2 avg pool ----
    if (t < 96) {
        int b = t / 3, c = t % 3;
        int ph = p >> 6, pw = p & 63;
        const float* xp = x + (size_t)(b * 3 + c) * 16384;
        int y0 = 2 * ph - 1, x0 = 2 * pw - 1;
        float acc = 0.f;
        #pragma unroll
        for (int dy = 0; dy < 3; dy++) {
            int yy = y0 + dy;
            if (yy < 0) continue;
            #pragma unroll
            for (int dx = 0; dx < 3; dx++) {
                int xx = x0 + dx;
                if (xx < 0) continue;
                acc += __ldg(xp + yy * 128 + xx);
            }
        }
        Hs[t] = acc * (1.f / 9.f);
    }

    // ---- cond-sums for BOTH blocks (coalesced in o) ----
    {
        int o = t & 127;
        const float* w1P = ((t < 128) ? w1a : w1b) + (size_t)p * 2176;
        const float* b1P = ((t < 128) ? b1a : b1b) + (size_t)p * 128;
        const float* posP = pos + (size_t)p * 16;
        float cs = __ldg(b1P + o);
        #pragma unroll
        for (int k = 0; k < 16; k++)
            cs = fmaf(__ldg(posP + k), __ldg(w1P + (1 + k) * 128 + o), cs);
        CSs[t] = cs;
    }
    __syncthreads();   // Hs, CSs, scales, mbarriers visible

    // ---- layer 1 (block a), all 256 threads ----
    {
        const float* w1r0 = w1a + (size_t)p * 2176;
        float4 w1v = __ldg((const float4*)(w1r0) + l);
        float4 csv = *(const float4*)(CSs + 4 * l);
        #pragma unroll
        for (int r = 0; r < 4; r++) {
            int b = w + 8 * r;
            float h = Hs[b * 3];
            float4 v;
            v.x = to_tf32(gelu_fast(fmaf(h, w1v.x, csv.x)));
            v.y = to_tf32(gelu_fast(fmaf(h, w1v.y, csv.y)));
            v.z = to_tf32(gelu_fast(fmaf(h, w1v.z, csv.z)));
            v.w = to_tf32(gelu_fast(fmaf(h, w1v.w, csv.w)));
            *(float4*)(As + b * 128 + ((4 * l) ^ SWZ(b))) = v;
        }
    }
    __syncthreads();   // A1(blk a) visible; ROLES DIVERGE BELOW

    if (t >= 128) {
        // ===== PRODUCER (warps 4-7): software-pipelined panel copy =====
        // LDG(g+1) issues right after STS(g): DRAM latency overlaps FREE wait.
        const int u = t - 128;
        const int wrow = u >> 5;
        const int co = 4 * (u & 31);
        float4 q[8];

        #define LDGP(G) {                                                             \
            const float* w2P_ = ((G) < 4) ? w2aP : w2bP;                              \
            _Pragma("unroll")                                                         \
            for (int k = 0; k < 8; k++) {                                             \
                int i = wrow + 4 * k;                                                 \
                q[k] = *(const float4*)(w2P_ + (size_t)(((G) & 3) * 32 + i) * 128 + co); \
            } }
        #define STSP(G) {                                                             \
            const int bb = (G) & 1;                                                   \
            float* buf = sm + (bb ? OFF_P1 : OFF_P0);                                 \
            _Pragma("unroll")                                                         \
            for (int k = 0; k < 8; k++) {                                             \
                int i = wrow + 4 * k;                                                 \
                float4 v;                                                             \
                v.x = to_tf32(q[k].x); v.y = to_tf32(q[k].y);                         \
                v.z = to_tf32(q[k].z); v.w = to_tf32(q[k].w);                         \
                *(float4*)(buf + i * 128 + (co ^ SWZ(i))) = v;                        \
            }                                                                         \
            mbar_arrive(MB(bb)); }

        LDGP(0)
        STSP(0)
        LDGP(1)
        STSP(1)
        LDGP(2)
        mbar_wait(MB(2), 0u); STSP(2)
        LDGP(3)
        mbar_wait(MB(3), 0u); STSP(3)
        LDGP(4)
        mbar_wait(MB(2), 1u); STSP(4)
        LDGP(5)
        mbar_wait(MB(3), 1u); STSP(5)

        // layer 1 for block b (As free after consumers' H1RDY)
        mbar_wait(MB(4), 0u);
        {
            const float* w1r0 = w1b + (size_t)p * 2176;
            int li = u & 31, bw = u >> 5;
            float4 w1v = __ldg((const float4*)(w1r0) + li);
            float4 csv = *(const float4*)(CSs + 128 + 4 * li);
            #pragma unroll
            for (int r = 0; r < 8; r++) {
                int b = bw + 4 * r;
                float h = Hs[b * 3];
                float4 v;
                v.x = to_tf32(gelu_fast(fmaf(h, w1v.x, csv.x)));
                v.y = to_tf32(gelu_fast(fmaf(h, w1v.y, csv.y)));
                v.z = to_tf32(gelu_fast(fmaf(h, w1v.z, csv.z)));
                v.w = to_tf32(gelu_fast(fmaf(h, w1v.w, csv.w)));
                *(float4*)(As + b * 128 + ((4 * li) ^ SWZ(b))) = v;
            }
        }
        mbar_arrive(MB(5));                  // A1(blk b) ready

        LDGP(6)
        mbar_wait(MB(2), 0u); STSP(6)
        LDGP(7)
        mbar_wait(MB(3), 0u); STSP(7)
        #undef LDGP
        #undef STSP
    } else {
        // ===== CONSUMER (warps 0-3) =====
        const int gid = l >> 2, tig = l & 3;
        const int obase = w << 5;            // 32 outputs per warp
        const int bsw0 = SWZ(tig);
        const int bsw1 = SWZ(tig + 4);
        float ldj = 0.f;                     // valid for t<32

        for (int blk = 0; blk < 2; blk++) {
            if (blk == 1) mbar_wait(MB(5), 0u);     // A1(blk b) ready

            float acc[2][4][4];
            #pragma unroll
            for (int mh = 0; mh < 2; mh++)
                #pragma unroll
                for (int nt = 0; nt < 4; nt++)
                    #pragma unroll
                    for (int k = 0; k < 4; k++) acc[mh][nt][k] = 0.f;

            #pragma unroll
            for (int c = 0; c < 4; c++) {
                int g = blk * 4 + c, bb = g & 1;
                mbar_wait(MB(bb), (uint32_t)((g >> 1) & 1));   // panel full
                const float* Pc = sm + (bb ? OFF_P1 : OFF_P0);
                #pragma unroll
                for (int ks = 0; ks < 4; ks++) {
                    int col = c * 32 + ks * 8 + tig;
                    uint32_t a[2][4];
                    #pragma unroll
                    for (int mh = 0; mh < 2; mh++) {
                        int r0 = mh * 16 + gid, r1 = r0 + 8;
                        a[mh][0] = __float_as_uint(As[r0 * 128 + (col ^ SWZ(r0))]);
                        a[mh][1] = __float_as_uint(As[r1 * 128 + (col ^ SWZ(r1))]);
                        a[mh][2] = __float_as_uint(As[r0 * 128 + ((col + 4) ^ SWZ(r0))]);
                        a[mh][3] = __float_as_uint(As[r1 * 128 + ((col + 4) ^ SWZ(r1))]);
                    }
                    const float* Brow0 = Pc + (ks * 8 + tig) * 128;
                    const float* Brow1 = Brow0 + 4 * 128;
                    #pragma unroll
                    for (int nt = 0; nt < 4; nt++) {
                        int oo = obase + nt * 8 + gid;
                        uint32_t b0 = __float_as_uint(Brow0[oo ^ bsw0]);
                        uint32_t b1 = __float_as_uint(Brow1[oo ^ bsw1]);
                        mma_tf32(acc[0][nt], a[0][0], a[0][1], a[0][2], a[0][3], b0, b1);
                        mma_tf32(acc[1][nt], a[1][0], a[1][1], a[1][2], a[1][3], b0, b1);
                    }
                }
                mbar_arrive(MB(2 + bb));     // panel free
            }
            CBAR();                          // consumers done reading A1

            // ---- A2 = gelu(acc + b2), in place of A1 ----
            {
                const float* B2 = B2s + blk * 128;
                #pragma unroll
                for (int mh = 0; mh < 2; mh++) {
                    int r0 = mh * 16 + gid, r1 = r0 + 8;
                    #pragma unroll
                    for (int nt = 0; nt < 4; nt++) {
                        int colo = obase + nt * 8 + 2 * tig;
                        float b2l = B2[colo], b2h = B2[colo + 1];
                        float2 v0, v1;
                        v0.x = gelu_fast(acc[mh][nt][0] + b2l);
                        v0.y = gelu_fast(acc[mh][nt][1] + b2h);
                        v1.x = gelu_fast(acc[mh][nt][2] + b2l);
                        v1.y = gelu_fast(acc[mh][nt][3] + b2h);
                        *(float2*)(As + r0 * 128 + (colo ^ SWZ(r0))) = v0;
                        *(float2*)(As + r1 * 128 + (colo ^ SWZ(r1))) = v1;
                    }
                }
            }
            CBAR();                          // A2 visible

            // ---- layer 3: all 128 consumers, full K ----
            {
                int jj = t & 3, b = t >> 2;
                int sw = SWZ(b);
                const float* W3c = W3s + blk * 512;
                const float* Ar = As + b * 128;
                float a4 = 0.f;
                #pragma unroll 8
                for (int m = 0; m < 32; m++) {
                    float4 av = *(const float4*)(Ar + ((4 * m) ^ sw));
                    int i = 4 * m;
                    a4 = fmaf(av.x, W3c[i * 4 + jj], a4);
                    a4 = fmaf(av.y, W3c[(i + 1) * 4 + jj], a4);
                    a4 = fmaf(av.z, W3c[(i + 2) * 4 + jj], a4);
                    a4 = fmaf(av.w, W3c[(i + 3) * 4 + jj], a4);
                }
                A3s[t] = (a4 + B3s[blk * 4 + jj]) * 0.1f;
            }
            CBAR();                          // A3 ready; As reads done

            // ---- coupling epilogue + permutation (fast math, precomp scales) ----
            if (t < 32) {
                int b = t;
                const float* goP = (blk ? gob : goa) + (size_t)p * 3;
                const int*   pmP = (blk ? pmb : pma) + (size_t)p * 3;
                float sc0 = SC2[blk * 3], sc1 = SC2[blk * 3 + 1], sc2 = SC2[blk * 3 + 2];
                float s0 = 2.f * fast_tanh(A3s[b * 4]);
                float s1 = 2.f * fast_tanh(A3s[b * 4 + 1]);
                float ov0 = Hs[b * 3];
                float ov1 = Hs[b * 3 + 1] * fast_exp(s0) + A3s[b * 4 + 2];
                float ov2 = Hs[b * 3 + 2] * fast_exp(s1) + A3s[b * 4 + 3];
                ov0 = ov0 * sc0 + __ldg(goP);
                ov1 = ov1 * sc1 + __ldg(goP + 1);
                ov2 = ov2 * sc2 + __ldg(goP + 2);
                ldj += s0 + s1 + LGs[blk];
                int k0 = __ldg(pmP), k1 = __ldg(pmP + 1), k2 = __ldg(pmP + 2);
                Hs[b * 3 + 0] = (k0 == 0) ? ov0 : ((k0 == 1) ? ov1 : ov2);
                Hs[b * 3 + 1] = (k1 == 0) ? ov0 : ((k1 == 1) ? ov1 : ov2);
                Hs[b * 3 + 2] = (k2 == 0) ? ov0 : ((k2 == 1) ? ov1 : ov2);
            }
            CBAR();                          // Hs visible among consumers
            if (blk == 0) mbar_arrive(MB(4));   // H ready -> producers layer1(blk b)
        }

        if (t < 96) zout[(size_t)p * 96 + t] = Hs[t];
        if (t < 32) ldjout[(size_t)p * 32 + t] = ldj;
    }
}

extern "C" void kernel_launch(void* const* d_in, const int* in_sizes, int n_in,
                              void* d_out, int out_size) {
    (void)n_in; (void)out_size;

    int ia[9], ib[9];
    if (in_sizes[10] == 12288) {
        const int A[9]  = {2, 3, 4, 5, 6, 7, 8, 9, 10};
        const int Bn[9] = {11, 12, 13, 14, 15, 16, 17, 18, 19};
        for (int i = 0; i < 9; i++) { ia[i] = A[i]; ib[i] = Bn[i]; }
    } else {
        const int A[9]  = {2, 3, 4, 5, 6, 7, 8, 9, 18};
        const int Bn[9] = {10, 11, 12, 13, 14, 15, 16, 17, 19};
        for (int i = 0; i < 9; i++) { ia[i] = A[i]; ib[i] = Bn[i]; }
    }

    cudaFuncSetAttribute(patchflow_kernel,
                         cudaFuncAttributeMaxDynamicSharedMemorySize, SMEM_BYTES);

    float* z = (float*)d_out;                 // [4096, 32, 3]
    float* ldj = z + (size_t)4096 * 32 * 3;   // [4096, 32]

    patchflow_kernel<<<4096, 256, SMEM_BYTES>>>(
        (const float*)d_in[0], (const float*)d_in[1],
        (const float*)d_in[ia[0]], (const float*)d_in[ia[1]],
        (const float*)d_in[ia[2]], (const float*)d_in[ia[3]],
        (const float*)d_in[ia[4]], (const float*)d_in[ia[5]],
        (const float*)d_in[ia[6]], (const float*)d_in[ia[7]],
        (const int*)d_in[ia[8]],
        (const float*)d_in[ib[0]], (const float*)d_in[ib[1]],
        (const float*)d_in[ib[2]], (const float*)d_in[ib[3]],
        (const float*)d_in[ib[4]], (const float*)d_in[ib[5]],
        (const float*)d_in[ib[6]], (const float*)d_in[ib[7]],
        (const int*)d_in[ib[8]],
        z, ldj);
}

// round 13
// speedup vs baseline: 2.6959x; 1.0380x over previous
#include <cuda_runtime.h>
#include <cstdint>

// ---- shared memory layout (floats) ----
#define OFF_P0   0        // 4096: W2 panel ping  [i=32][o=128] k-major, XOR-swizzled
#define OFF_P1   4096     // 4096: W2 panel pong
#define OFF_A    8192     // 4096: A1 (mma B-operand); first 512 reused as layer3 partials
#define OFF_B2   12288    // 256  [0:128]=a [128:256]=b
#define OFF_W3   12544    // 1024 [0:512]=a [512:1024]=b
#define OFF_B3   13568    // 8
#define OFF_CS   13576    // 256
#define OFF_H    13960    // 96
#define OFF_SC2  14056    // 8: scale per (blk,c)
#define OFF_LG   14064    // 2: sum log scale per blk
#define OFF_MB   14068    // 6 mbarriers x 8B
#define SMEM_FLOATS 14080
#define SMEM_BYTES (SMEM_FLOATS * 4)

#define SWZ(r) (((r) & 7) << 2)
#define MB(i) (mb + 8u * (i))

// exact GELU via A&S 7.1.26 erfc (|abs err| <= ~1.5e-7)
__device__ __forceinline__ float gelu_fast(float v) {
    float z = fabsf(v) * 0.7071067811865475f;
    float t;
    asm("rcp.approx.f32 %0, %1;" : "=f"(t) : "f"(fmaf(0.3275911f, z, 1.0f)));
    float e;
    asm("ex2.approx.f32 %0, %1;" : "=f"(e) : "f"(z * z * -1.4426950408889634f));
    float poly = fmaf(t, 1.061405429f, -1.453152027f);
    poly = fmaf(t, poly, 1.421413741f);
    poly = fmaf(t, poly, -0.284496736f);
    poly = fmaf(t, poly, 0.254829592f);
    float erfc_half = 0.5f * (poly * t) * e;
    float phi = 0.5f + copysignf(0.5f - erfc_half, v);
    return v * phi;
}

__device__ __forceinline__ float to_tf32(float x) {
    float r;
    asm("cvt.rna.tf32.f32 %0, %1;" : "=f"(r) : "f"(x));
    return r;
}
__device__ __forceinline__ float fast_tanh(float x) {
    float e;
    asm("ex2.approx.f32 %0, %1;" : "=f"(e) : "f"(x * 2.8853900817779268f));
    float r;
    asm("rcp.approx.f32 %0, %1;" : "=f"(r) : "f"(e + 1.0f));
    return fmaf(-2.0f, r, 1.0f);
}
__device__ __forceinline__ float fast_exp(float x) {
    float e;
    asm("ex2.approx.f32 %0, %1;" : "=f"(e) : "f"(x * 1.4426950408889634f));
    return e;
}

__device__ __forceinline__ void mma_tf32(float* c,
                                         uint32_t a0, uint32_t a1, uint32_t a2, uint32_t a3,
                                         uint32_t b0, uint32_t b1) {
    asm volatile(
        "mma.sync.aligned.m16n8k8.row.col.f32.tf32.tf32.f32 "
        "{%0,%1,%2,%3}, {%4,%5,%6,%7}, {%8,%9}, {%0,%1,%2,%3};"
        : "+f"(c[0]), "+f"(c[1]), "+f"(c[2]), "+f"(c[3])
        : "r"(a0), "r"(a1), "r"(a2), "r"(a3), "r"(b0), "r"(b1));
}

__device__ __forceinline__ void mbar_init(uint32_t a, uint32_t cnt) {
    asm volatile("mbarrier.init.shared.b64 [%0], %1;" :: "r"(a), "r"(cnt) : "memory");
}
__device__ __forceinline__ void mbar_arrive(uint32_t a) {
    asm volatile("mbarrier.arrive.shared.b64 _, [%0];" :: "r"(a) : "memory");
}
__device__ __forceinline__ void mbar_wait(uint32_t a, uint32_t par) {
    asm volatile(
        "{\n\t"
        ".reg .pred P1;\n"
        "WL%=:\n\t"
        "mbarrier.try_wait.parity.acquire.cta.shared::cta.b64 P1, [%0], %1, 0x989680;\n\t"
        "@P1 bra WD%=;\n\t"
        "bra.uni WL%=;\n"
        "WD%=:\n\t"
        "}"
        :: "r"(a), "r"(par) : "memory");
}
#define CBAR() asm volatile("bar.sync 5, 128;" ::: "memory")

__global__ void __launch_bounds__(256, 4)
patchflow_kernel(const float* __restrict__ x, const float* __restrict__ pos,
                 const float* __restrict__ w1a, const float* __restrict__ b1a,
                 const float* __restrict__ w2a, const float* __restrict__ b2a,
                 const float* __restrict__ w3a, const float* __restrict__ b3a,
                 const float* __restrict__ gsa, const float* __restrict__ goa,
                 const int* __restrict__ pma,
                 const float* __restrict__ w1b, const float* __restrict__ b1b,
                 const float* __restrict__ w2b, const float* __restrict__ b2b,
                 const float* __restrict__ w3b, const float* __restrict__ b3b,
                 const float* __restrict__ gsb, const float* __restrict__ gob,
                 const int* __restrict__ pmb,
                 float* __restrict__ zout, float* __restrict__ ldjout)
{
    extern __shared__ float sm[];
    const int p = blockIdx.x;
    const int t = threadIdx.x;
    const int w = t >> 5, l = t & 31;

    float* As  = sm + OFF_A;
    float* B2s = sm + OFF_B2;
    float* W3s = sm + OFF_W3;
    float* B3s = sm + OFF_B3;
    float* CSs = sm + OFF_CS;
    float* Hs  = sm + OFF_H;
    float* SC2 = sm + OFF_SC2;
    float* LGs = sm + OFF_LG;
    const uint32_t mb = (uint32_t)__cvta_generic_to_shared(sm + OFF_MB);

    const float* w2aP = w2a + (size_t)p * 16384;
    const float* w2bP = w2b + (size_t)p * 16384;

    if (t == 0) {
        #pragma unroll
        for (int i = 0; i < 6; i++) mbar_init(MB(i), 128);
    }

    // ---- small weights into smem ----
    if (t < 128) {
        B2s[t]       = __ldg(b2a + (size_t)p * 128 + t);
        B2s[128 + t] = __ldg(b2b + (size_t)p * 128 + t);
        *(float4*)(W3s + 4 * t) = __ldg((const float4*)(w3a + (size_t)p * 512) + t);
    } else {
        *(float4*)(W3s + 512 + 4 * (t - 128)) =
            __ldg((const float4*)(w3b + (size_t)p * 512) + (t - 128));
    }
    if (t == 32) {
        *(float4*)(B3s)     = __ldg((const float4*)(b3a + (size_t)p * 4));
        *(float4*)(B3s + 4) = __ldg((const float4*)(b3b + (size_t)p * 4));
    }

    // ---- per-block coupling scales (prologue) ----
    if (t == 96 || t == 97) {
        int blk = t - 96;
        const float* gsP = (blk ? gsb : gsa) + (size_t)p * 3;
        float lg = 0.f;
        #pragma unroll
        for (int c = 0; c < 3; c++) {
            float y = 0.5f * __ldg(gsP + c);
            float sc = 0.2f * ((y > 15.f) ? y : log1pf(expf(y)));
            SC2[blk * 3 + c] = sc;
            lg += logf(sc);
        }
        LGs[blk] = lg;
    }

    // ---- 3x3 stride-2 avg pool ----
    if (t < 96) {
        int b = t / 3, c = t % 3;
        int ph = p >> 6, pw = p & 63;
        const float* xp = x + (size_t)(b * 3 + c) * 16384;
        int y0 = 2 * ph - 1, x0 = 2 * pw - 1;
        float acc = 0.f;
        #pragma unroll
        for (int dy = 0; dy < 3; dy++) {
            int yy = y0 + dy;
            if (yy < 0) continue;
            #pragma unroll
            for (int dx = 0; dx < 3; dx++) {
                int xx = x0 + dx;
                if (xx < 0) continue;
                acc += __ldg(xp + yy * 128 + xx);
            }
        }
        Hs[t] = acc * (1.f / 9.f);
    }

    // ---- cond-sums for BOTH blocks ----
    {
        int o = t & 127;
        const float* w1P = ((t < 128) ? w1a : w1b) + (size_t)p * 2176;
        const float* b1P = ((t < 128) ? b1a : b1b) + (size_t)p * 128;
        const float* posP = pos + (size_t)p * 16;
        float cs = __ldg(b1P + o);
        #pragma unroll
        for (int k = 0; k < 16; k++)
            cs = fmaf(__ldg(posP + k), __ldg(w1P + (1 + k) * 128 + o), cs);
        CSs[t] = cs;
    }
    __syncthreads();

    // ---- layer 1 (block a), all 256 threads ----
    {
        const float* w1r0 = w1a + (size_t)p * 2176;
        float4 w1v = __ldg((const float4*)(w1r0) + l);
        float4 csv = *(const float4*)(CSs + 4 * l);
        #pragma unroll
        for (int r = 0; r < 4; r++) {
            int b = w + 8 * r;
            float h = Hs[b * 3];
            float4 v;
            v.x = to_tf32(gelu_fast(fmaf(h, w1v.x, csv.x)));
            v.y = to_tf32(gelu_fast(fmaf(h, w1v.y, csv.y)));
            v.z = to_tf32(gelu_fast(fmaf(h, w1v.z, csv.z)));
            v.w = to_tf32(gelu_fast(fmaf(h, w1v.w, csv.w)));
            *(float4*)(As + b * 128 + ((4 * l) ^ SWZ(b))) = v;
        }
    }
    __syncthreads();   // A1(blk a) visible; ROLES DIVERGE

    if (t >= 128) {
        // ===== PRODUCER (warps 4-7): software-pipelined panel copy =====
        const int u = t - 128;
        const int wrow = u >> 5;
        const int co = 4 * (u & 31);
        float4 q[8];

        #define LDGP(G) {                                                             \
            const float* w2P_ = ((G) < 4) ? w2aP : w2bP;                              \
            _Pragma("unroll")                                                         \
            for (int k = 0; k < 8; k++) {                                             \
                int i = wrow + 4 * k;                                                 \
                q[k] = *(const float4*)(w2P_ + (size_t)(((G) & 3) * 32 + i) * 128 + co); \
            } }
        #define STSP(G) {                                                             \
            const int bb = (G) & 1;                                                   \
            float* buf = sm + (bb ? OFF_P1 : OFF_P0);                                 \
            _Pragma("unroll")                                                         \
            for (int k = 0; k < 8; k++) {                                             \
                int i = wrow + 4 * k;                                                 \
                float4 v;                                                             \
                v.x = to_tf32(q[k].x); v.y = to_tf32(q[k].y);                         \
                v.z = to_tf32(q[k].z); v.w = to_tf32(q[k].w);                         \
                *(float4*)(buf + i * 128 + (co ^ SWZ(i))) = v;                        \
            }                                                                         \
            mbar_arrive(MB(bb)); }

        LDGP(0)
        STSP(0)
        LDGP(1)
        STSP(1)
        LDGP(2)
        mbar_wait(MB(2), 0u); STSP(2)
        LDGP(3)
        mbar_wait(MB(3), 0u); STSP(3)
        LDGP(4)
        mbar_wait(MB(2), 1u); STSP(4)
        LDGP(5)
        mbar_wait(MB(3), 1u); STSP(5)

        mbar_wait(MB(4), 0u);
        {
            const float* w1r0 = w1b + (size_t)p * 2176;
            int li = u & 31, bw = u >> 5;
            float4 w1v = __ldg((const float4*)(w1r0) + li);
            float4 csv = *(const float4*)(CSs + 128 + 4 * li);
            #pragma unroll
            for (int r = 0; r < 8; r++) {
                int b = bw + 4 * r;
                float h = Hs[b * 3];
                float4 v;
                v.x = to_tf32(gelu_fast(fmaf(h, w1v.x, csv.x)));
                v.y = to_tf32(gelu_fast(fmaf(h, w1v.y, csv.y)));
                v.z = to_tf32(gelu_fast(fmaf(h, w1v.z, csv.z)));
                v.w = to_tf32(gelu_fast(fmaf(h, w1v.w, csv.w)));
                *(float4*)(As + b * 128 + ((4 * li) ^ SWZ(b))) = v;
            }
        }
        mbar_arrive(MB(5));

        LDGP(6)
        mbar_wait(MB(2), 0u); STSP(6)
        LDGP(7)
        mbar_wait(MB(3), 0u); STSP(7)
        #undef LDGP
        #undef STSP
    } else {
        // ===== CONSUMER (warps 0-3) =====
        const int gid = l >> 2, tig = l & 3;
        const int obase = w << 5;
        const int g0 = gid & 1, kper = gid >> 1;
        // Hoisted per-lane A offsets: physical addr = row*128 + 32c + oA{0,1}[j]
        // (warp-uniform k-tile ks = j; the swizzle folds into these constants)
        int oA0[4], oA1[4];
        #pragma unroll
        for (int j = 0; j < 4; j++) {
            oA0[j] = 8 * (j ^ kper) + tig + 4 * g0;
            oA1[j] = 8 * (j ^ kper) + tig + 4 * (g0 ^ 1);
        }
        // B in-row column offsets (hoisted XOR constants)
        const int bsw0 = SWZ(tig), bsw1 = SWZ(tig + 4);
        int bo0[4], bo1[4];
        #pragma unroll
        for (int nt = 0; nt < 4; nt++) {
            int oo = obase + nt * 8 + gid;
            bo0[nt] = oo ^ bsw0;
            bo1[nt] = oo ^ bsw1;
        }
        float ldj = 0.f;   // valid for t<32

        for (int blk = 0; blk < 2; blk++) {
            if (blk == 1) mbar_wait(MB(5), 0u);

            float acc[2][4][4];
            #pragma unroll
            for (int mh = 0; mh < 2; mh++)
                #pragma unroll
                for (int nt = 0; nt < 4; nt++)
                    #pragma unroll
                    for (int k = 0; k < 4; k++) acc[mh][nt][k] = 0.f;

            #pragma unroll
            for (int c = 0; c < 4; c++) {
                int g = blk * 4 + c, bb = g & 1;
                mbar_wait(MB(bb), (uint32_t)((g >> 1) & 1));
                const float* Pc = sm + (bb ? OFF_P1 : OFF_P0);
                const float* Ac = As + 32 * c;
                #pragma unroll
                for (int j = 0; j < 4; j++) {
                    // warp-uniform k-tile j; per-lane constant offsets
                    uint32_t a00 = __float_as_uint(Ac[gid * 128 + oA0[j]]);
                    uint32_t a01 = __float_as_uint(Ac[(gid + 8) * 128 + oA0[j]]);
                    uint32_t a02 = __float_as_uint(Ac[gid * 128 + oA1[j]]);
                    uint32_t a03 = __float_as_uint(Ac[(gid + 8) * 128 + oA1[j]]);
                    uint32_t a10 = __float_as_uint(Ac[(gid + 16) * 128 + oA0[j]]);
                    uint32_t a11 = __float_as_uint(Ac[(gid + 24) * 128 + oA0[j]]);
                    uint32_t a12 = __float_as_uint(Ac[(gid + 16) * 128 + oA1[j]]);
                    uint32_t a13 = __float_as_uint(Ac[(gid + 24) * 128 + oA1[j]]);
                    const float* Brow0 = Pc + (j * 8 + tig) * 128;
                    const float* Brow1 = Brow0 + 512;
                    #pragma unroll
                    for (int nt = 0; nt < 4; nt++) {
                        uint32_t b0 = __float_as_uint(Brow0[bo0[nt]]);
                        uint32_t b1 = __float_as_uint(Brow1[bo1[nt]]);
                        mma_tf32(acc[0][nt], a00, a01, a02, a03, b0, b1);
                        mma_tf32(acc[1][nt], a10, a11, a12, a13, b0, b1);
                    }
                }
                mbar_arrive(MB(2 + bb));
            }
            CBAR();                          // consumers done reading A1

            // ---- fused: bias + gelu + layer3 partial dot (A2 never hits smem) ----
            float4 ps0 = {0,0,0,0}, ps1 = ps0, ps2 = ps0, ps3 = ps0;
            {
                const float* B2 = B2s + blk * 128;
                const float* W3c = W3s + blk * 512;
                #pragma unroll
                for (int nt = 0; nt < 4; nt++) {
                    int colo = obase + nt * 8 + 2 * tig;
                    float4 wl = *(const float4*)(W3c + colo * 4);
                    float4 wh = *(const float4*)(W3c + colo * 4 + 4);
                    float bl = B2[colo], bh = B2[colo + 1];
                    float g;
                    #define ACC4(PS, G) { PS.x = fmaf(G, wl.x, PS.x); PS.y = fmaf(G, wl.y, PS.y); \
                                          PS.z = fmaf(G, wl.z, PS.z); PS.w = fmaf(G, wl.w, PS.w); }
                    #define ACC4H(PS, G) { PS.x = fmaf(G, wh.x, PS.x); PS.y = fmaf(G, wh.y, PS.y); \
                                           PS.z = fmaf(G, wh.z, PS.z); PS.w = fmaf(G, wh.w, PS.w); }
                    g = gelu_fast(acc[0][nt][0] + bl); ACC4(ps0, g)
                    g = gelu_fast(acc[0][nt][1] + bh); ACC4H(ps0, g)
                    g = gelu_fast(acc[0][nt][2] + bl); ACC4(ps1, g)
                    g = gelu_fast(acc[0][nt][3] + bh); ACC4H(ps1, g)
                    g = gelu_fast(acc[1][nt][0] + bl); ACC4(ps2, g)
                    g = gelu_fast(acc[1][nt][1] + bh); ACC4H(ps2, g)
                    g = gelu_fast(acc[1][nt][2] + bl); ACC4(ps3, g)
                    g = gelu_fast(acc[1][nt][3] + bh); ACC4H(ps3, g)
                    #undef ACC4
                    #undef ACC4H
                }
            }
            // reduce over tig (lane bits 0-1)
            #define RED(PS) { \
                PS.x += __shfl_xor_sync(0xffffffffu, PS.x, 1); PS.x += __shfl_xor_sync(0xffffffffu, PS.x, 2); \
                PS.y += __shfl_xor_sync(0xffffffffu, PS.y, 1); PS.y += __shfl_xor_sync(0xffffffffu, PS.y, 2); \
                PS.z += __shfl_xor_sync(0xffffffffu, PS.z, 1); PS.z += __shfl_xor_sync(0xffffffffu, PS.z, 2); \
                PS.w += __shfl_xor_sync(0xffffffffu, PS.w, 1); PS.w += __shfl_xor_sync(0xffffffffu, PS.w, 2); }
            RED(ps0) RED(ps1) RED(ps2) RED(ps3)
            #undef RED
            if (tig == 0) {                  // per-warp partials into dead As region
                float* A3P = As + w * 128;
                *(float4*)(A3P + gid * 4)        = ps0;
                *(float4*)(A3P + (gid + 8) * 4)  = ps1;
                *(float4*)(A3P + (gid + 16) * 4) = ps2;
                *(float4*)(A3P + (gid + 24) * 4) = ps3;
            }
            CBAR();                          // partials visible

            // ---- coupling (folds final cross-warp A3 reduction in) ----
            if (t < 32) {
                int b = t;
                float a3[4];
                #pragma unroll
                for (int j = 0; j < 4; j++) {
                    float s = As[b * 4 + j] + As[128 + b * 4 + j]
                            + As[256 + b * 4 + j] + As[384 + b * 4 + j];
                    a3[j] = (s + B3s[blk * 4 + j]) * 0.1f;
                }
                const float* goP = (blk ? gob : goa) + (size_t)p * 3;
                const int*   pmP = (blk ? pmb : pma) + (size_t)p * 3;
                float sc0 = SC2[blk * 3], sc1 = SC2[blk * 3 + 1], sc2 = SC2[blk * 3 + 2];
                float s0 = 2.f * fast_tanh(a3[0]);
                float s1 = 2.f * fast_tanh(a3[1]);
                float ov0 = Hs[b * 3];
                float ov1 = Hs[b * 3 + 1] * fast_exp(s0) + a3[2];
                float ov2 = Hs[b * 3 + 2] * fast_exp(s1) + a3[3];
                ov0 = ov0 * sc0 + __ldg(goP);
                ov1 = ov1 * sc1 + __ldg(goP + 1);
                ov2 = ov2 * sc2 + __ldg(goP + 2);
                ldj += s0 + s1 + LGs[blk];
                int k0 = __ldg(pmP), k1 = __ldg(pmP + 1), k2 = __ldg(pmP + 2);
                Hs[b * 3 + 0] = (k0 == 0) ? ov0 : ((k0 == 1) ? ov1 : ov2);
                Hs[b * 3 + 1] = (k1 == 0) ? ov0 : ((k1 == 1) ? ov1 : ov2);
                Hs[b * 3 + 2] = (k2 == 0) ? ov0 : ((k2 == 1) ? ov1 : ov2);
            }
            CBAR();                          // Hs visible among consumers
            if (blk == 0) mbar_arrive(MB(4));   // H ready -> producers layer1(blk b)
        }

        if (t < 96) zout[(size_t)p * 96 + t] = Hs[t];
        if (t < 32) ldjout[(size_t)p * 32 + t] = ldj;
    }
}

extern "C" void kernel_launch(void* const* d_in, const int* in_sizes, int n_in,
                              void* d_out, int out_size) {
    (void)n_in; (void)out_size;

    int ia[9], ib[9];
    if (in_sizes[10] == 12288) {
        const int A[9]  = {2, 3, 4, 5, 6, 7, 8, 9, 10};
        const int Bn[9] = {11, 12, 13, 14, 15, 16, 17, 18, 19};
        for (int i = 0; i < 9; i++) { ia[i] = A[i]; ib[i] = Bn[i]; }
    } else {
        const int A[9]  = {2, 3, 4, 5, 6, 7, 8, 9, 18};
        const int Bn[9] = {10, 11, 12, 13, 14, 15, 16, 17, 19};
        for (int i = 0; i < 9; i++) { ia[i] = A[i]; ib[i] = Bn[i]; }
    }

    cudaFuncSetAttribute(patchflow_kernel,
                         cudaFuncAttributeMaxDynamicSharedMemorySize, SMEM_BYTES);

    float* z = (float*)d_out;                 // [4096, 32, 3]
    float* ldj = z + (size_t)4096 * 32 * 3;   // [4096, 32]

    patchflow_kernel<<<4096, 256, SMEM_BYTES>>>(
        (const float*)d_in[0], (const float*)d_in[1],
        (const float*)d_in[ia[0]], (const float*)d_in[ia[1]],
        (const float*)d_in[ia[2]], (const float*)d_in[ia[3]],
        (const float*)d_in[ia[4]], (const float*)d_in[ia[5]],
        (const float*)d_in[ia[6]], (const float*)d_in[ia[7]],
        (const int*)d_in[ia[8]],
        (const float*)d_in[ib[0]], (const float*)d_in[ib[1]],
        (const float*)d_in[ib[2]], (const float*)d_in[ib[3]],
        (const float*)d_in[ib[4]], (const float*)d_in[ib[5]],
        (const float*)d_in[ib[6]], (const float*)d_in[ib[7]],
        (const int*)d_in[ib[8]],
        z, ldj);
}

// round 14
// speedup vs baseline: 3.3716x; 1.2506x over previous
#include <cuda_runtime.h>
#include <cstdint>

// ---- shared memory layout (floats) ----
#define OFF_P0   0        // 4096: W2 panel ping  [i=32][o=128] k-major, XOR-swizzled
#define OFF_P1   4096     // 4096: W2 panel pong
#define OFF_A    8192     // 4096: A1 (mma B-operand); first 512 reused as layer3 partials
#define OFF_B2   12288    // 256  [0:128]=a [128:256]=b
#define OFF_W3   12544    // 1024 [0:512]=a [512:1024]=b
#define OFF_B3   13568    // 8
#define OFF_CS   13576    // 256
#define OFF_H    13960    // 96
#define OFF_SC2  14056    // 8: scale per (blk,c)
#define OFF_LG   14064    // 2: sum log scale per blk
#define OFF_MB   14068    // 6 mbarriers x 8B
#define SMEM_FLOATS 14080
#define SMEM_BYTES (SMEM_FLOATS * 4)

#define SWZ(r) (((r) & 7) << 2)
#define MB(i) (mb + 8u * (i))

// exact GELU via A&S 7.1.26 erfc (|abs err| <= ~1.5e-7)
__device__ __forceinline__ float gelu_fast(float v) {
    float z = fabsf(v) * 0.7071067811865475f;
    float t;
    asm("rcp.approx.f32 %0, %1;" : "=f"(t) : "f"(fmaf(0.3275911f, z, 1.0f)));
    float e;
    asm("ex2.approx.f32 %0, %1;" : "=f"(e) : "f"(z * z * -1.4426950408889634f));
    float poly = fmaf(t, 1.061405429f, -1.453152027f);
    poly = fmaf(t, poly, 1.421413741f);
    poly = fmaf(t, poly, -0.284496736f);
    poly = fmaf(t, poly, 0.254829592f);
    float erfc_half = 0.5f * (poly * t) * e;
    float phi = 0.5f + copysignf(0.5f - erfc_half, v);
    return v * phi;
}

__device__ __forceinline__ float to_tf32(float x) {
    float r;
    asm("cvt.rna.tf32.f32 %0, %1;" : "=f"(r) : "f"(x));
    return r;
}
__device__ __forceinline__ float fast_tanh(float x) {
    float e;
    asm("ex2.approx.f32 %0, %1;" : "=f"(e) : "f"(x * 2.8853900817779268f));
    float r;
    asm("rcp.approx.f32 %0, %1;" : "=f"(r) : "f"(e + 1.0f));
    return fmaf(-2.0f, r, 1.0f);
}
__device__ __forceinline__ float fast_exp(float x) {
    float e;
    asm("ex2.approx.f32 %0, %1;" : "=f"(e) : "f"(x * 1.4426950408889634f));
    return e;
}

__device__ __forceinline__ void mma_tf32(float* c,
                                         uint32_t a0, uint32_t a1, uint32_t a2, uint32_t a3,
                                         uint32_t b0, uint32_t b1) {
    asm volatile(
        "mma.sync.aligned.m16n8k8.row.col.f32.tf32.tf32.f32 "
        "{%0,%1,%2,%3}, {%4,%5,%6,%7}, {%8,%9}, {%0,%1,%2,%3};"
        : "+f"(c[0]), "+f"(c[1]), "+f"(c[2]), "+f"(c[3])
        : "r"(a0), "r"(a1), "r"(a2), "r"(a3), "r"(b0), "r"(b1));
}

__device__ __forceinline__ void cp16(float* s, const float* g) {
    unsigned a = (unsigned)__cvta_generic_to_shared(s);
    asm volatile("cp.async.cg.shared.global [%0], [%1], 16;" :: "r"(a), "l"(g));
}

__device__ __forceinline__ void mbar_init(uint32_t a, uint32_t cnt) {
    asm volatile("mbarrier.init.shared.b64 [%0], %1;" :: "r"(a), "r"(cnt) : "memory");
}
__device__ __forceinline__ void mbar_arrive(uint32_t a) {
    asm volatile("mbarrier.arrive.shared.b64 _, [%0];" :: "r"(a) : "memory");
}
__device__ __forceinline__ void mbar_wait(uint32_t a, uint32_t par) {
    asm volatile(
        "{\n\t"
        ".reg .pred P1;\n"
        "WL%=:\n\t"
        "mbarrier.try_wait.parity.acquire.cta.shared::cta.b64 P1, [%0], %1, 0x989680;\n\t"
        "@P1 bra WD%=;\n\t"
        "bra.uni WL%=;\n"
        "WD%=:\n\t"
        "}"
        :: "r"(a), "r"(par) : "memory");
}
#define CBAR() asm volatile("bar.sync 5, 128;" ::: "memory")
// async arrive on FULL barrier when all of this thread's prior cp.asyncs complete
#define ARRV(i) asm volatile("cp.async.mbarrier.arrive.noinc.shared.b64 [%0];" :: "r"(MB(i)) : "memory")

__global__ void __launch_bounds__(256, 4)
patchflow_kernel(const float* __restrict__ x, const float* __restrict__ pos,
                 const float* __restrict__ w1a, const float* __restrict__ b1a,
                 const float* __restrict__ w2a, const float* __restrict__ b2a,
                 const float* __restrict__ w3a, const float* __restrict__ b3a,
                 const float* __restrict__ gsa, const float* __restrict__ goa,
                 const int* __restrict__ pma,
                 const float* __restrict__ w1b, const float* __restrict__ b1b,
                 const float* __restrict__ w2b, const float* __restrict__ b2b,
                 const float* __restrict__ w3b, const float* __restrict__ b3b,
                 const float* __restrict__ gsb, const float* __restrict__ gob,
                 const int* __restrict__ pmb,
                 float* __restrict__ zout, float* __restrict__ ldjout)
{
    extern __shared__ float sm[];
    const int p = blockIdx.x;
    const int t = threadIdx.x;
    const int w = t >> 5, l = t & 31;

    float* As  = sm + OFF_A;
    float* B2s = sm + OFF_B2;
    float* W3s = sm + OFF_W3;
    float* B3s = sm + OFF_B3;
    float* CSs = sm + OFF_CS;
    float* Hs  = sm + OFF_H;
    float* SC2 = sm + OFF_SC2;
    float* LGs = sm + OFF_LG;
    const uint32_t mb = (uint32_t)__cvta_generic_to_shared(sm + OFF_MB);

    const float* w2aP = w2a + (size_t)p * 16384;
    const float* w2bP = w2b + (size_t)p * 16384;

    // producer copy geometry (meaningful for t>=128; harmless otherwise)
    const int wrow = w & 3;
    const int co = 4 * l;

    // panel copy: 8 x cp.async 16B per thread, swizzled dst
    #define ISSUE(G) {                                                                 \
        const float* w2P_ = ((G) < 4) ? w2aP : w2bP;                                   \
        float* buf = sm + (((G) & 1) ? OFF_P1 : OFF_P0);                               \
        _Pragma("unroll")                                                              \
        for (int k = 0; k < 8; k++) {                                                  \
            int i = wrow + 4 * k;                                                      \
            cp16(buf + i * 128 + (co ^ SWZ(i)),                                        \
                 w2P_ + (size_t)(((G) & 3) * 32 + i) * 128 + co);                      \
        } }

    if (t == 0) {
        #pragma unroll
        for (int i = 0; i < 6; i++) mbar_init(MB(i), 128);
    }
    __syncthreads();   // mbarrier init visible before any async arrival can fire

    // kick off panels 0,1 immediately (overlaps all prologue work)
    if (t >= 128) {
        ISSUE(0) ARRV(0);
        ISSUE(1) ARRV(1);
    }

    // ---- small weights into smem ----
    if (t < 128) {
        B2s[t]       = __ldg(b2a + (size_t)p * 128 + t);
        B2s[128 + t] = __ldg(b2b + (size_t)p * 128 + t);
        *(float4*)(W3s + 4 * t) = __ldg((const float4*)(w3a + (size_t)p * 512) + t);
    } else {
        *(float4*)(W3s + 512 + 4 * (t - 128)) =
            __ldg((const float4*)(w3b + (size_t)p * 512) + (t - 128));
    }
    if (t == 32) {
        *(float4*)(B3s)     = __ldg((const float4*)(b3a + (size_t)p * 4));
        *(float4*)(B3s + 4) = __ldg((const float4*)(b3b + (size_t)p * 4));
    }

    // ---- per-block coupling scales (prologue) ----
    if (t == 96 || t == 97) {
        int blk = t - 96;
        const float* gsP = (blk ? gsb : gsa) + (size_t)p * 3;
        float lg = 0.f;
        #pragma unroll
        for (int c = 0; c < 3; c++) {
            float y = 0.5f * __ldg(gsP + c);
            float sc = 0.2f * ((y > 15.f) ? y : log1pf(expf(y)));
            SC2[blk * 3 + c] = sc;
            lg += logf(sc);
        }
        LGs[blk] = lg;
    }

    // ---- 3x3 stride-2 avg pool ----
    if (t < 96) {
        int b = t / 3, c = t % 3;
        int ph = p >> 6, pw = p & 63;
        const float* xp = x + (size_t)(b * 3 + c) * 16384;
        int y0 = 2 * ph - 1, x0 = 2 * pw - 1;
        float acc = 0.f;
        #pragma unroll
        for (int dy = 0; dy < 3; dy++) {
            int yy = y0 + dy;
            if (yy < 0) continue;
            #pragma unroll
            for (int dx = 0; dx < 3; dx++) {
                int xx = x0 + dx;
                if (xx < 0) continue;
                acc += __ldg(xp + yy * 128 + xx);
            }
        }
        Hs[t] = acc * (1.f / 9.f);
    }

    // ---- cond-sums for BOTH blocks ----
    {
        int o = t & 127;
        const float* w1P = ((t < 128) ? w1a : w1b) + (size_t)p * 2176;
        const float* b1P = ((t < 128) ? b1a : b1b) + (size_t)p * 128;
        const float* posP = pos + (size_t)p * 16;
        float cs = __ldg(b1P + o);
        #pragma unroll
        for (int k = 0; k < 16; k++)
            cs = fmaf(__ldg(posP + k), __ldg(w1P + (1 + k) * 128 + o), cs);
        CSs[t] = cs;
    }
    __syncthreads();

    // ---- layer 1 (block a), all 256 threads ----
    {
        const float* w1r0 = w1a + (size_t)p * 2176;
        float4 w1v = __ldg((const float4*)(w1r0) + l);
        float4 csv = *(const float4*)(CSs + 4 * l);
        #pragma unroll
        for (int r = 0; r < 4; r++) {
            int b = w + 8 * r;
            float h = Hs[b * 3];
            float4 v;
            v.x = to_tf32(gelu_fast(fmaf(h, w1v.x, csv.x)));
            v.y = to_tf32(gelu_fast(fmaf(h, w1v.y, csv.y)));
            v.z = to_tf32(gelu_fast(fmaf(h, w1v.z, csv.z)));
            v.w = to_tf32(gelu_fast(fmaf(h, w1v.w, csv.w)));
            *(float4*)(As + b * 128 + ((4 * l) ^ SWZ(b))) = v;
        }
    }
    __syncthreads();   // A1(blk a) visible; ROLES DIVERGE

    if (t >= 128) {
        // ===== PRODUCER (warps 4-7): pure cp.async pipeline, FREE-gated only =====
        mbar_wait(MB(2), 0u); ISSUE(2) ARRV(0);
        mbar_wait(MB(3), 0u); ISSUE(3) ARRV(1);
        mbar_wait(MB(2), 1u); ISSUE(4) ARRV(0);
        mbar_wait(MB(3), 1u); ISSUE(5) ARRV(1);

        // layer 1 for block b (As free after consumers' H1RDY)
        mbar_wait(MB(4), 0u);
        {
            const float* w1r0 = w1b + (size_t)p * 2176;
            int li = t & 31, bw = (t >> 5) & 3;
            float4 w1v = __ldg((const float4*)(w1r0) + li);
            float4 csv = *(const float4*)(CSs + 128 + 4 * li);
            #pragma unroll
            for (int r = 0; r < 8; r++) {
                int b = bw + 4 * r;
                float h = Hs[b * 3];
                float4 v;
                v.x = to_tf32(gelu_fast(fmaf(h, w1v.x, csv.x)));
                v.y = to_tf32(gelu_fast(fmaf(h, w1v.y, csv.y)));
                v.z = to_tf32(gelu_fast(fmaf(h, w1v.z, csv.z)));
                v.w = to_tf32(gelu_fast(fmaf(h, w1v.w, csv.w)));
                *(float4*)(As + b * 128 + ((4 * li) ^ SWZ(b))) = v;
            }
        }
        mbar_arrive(MB(5));

        mbar_wait(MB(2), 0u); ISSUE(6) ARRV(0);
        mbar_wait(MB(3), 0u); ISSUE(7) ARRV(1);
    } else {
        // ===== CONSUMER (warps 0-3) =====
        const int gid = l >> 2, tig = l & 3;
        const int obase = w << 5;
        const int g0 = gid & 1, kper = gid >> 1;
        int oA0[4], oA1[4];
        #pragma unroll
        for (int j = 0; j < 4; j++) {
            oA0[j] = 8 * (j ^ kper) + tig + 4 * g0;
            oA1[j] = 8 * (j ^ kper) + tig + 4 * (g0 ^ 1);
        }
        const int bsw0 = SWZ(tig), bsw1 = SWZ(tig + 4);
        int bo0[4], bo1[4];
        #pragma unroll
        for (int nt = 0; nt < 4; nt++) {
            int oo = obase + nt * 8 + gid;
            bo0[nt] = oo ^ bsw0;
            bo1[nt] = oo ^ bsw1;
        }
        float ldj = 0.f;   // valid for t<32

        for (int blk = 0; blk < 2; blk++) {
            if (blk == 1) mbar_wait(MB(5), 0u);

            float acc[2][4][4];
            #pragma unroll
            for (int mh = 0; mh < 2; mh++)
                #pragma unroll
                for (int nt = 0; nt < 4; nt++)
                    #pragma unroll
                    for (int k = 0; k < 4; k++) acc[mh][nt][k] = 0.f;

            #pragma unroll
            for (int c = 0; c < 4; c++) {
                int g = blk * 4 + c, bb = g & 1;
                mbar_wait(MB(bb), (uint32_t)((g >> 1) & 1));
                const float* Pc = sm + (bb ? OFF_P1 : OFF_P0);
                const float* Ac = As + 32 * c;
                #pragma unroll
                for (int j = 0; j < 4; j++) {
                    uint32_t a00 = __float_as_uint(Ac[gid * 128 + oA0[j]]);
                    uint32_t a01 = __float_as_uint(Ac[(gid + 8) * 128 + oA0[j]]);
                    uint32_t a02 = __float_as_uint(Ac[gid * 128 + oA1[j]]);
                    uint32_t a03 = __float_as_uint(Ac[(gid + 8) * 128 + oA1[j]]);
                    uint32_t a10 = __float_as_uint(Ac[(gid + 16) * 128 + oA0[j]]);
                    uint32_t a11 = __float_as_uint(Ac[(gid + 24) * 128 + oA0[j]]);
                    uint32_t a12 = __float_as_uint(Ac[(gid + 16) * 128 + oA1[j]]);
                    uint32_t a13 = __float_as_uint(Ac[(gid + 24) * 128 + oA1[j]]);
                    const float* Brow0 = Pc + (j * 8 + tig) * 128;
                    const float* Brow1 = Brow0 + 512;
                    #pragma unroll
                    for (int nt = 0; nt < 4; nt++) {
                        uint32_t b0 = __float_as_uint(Brow0[bo0[nt]]);
                        uint32_t b1 = __float_as_uint(Brow1[bo1[nt]]);
                        mma_tf32(acc[0][nt], a00, a01, a02, a03, b0, b1);
                        mma_tf32(acc[1][nt], a10, a11, a12, a13, b0, b1);
                    }
                }
                mbar_arrive(MB(2 + bb));
            }
            CBAR();                          // consumers done reading A1

            // ---- fused: bias + gelu + layer3 partial dot (A2 never hits smem) ----
            float4 ps0 = {0,0,0,0}, ps1 = ps0, ps2 = ps0, ps3 = ps0;
            {
                const float* B2 = B2s + blk * 128;
                const float* W3c = W3s + blk * 512;
                #pragma unroll
                for (int nt = 0; nt < 4; nt++) {
                    int colo = obase + nt * 8 + 2 * tig;
                    float4 wl = *(const float4*)(W3c + colo * 4);
                    float4 wh = *(const float4*)(W3c + colo * 4 + 4);
                    float bl = B2[colo], bh = B2[colo + 1];
                    float g;
                    #define ACC4(PS, G) { PS.x = fmaf(G, wl.x, PS.x); PS.y = fmaf(G, wl.y, PS.y); \
                                          PS.z = fmaf(G, wl.z, PS.z); PS.w = fmaf(G, wl.w, PS.w); }
                    #define ACC4H(PS, G) { PS.x = fmaf(G, wh.x, PS.x); PS.y = fmaf(G, wh.y, PS.y); \
                                           PS.z = fmaf(G, wh.z, PS.z); PS.w = fmaf(G, wh.w, PS.w); }
                    g = gelu_fast(acc[0][nt][0] + bl); ACC4(ps0, g)
                    g = gelu_fast(acc[0][nt][1] + bh); ACC4H(ps0, g)
                    g = gelu_fast(acc[0][nt][2] + bl); ACC4(ps1, g)
                    g = gelu_fast(acc[0][nt][3] + bh); ACC4H(ps1, g)
                    g = gelu_fast(acc[1][nt][0] + bl); ACC4(ps2, g)
                    g = gelu_fast(acc[1][nt][1] + bh); ACC4H(ps2, g)
                    g = gelu_fast(acc[1][nt][2] + bl); ACC4(ps3, g)
                    g = gelu_fast(acc[1][nt][3] + bh); ACC4H(ps3, g)
                    #undef ACC4
                    #undef ACC4H
                }
            }
            #define RED(PS) { \
                PS.x += __shfl_xor_sync(0xffffffffu, PS.x, 1); PS.x += __shfl_xor_sync(0xffffffffu, PS.x, 2); \
                PS.y += __shfl_xor_sync(0xffffffffu, PS.y, 1); PS.y += __shfl_xor_sync(0xffffffffu, PS.y, 2); \
                PS.z += __shfl_xor_sync(0xffffffffu, PS.z, 1); PS.z += __shfl_xor_sync(0xffffffffu, PS.z, 2); \
                PS.w += __shfl_xor_sync(0xffffffffu, PS.w, 1); PS.w += __shfl_xor_sync(0xffffffffu, PS.w, 2); }
            RED(ps0) RED(ps1) RED(ps2) RED(ps3)
            #undef RED
            if (tig == 0) {
                float* A3P = As + w * 128;
                *(float4*)(A3P + gid * 4)        = ps0;
                *(float4*)(A3P + (gid + 8) * 4)  = ps1;
                *(float4*)(A3P + (gid + 16) * 4) = ps2;
                *(float4*)(A3P + (gid + 24) * 4) = ps3;
            }
            CBAR();                          // partials visible

            // ---- coupling (folds final cross-warp A3 reduction in) ----
            if (t < 32) {
                int b = t;
                float a3[4];
                #pragma unroll
                for (int j = 0; j < 4; j++) {
                    float s = As[b * 4 + j] + As[128 + b * 4 + j]
                            + As[256 + b * 4 + j] + As[384 + b * 4 + j];
                    a3[j] = (s + B3s[blk * 4 + j]) * 0.1f;
                }
                const float* goP = (blk ? gob : goa) + (size_t)p * 3;
                const int*   pmP = (blk ? pmb : pma) + (size_t)p * 3;
                float sc0 = SC2[blk * 3], sc1 = SC2[blk * 3 + 1], sc2 = SC2[blk * 3 + 2];
                float s0 = 2.f * fast_tanh(a3[0]);
                float s1 = 2.f * fast_tanh(a3[1]);
                float ov0 = Hs[b * 3];
                float ov1 = Hs[b * 3 + 1] * fast_exp(s0) + a3[2];
                float ov2 = Hs[b * 3 + 2] * fast_exp(s1) + a3[3];
                ov0 = ov0 * sc0 + __ldg(goP);
                ov1 = ov1 * sc1 + __ldg(goP + 1);
                ov2 = ov2 * sc2 + __ldg(goP + 2);
                ldj += s0 + s1 + LGs[blk];
                int k0 = __ldg(pmP), k1 = __ldg(pmP + 1), k2 = __ldg(pmP + 2);
                Hs[b * 3 + 0] = (k0 == 0) ? ov0 : ((k0 == 1) ? ov1 : ov2);
                Hs[b * 3 + 1] = (k1 == 0) ? ov0 : ((k1 == 1) ? ov1 : ov2);
                Hs[b * 3 + 2] = (k2 == 0) ? ov0 : ((k2 == 1) ? ov1 : ov2);
            }
            CBAR();                          // Hs visible among consumers
            if (blk == 0) mbar_arrive(MB(4));   // H ready -> producers layer1(blk b)
        }

        if (t < 96) zout[(size_t)p * 96 + t] = Hs[t];
        if (t < 32) ldjout[(size_t)p * 32 + t] = ldj;
    }
    #undef ISSUE
}

extern "C" void kernel_launch(void* const* d_in, const int* in_sizes, int n_in,
                              void* d_out, int out_size) {
    (void)n_in; (void)out_size;

    int ia[9], ib[9];
    if (in_sizes[10] == 12288) {
        const int A[9]  = {2, 3, 4, 5, 6, 7, 8, 9, 10};
        const int Bn[9] = {11, 12, 13, 14, 15, 16, 17, 18, 19};
        for (int i = 0; i < 9; i++) { ia[i] = A[i]; ib[i] = Bn[i]; }
    } else {
        const int A[9]  = {2, 3, 4, 5, 6, 7, 8, 9, 18};
        const int Bn[9] = {10, 11, 12, 13, 14, 15, 16, 17, 19};
        for (int i = 0; i < 9; i++) { ia[i] = A[i]; ib[i] = Bn[i]; }
    }

    cudaFuncSetAttribute(patchflow_kernel,
                         cudaFuncAttributeMaxDynamicSharedMemorySize, SMEM_BYTES);

    float* z = (float*)d_out;                 // [4096, 32, 3]
    float* ldj = z + (size_t)4096 * 32 * 3;   // [4096, 32]

    patchflow_kernel<<<4096, 256, SMEM_BYTES>>>(
        (const float*)d_in[0], (const float*)d_in[1],
        (const float*)d_in[ia[0]], (const float*)d_in[ia[1]],
        (const float*)d_in[ia[2]], (const float*)d_in[ia[3]],
        (const float*)d_in[ia[4]], (const float*)d_in[ia[5]],
        (const float*)d_in[ia[6]], (const float*)d_in[ia[7]],
        (const int*)d_in[ia[8]],
        (const float*)d_in[ib[0]], (const float*)d_in[ib[1]],
        (const float*)d_in[ib[2]], (const float*)d_in[ib[3]],
        (const float*)d_in[ib[4]], (const float*)d_in[ib[5]],
        (const float*)d_in[ib[6]], (const float*)d_in[ib[7]],
        (const int*)d_in[ib[8]],
        z, ldj);
}